// round 9
// baseline (speedup 1.0000x reference)
#include <cuda_runtime.h>
#include <cuda_bf16.h>
#include <math.h>
#include <stdint.h>

#define NN 10000
#define EE 160000

// ---------------- scratch (device globals) ----------------------------------
__device__ float g_dinv[NN];
__device__ int   g_count[NN];
__device__ int   g_fill[NN];
__device__ int   g_rowptr[NN + 1];
__device__ int   g_col[EE];
__device__ float g_ew[EE];
__device__ float g_cat[(size_t)NN * 1024];
__device__ float g_tmp[(size_t)NN * 1024];   // slabs t1,t2,t3,ua (NN*256 each)
__device__ float g_u2[NN * 256];
__device__ float g_mlp[NN * 256];
__device__ float g_mlp2[NN * 128];
__device__ float g_af[(size_t)NN * 1024];    // tf32-rounded GEMM input
#define WTOT 2654208
__device__ float g_wt[WTOT];                 // tf32-rounded transposed weights

__device__ __forceinline__ float gelu_f(float x) {
    return 0.5f * x * (1.0f + erff(x * 0.70710678118654752f));
}
__device__ __forceinline__ float tf32r(float x) {
    float r;
    asm("cvt.rna.tf32.f32 %0, %1;" : "=f"(r) : "f"(x));
    return r;
}
__device__ __forceinline__ uint32_t smem_u32(const void* p) {
    uint32_t a;
    asm("{ .reg .u64 t; cvta.to.shared.u64 t, %1; cvt.u32.u64 %0, t; }" : "=r"(a) : "l"(p));
    return a;
}
__device__ __forceinline__ void ldsm4(uint32_t& r0, uint32_t& r1, uint32_t& r2,
                                      uint32_t& r3, uint32_t addr) {
    asm volatile("ldmatrix.sync.aligned.m8n8.x4.shared.b16 {%0,%1,%2,%3}, [%4];"
                 : "=r"(r0), "=r"(r1), "=r"(r2), "=r"(r3) : "r"(addr));
}
__device__ __forceinline__ void mma_tf32(float* c, const uint32_t* a, const uint32_t* b) {
    asm volatile(
        "mma.sync.aligned.m16n8k8.row.col.f32.tf32.tf32.f32 "
        "{%0,%1,%2,%3}, {%4,%5,%6,%7}, {%8,%9}, {%0,%1,%2,%3};"
        : "+f"(c[0]), "+f"(c[1]), "+f"(c[2]), "+f"(c[3])
        : "r"(a[0]), "r"(a[1]), "r"(a[2]), "r"(a[3]), "r"(b[0]), "r"(b[1]));
}

// ---------------- graph preprocessing ---------------------------------------
__global__ void k_zero() {
    int i = blockIdx.x * blockDim.x + threadIdx.x;
    if (i < NN) { g_count[i] = 0; g_fill[i] = 0; }
}
__global__ void k_count(const int* __restrict__ ei) {
    int e = blockIdx.x * blockDim.x + threadIdx.x;
    if (e < EE) atomicAdd(&g_count[ei[EE + e]], 1);
}
__global__ void k_dinvk() {
    int i = blockIdx.x * blockDim.x + threadIdx.x;
    if (i < NN) g_dinv[i] = rsqrtf((float)(g_count[i] + 1));
}
__global__ void k_scan() {
    int tid = threadIdx.x, lane = tid & 31, w = tid >> 5;
    const int chunk = 10;
    int b = tid * chunk, e = min(b + chunk, NN);
    int local = 0;
    for (int i = b; i < e; i++) local += g_count[i];
    int v = local;
#pragma unroll
    for (int o = 1; o < 32; o <<= 1) {
        int t = __shfl_up_sync(0xffffffffu, v, o);
        if (lane >= o) v += t;
    }
    __shared__ int ws[32];
    if (lane == 31) ws[w] = v;
    __syncthreads();
    if (w == 0) {
        int s = ws[lane];
#pragma unroll
        for (int o = 1; o < 32; o <<= 1) {
            int t = __shfl_up_sync(0xffffffffu, s, o);
            if (lane >= o) s += t;
        }
        ws[lane] = s;
    }
    __syncthreads();
    int run = v - local + (w ? ws[w - 1] : 0);
    for (int i = b; i < e; i++) { int c = g_count[i]; g_rowptr[i] = run; run += c; }
    if (tid == 1023) g_rowptr[NN] = run;
}
__global__ void k_scatter(const int* __restrict__ ei) {
    int e = blockIdx.x * blockDim.x + threadIdx.x;
    if (e >= EE) return;
    int s = ei[e], d = ei[EE + e];
    int pos = g_rowptr[d] + atomicAdd(&g_fill[d], 1);
    g_col[pos] = s;
    g_ew[pos] = g_dinv[s] * g_dinv[d];
}

// ---------------- weight conversion (transposed, tf32-rounded) ---------------
__global__ void k_wconv(const float* __restrict__ src, float* __restrict__ dst,
                        int K, int N, size_t srcStride, size_t dstStride) {
    int m = blockIdx.y;
    int e = blockIdx.x * 256 + threadIdx.x;
    if (e >= K * N) return;
    int k = e / N, n = e % N;
    dst[m * dstStride + (size_t)n * K + k] = tf32r(src[m * srcStride + e]);
}

// ---------------- tf32 mma GEMM ----------------------------------------------
struct GOut {
    const float* a[4];
    float* p[4];
    const float* b[4];
    int ld[4];
    int act;   // 0 none, 1 gelu, 2 gelu+tf32r
};

// ---- wide kernel: block 128x256, 8 warps (2x4, 64x64 each), BK=32, 3-stage --
// One block-column == one 256-wide output range.
#define SM2_STAGE 49152
#define SM2_TOTAL (3 * SM2_STAGE)

__global__ void __launch_bounds__(256, 1) k_mma2(
    const float* __restrict__ B, GOut o, int K, int rg0) {
    extern __shared__ char smc[];
    uint32_t sb = smem_u32(smc);
    int tid = threadIdx.x, lane = tid & 31, wid = tid >> 5;
    int WM = wid >> 2, WN = wid & 3;
    int bm = blockIdx.y * 128;
    int range = blockIdx.x + rg0;
    int brow0 = range * 256;
    const float* A = o.a[range];
    const int NIT = K >> 5;

    float acc[4][8][4];
#pragma unroll
    for (int i = 0; i < 4; i++)
#pragma unroll
        for (int j = 0; j < 8; j++)
#pragma unroll
            for (int r = 0; r < 4; r++) acc[i][j][r] = 0.f;

    auto LOAD = [&](int it) {
        int st = it % 3;
        uint32_t da = sb + st * SM2_STAGE;
        uint32_t db = da + 16384;
        int k0 = it << 5;
#pragma unroll
        for (int i = 0; i < 4; i++) {           // A: 128 rows x 8 float4
            int idx = i * 256 + tid;
            int row = idx >> 3, c = idx & 7;
            uint32_t so = row * 128 + ((c ^ (row & 7)) << 4);
            int ar = bm + row;
            const float* as = A + (size_t)min(ar, NN - 1) * K + k0 + c * 4;
            int sz = (ar < NN) ? 16 : 0;
            asm volatile("cp.async.cg.shared.global [%0], [%1], 16, %2;"
                         :: "r"(da + so), "l"(as), "r"(sz));
        }
#pragma unroll
        for (int i = 0; i < 8; i++) {           // B: 256 rows x 8 float4
            int idx = i * 256 + tid;
            int row = idx >> 3, c = idx & 7;
            uint32_t so = row * 128 + ((c ^ (row & 7)) << 4);
            const float* bs = B + (size_t)(brow0 + row) * K + k0 + c * 4;
            asm volatile("cp.async.cg.shared.global [%0], [%1], 16;"
                         :: "r"(db + so), "l"(bs));
        }
        asm volatile("cp.async.commit_group;");
    };

    LOAD(0);
    LOAD(1);
    for (int it = 0; it < NIT; it++) {
        asm volatile("cp.async.wait_group 1;");
        __syncthreads();
        if (it + 2 < NIT) LOAD(it + 2);
        int st = it % 3;
        uint32_t da = sb + st * SM2_STAGE, db = da + 16384;
#pragma unroll
        for (int kk = 0; kk < 4; kk++) {
            uint32_t a[4][4], b[8][2];
#pragma unroll
            for (int mt = 0; mt < 4; mt++) {
                int row = WM * 64 + mt * 16 + (lane & 15);
                int ch = kk * 2 + (lane >> 4);
                uint32_t ad = da + row * 128 + ((ch ^ (row & 7)) << 4);
                ldsm4(a[mt][0], a[mt][1], a[mt][2], a[mt][3], ad);
            }
#pragma unroll
            for (int ng = 0; ng < 4; ng++) {
                int row = WN * 64 + ng * 16 + (lane & 7) + ((lane & 16) >> 1);
                int ch = kk * 2 + ((lane >> 3) & 1);
                uint32_t bd = db + row * 128 + ((ch ^ (row & 7)) << 4);
                ldsm4(b[2 * ng][0], b[2 * ng][1], b[2 * ng + 1][0], b[2 * ng + 1][1], bd);
            }
#pragma unroll
            for (int mt = 0; mt < 4; mt++)
#pragma unroll
                for (int nt = 0; nt < 8; nt++)
                    mma_tf32(acc[mt][nt], a[mt], b[nt]);
        }
        __syncthreads();
    }

    float* D = o.p[range];
    const float* bias = o.b[range];
    int ldd = o.ld[range];
    int act = o.act;
#pragma unroll
    for (int mt = 0; mt < 4; mt++) {
        int r = bm + WM * 64 + mt * 16 + (lane >> 2);
#pragma unroll
        for (int nt = 0; nt < 8; nt++) {
            int gcol = WN * 64 + nt * 8 + ((lane & 3) << 1);
            float b0 = 0.f, b1 = 0.f;
            if (bias) { b0 = bias[gcol]; b1 = bias[gcol + 1]; }
            float v0 = acc[mt][nt][0] + b0, v1 = acc[mt][nt][1] + b1;
            float v2 = acc[mt][nt][2] + b0, v3 = acc[mt][nt][3] + b1;
            if (act) {
                v0 = gelu_f(v0); v1 = gelu_f(v1); v2 = gelu_f(v2); v3 = gelu_f(v3);
                if (act == 2) { v0 = tf32r(v0); v1 = tf32r(v1); v2 = tf32r(v2); v3 = tf32r(v3); }
            }
            if (r < NN) *(float2*)(D + (size_t)r * ldd + gcol) = make_float2(v0, v1);
            if (r + 8 < NN) *(float2*)(D + (size_t)(r + 8) * ldd + gcol) = make_float2(v2, v3);
        }
    }
}

// ---- narrow kernel (128x128, 4 warps) for N=128 (head w2) -------------------
__global__ void __launch_bounds__(128, 2) k_mma(
    const float* __restrict__ B, GOut o, int K, int bnoff) {
    extern __shared__ char smc[];
    uint32_t sb = smem_u32(smc);
    int tid = threadIdx.x, lane = tid & 31, wid = tid >> 5;
    int WM = wid >> 1, WN = wid & 1;
    int bm = blockIdx.y * 128, bn = (blockIdx.x + bnoff) * 128;
    int range = bn >> 8;
    const float* A = o.a[range];
    const int NIT = K >> 5;

    float acc[4][8][4];
#pragma unroll
    for (int i = 0; i < 4; i++)
#pragma unroll
        for (int j = 0; j < 8; j++)
#pragma unroll
            for (int r = 0; r < 4; r++) acc[i][j][r] = 0.f;

    auto LOAD = [&](int it) {
        int st = it % 3;
        uint32_t da = sb + st * 32768;
        uint32_t db = da + 16384;
        int k0 = it << 5;
#pragma unroll
        for (int i = 0; i < 8; i++) {
            int idx = i * 128 + tid;
            int row = idx >> 3, c = idx & 7;
            uint32_t so = row * 128 + ((c ^ (row & 7)) << 4);
            int ar = bm + row;
            const float* as = A + (size_t)min(ar, NN - 1) * K + k0 + c * 4;
            int sz = (ar < NN) ? 16 : 0;
            asm volatile("cp.async.cg.shared.global [%0], [%1], 16, %2;"
                         :: "r"(da + so), "l"(as), "r"(sz));
            const float* bs = B + (size_t)(bn + row) * K + k0 + c * 4;
            asm volatile("cp.async.cg.shared.global [%0], [%1], 16;"
                         :: "r"(db + so), "l"(bs));
        }
        asm volatile("cp.async.commit_group;");
    };

    LOAD(0);
    LOAD(1);
    for (int it = 0; it < NIT; it++) {
        asm volatile("cp.async.wait_group 1;");
        __syncthreads();
        if (it + 2 < NIT) LOAD(it + 2);
        int st = it % 3;
        uint32_t da = sb + st * 32768, db = da + 16384;
#pragma unroll
        for (int kk = 0; kk < 4; kk++) {
            uint32_t a[4][4], b[8][2];
#pragma unroll
            for (int mt = 0; mt < 4; mt++) {
                int row = WM * 64 + mt * 16 + (lane & 15);
                int ch = kk * 2 + (lane >> 4);
                uint32_t ad = da + row * 128 + ((ch ^ (row & 7)) << 4);
                ldsm4(a[mt][0], a[mt][1], a[mt][2], a[mt][3], ad);
            }
#pragma unroll
            for (int ng = 0; ng < 4; ng++) {
                int row = WN * 64 + ng * 16 + (lane & 7) + ((lane & 16) >> 1);
                int ch = kk * 2 + ((lane >> 3) & 1);
                uint32_t bd = db + row * 128 + ((ch ^ (row & 7)) << 4);
                ldsm4(b[2 * ng][0], b[2 * ng][1], b[2 * ng + 1][0], b[2 * ng + 1][1], bd);
            }
#pragma unroll
            for (int mt = 0; mt < 4; mt++)
#pragma unroll
                for (int nt = 0; nt < 8; nt++)
                    mma_tf32(acc[mt][nt], a[mt], b[nt]);
        }
    }

    float* D = o.p[range];
    const float* bias = o.b[range];
    int ldd = o.ld[range];
    int act = o.act;
#pragma unroll
    for (int mt = 0; mt < 4; mt++) {
        int r = bm + WM * 64 + mt * 16 + (lane >> 2);
#pragma unroll
        for (int nt = 0; nt < 8; nt++) {
            int gcol = (bn & 255) + WN * 64 + nt * 8 + ((lane & 3) << 1);
            float b0 = 0.f, b1 = 0.f;
            if (bias) { b0 = bias[gcol]; b1 = bias[gcol + 1]; }
            float v0 = acc[mt][nt][0] + b0, v1 = acc[mt][nt][1] + b1;
            float v2 = acc[mt][nt][2] + b0, v3 = acc[mt][nt][3] + b1;
            if (act) {
                v0 = gelu_f(v0); v1 = gelu_f(v1); v2 = gelu_f(v2); v3 = gelu_f(v3);
                if (act == 2) { v0 = tf32r(v0); v1 = tf32r(v1); v2 = tf32r(v2); v3 = tf32r(v3); }
            }
            if (r < NN) *(float2*)(D + (size_t)r * ldd + gcol) = make_float2(v0, v1);
            if (r + 8 < NN) *(float2*)(D + (size_t)(r + 8) * ldd + gcol) = make_float2(v2, v3);
        }
    }
}

// ---------------- fp32 SGEMM (input projection, K=84) ------------------------
template <int ACT>
__global__ void k_gemm(const float* __restrict__ A, const float* __restrict__ B,
                       const float* __restrict__ bias, float* __restrict__ C,
                       int nrows, int K, int M, int ldc) {
    __shared__ float As[16][68];
    __shared__ float Bs[16][68];
    int bm = blockIdx.y * 64, bn = blockIdx.x * 64;
    int tid = threadIdx.x;
    int tx = tid & 15, ty = tid >> 4;
    int ar = tid >> 2, ak = (tid & 3) * 4;
    int br = tid >> 4, bc = (tid & 15) * 4;
    float acc[4][4];
#pragma unroll
    for (int i = 0; i < 4; i++)
#pragma unroll
        for (int j = 0; j < 4; j++) acc[i][j] = 0.f;
    int arow = bm + ar;
    for (int k0 = 0; k0 < K; k0 += 16) {
        float a0 = 0.f, a1 = 0.f, a2 = 0.f, a3 = 0.f;
        if (arow < nrows) {
            const float* ap = A + (size_t)arow * K + k0 + ak;
            if (k0 + ak + 4 <= K) {
                float4 v = *(const float4*)ap;
                a0 = v.x; a1 = v.y; a2 = v.z; a3 = v.w;
            } else {
                int rem = K - (k0 + ak);
                if (rem > 0) a0 = ap[0];
                if (rem > 1) a1 = ap[1];
                if (rem > 2) a2 = ap[2];
                if (rem > 3) a3 = ap[3];
            }
        }
        As[ak + 0][ar] = a0; As[ak + 1][ar] = a1;
        As[ak + 2][ar] = a2; As[ak + 3][ar] = a3;
        float4 bv = make_float4(0.f, 0.f, 0.f, 0.f);
        if (k0 + br < K) bv = *(const float4*)(B + (size_t)(k0 + br) * M + bn + bc);
        *(float4*)&Bs[br][bc] = bv;
        __syncthreads();
#pragma unroll
        for (int k = 0; k < 16; k++) {
            float4 av = *(const float4*)&As[k][ty * 4];
            float4 bw = *(const float4*)&Bs[k][tx * 4];
            float a[4] = {av.x, av.y, av.z, av.w};
            float bb[4] = {bw.x, bw.y, bw.z, bw.w};
#pragma unroll
            for (int i = 0; i < 4; i++)
#pragma unroll
                for (int j = 0; j < 4; j++) acc[i][j] += a[i] * bb[j];
        }
        __syncthreads();
    }
#pragma unroll
    for (int i = 0; i < 4; i++) {
        int row = bm + ty * 4 + i;
        if (row >= nrows) continue;
#pragma unroll
        for (int j = 0; j < 4; j++) {
            int col = bn + tx * 4 + j;
            if (col >= M) continue;
            float v = acc[i][j] + bias[col];
            v = gelu_f(v);
            if (ACT == 2) v = tf32r(v);
            C[(size_t)row * ldc + col] = v;
        }
    }
}

// ---------------- SpMM: float4, 64 threads/node, 4 nodes/block ---------------
struct SpArgs {
    const float* i0; const float* i1; const float* i2;
    float* o0; float* o1; float* o2;
    const float* bias;
    int ld0, ld1, ld2;
    int rnd;
};
__global__ void __launch_bounds__(256) k_spmm(SpArgs a) {
    int y = blockIdx.y;
    const float* in = (y == 0) ? a.i0 : (y == 1) ? a.i1 : a.i2;
    float* out = (y == 0) ? a.o0 : (y == 1) ? a.o1 : a.o2;
    int ldo = (y == 0) ? a.ld0 : (y == 1) ? a.ld1 : a.ld2;
    int node = blockIdx.x * 4 + (threadIdx.x >> 6);
    int t = threadIdx.x & 63;
    if (node >= NN) return;
    const float4* in4 = (const float4*)in;
    int beg = g_rowptr[node], end = g_rowptr[node + 1];
    float di = g_dinv[node];
    float4 h = in4[(size_t)node * 64 + t];
    float w0 = di * di;
    float4 acc = make_float4(w0 * h.x, w0 * h.y, w0 * h.z, w0 * h.w);
    for (int e = beg; e < end; e++) {
        float w = __ldg(&g_ew[e]);
        float4 v = in4[(size_t)__ldg(&g_col[e]) * 64 + t];
        acc.x += w * v.x; acc.y += w * v.y; acc.z += w * v.z; acc.w += w * v.w;
    }
    if (y == 0 && a.bias) {
        const float4 b = *(const float4*)(a.bias + t * 4);
        acc.x += b.x; acc.y += b.y; acc.z += b.z; acc.w += b.w;
    }
    if (a.rnd) {
        acc.x = tf32r(acc.x); acc.y = tf32r(acc.y);
        acc.z = tf32r(acc.z); acc.w = tf32r(acc.w);
    }
    *(float4*)(out + (size_t)node * ldo + t * 4) = acc;
}

// ---------------- fused: hop3 (slab 768) + LayerNorm + GELU -> af -------------
__global__ void __launch_bounds__(256) k_spmm_ln(
    const float* __restrict__ in, const float* __restrict__ cat,
    const float* __restrict__ bias, const float* __restrict__ lg,
    const float* __restrict__ lb, float* __restrict__ af) {
    int tid = threadIdx.x;
    int t = tid & 63;
    int node = blockIdx.x * 4 + (tid >> 6);   // NN % 4 == 0
    const float4* in4 = (const float4*)in;
    int beg = g_rowptr[node], end = g_rowptr[node + 1];
    float di = g_dinv[node];
    float4 h = in4[(size_t)node * 64 + t];
    float w0 = di * di;
    float4 a3 = make_float4(w0 * h.x, w0 * h.y, w0 * h.z, w0 * h.w);
    for (int e = beg; e < end; e++) {
        float w = __ldg(&g_ew[e]);
        float4 v = in4[(size_t)__ldg(&g_col[e]) * 64 + t];
        a3.x += w * v.x; a3.y += w * v.y; a3.z += w * v.z; a3.w += w * v.w;
    }
    {
        const float4 b4 = *(const float4*)(bias + t * 4);
        a3.x += b4.x; a3.y += b4.y; a3.z += b4.z; a3.w += b4.w;
    }
    const float* crow = cat + (size_t)node * 1024;
    float4 v0 = *(const float4*)(crow + t * 4);
    float4 v1 = *(const float4*)(crow + 256 + t * 4);
    float4 v2 = *(const float4*)(crow + 512 + t * 4);
    float s = v0.x + v0.y + v0.z + v0.w + v1.x + v1.y + v1.z + v1.w +
              v2.x + v2.y + v2.z + v2.w + a3.x + a3.y + a3.z + a3.w;
    float ss = v0.x*v0.x + v0.y*v0.y + v0.z*v0.z + v0.w*v0.w +
               v1.x*v1.x + v1.y*v1.y + v1.z*v1.z + v1.w*v1.w +
               v2.x*v2.x + v2.y*v2.y + v2.z*v2.z + v2.w*v2.w +
               a3.x*a3.x + a3.y*a3.y + a3.z*a3.z + a3.w*a3.w;
    int w_ = tid >> 5, lane = tid & 31;
#pragma unroll
    for (int o = 16; o; o >>= 1) {
        s += __shfl_down_sync(0xffffffffu, s, o);
        ss += __shfl_down_sync(0xffffffffu, ss, o);
    }
    __shared__ float gs[8], gss[8];
    if (lane == 0) { gs[w_] = s; gss[w_] = ss; }
    __syncthreads();
    int wb = w_ & ~1;
    float S = gs[wb] + gs[wb + 1];
    float SS = gss[wb] + gss[wb + 1];
    float mu = S * (1.0f / 1024.0f);
    float var = SS * (1.0f / 1024.0f) - mu * mu;
    float inv = rsqrtf(var + 1e-5f);
    float* arow = af + (size_t)node * 1024;
    float vals[4][4] = {{v0.x, v0.y, v0.z, v0.w}, {v1.x, v1.y, v1.z, v1.w},
                        {v2.x, v2.y, v2.z, v2.w}, {a3.x, a3.y, a3.z, a3.w}};
#pragma unroll
    for (int r = 0; r < 4; r++) {
        int c = r * 256 + t * 4;
        float4 g4 = *(const float4*)(lg + c);
        float4 b4 = *(const float4*)(lb + c);
        float4 o4;
        o4.x = tf32r(gelu_f((vals[r][0] - mu) * inv * g4.x + b4.x));
        o4.y = tf32r(gelu_f((vals[r][1] - mu) * inv * g4.y + b4.y));
        o4.z = tf32r(gelu_f((vals[r][2] - mu) * inv * g4.z + b4.z));
        o4.w = tf32r(gelu_f((vals[r][3] - mu) * inv * g4.w + b4.w));
        *(float4*)(arow + c) = o4;
    }
}

// ---------------- LayerNorm(1024) + GELU -> af (layer 0) ---------------------
__global__ void k_ln(const float* __restrict__ h, const float* __restrict__ g,
                     const float* __restrict__ bta, float* __restrict__ af) {
    int node = blockIdx.x;
    int tid = threadIdx.x;
    const float* row = h + (size_t)node * 1024;
    float v[4];
    float s = 0.f, ss = 0.f;
#pragma unroll
    for (int i = 0; i < 4; i++) {
        v[i] = row[tid + i * 256];
        s += v[i]; ss += v[i] * v[i];
    }
    __shared__ float shs[8], shss[8];
#pragma unroll
    for (int o = 16; o; o >>= 1) {
        s += __shfl_down_sync(0xffffffffu, s, o);
        ss += __shfl_down_sync(0xffffffffu, ss, o);
    }
    int w = tid >> 5, lane = tid & 31;
    if (lane == 0) { shs[w] = s; shss[w] = ss; }
    __syncthreads();
    if (w == 0) {
        s = (lane < 8) ? shs[lane] : 0.f;
        ss = (lane < 8) ? shss[lane] : 0.f;
#pragma unroll
        for (int o = 4; o; o >>= 1) {
            s += __shfl_down_sync(0xffffffffu, s, o);
            ss += __shfl_down_sync(0xffffffffu, ss, o);
        }
        if (lane == 0) { shs[0] = s; shss[0] = ss; }
    }
    __syncthreads();
    float mu = shs[0] * (1.0f / 1024.0f);
    float var = shss[0] * (1.0f / 1024.0f) - mu * mu;
    float inv = rsqrtf(var + 1e-5f);
#pragma unroll
    for (int i = 0; i < 4; i++) {
        int c = tid + i * 256;
        float t = (v[i] - mu) * inv * g[c] + bta[c];
        af[(size_t)node * 1024 + c] = tf32r(gelu_f(t));
    }
}

// ---------------- final dot --------------------------------------------------
__global__ void k_out(const float* __restrict__ h2, const float* __restrict__ w3,
                      const float* __restrict__ b3, float* __restrict__ out, int n) {
    int gw = (blockIdx.x * blockDim.x + threadIdx.x) >> 5;
    int lane = threadIdx.x & 31;
    if (gw >= n) return;
    const float* row = h2 + (size_t)gw * 128;
    float s = 0.f;
#pragma unroll
    for (int i = 0; i < 4; i++) s += row[lane + i * 32] * w3[lane + i * 32];
#pragma unroll
    for (int o = 16; o; o >>= 1) s += __shfl_down_sync(0xffffffffu, s, o);
    if (lane == 0) out[gw] = s + b3[0];
}

// ---------------- host orchestration -----------------------------------------
template <typename T>
static T* sym(const void* s) {
    void* p = nullptr;
    cudaGetSymbolAddress(&p, s);
    return (T*)p;
}

extern "C" void kernel_launch(void* const* d_in, const int* in_sizes, int n_in,
                              void* d_out, int out_size) {
    const float* x      = (const float*)d_in[0];
    const int*   ei     = (const int*)d_in[1];
    const float* w_in   = (const float*)d_in[2];
    const float* b_in   = (const float*)d_in[3];
    const float* mh_w0  = (const float*)d_in[4];
    const float* mh_b0  = (const float*)d_in[5];
    const float* mh_w12 = (const float*)d_in[6];
    const float* mh_b12 = (const float*)d_in[7];
    const float* ln_g   = (const float*)d_in[8];
    const float* ln_b   = (const float*)d_in[9];
    const float* w1     = (const float*)d_in[10];
    const float* b1     = (const float*)d_in[11];
    const float* w2     = (const float*)d_in[12];
    const float* b2     = (const float*)d_in[13];
    const float* w3     = (const float*)d_in[14];
    const float* b3     = (const float*)d_in[15];
    float* out = (float*)d_out;

    float* cat  = sym<float>(g_cat);
    float* tmp  = sym<float>(g_tmp);
    float* u2   = sym<float>(g_u2);
    float* mlp  = sym<float>(g_mlp);
    float* mlp2 = sym<float>(g_mlp2);
    float* af   = sym<float>(g_af);
    float* wt   = sym<float>(g_wt);

    static cudaStream_t s1 = nullptr, s2 = nullptr;
    static cudaEvent_t ev[16];
    static bool init_done = false;
    if (!init_done) {
        cudaFuncSetAttribute(k_mma, cudaFuncAttributeMaxDynamicSharedMemorySize, 98304);
        cudaFuncSetAttribute(k_mma2, cudaFuncAttributeMaxDynamicSharedMemorySize, SM2_TOTAL);
        cudaStreamCreateWithFlags(&s1, cudaStreamNonBlocking);
        cudaStreamCreateWithFlags(&s2, cudaStreamNonBlocking);
        for (int i = 0; i < 16; i++)
            cudaEventCreateWithFlags(&ev[i], cudaEventDisableTiming);
        init_done = true;
    }

    const size_t OFF_L0 = 0, OFF_L1 = 262144, OFF_W1 = 2359296, OFF_W2 = 2621440;

    cudaEventRecord(ev[0], 0);
    cudaStreamWaitEvent(s1, ev[0], 0);
    cudaStreamWaitEvent(s2, ev[0], 0);

    // s1: CSR build
    k_zero<<<(NN + 255) / 256, 256, 0, s1>>>();
    k_count<<<(EE + 255) / 256, 256, 0, s1>>>(ei);
    k_dinvk<<<(NN + 255) / 256, 256, 0, s1>>>();
    k_scan<<<1, 1024, 0, s1>>>();
    k_scatter<<<(EE + 255) / 256, 256, 0, s1>>>(ei);

    // s2: big weight conversions
    k_wconv<<<dim3(1024, 8), 256, 0, s2>>>(mh_w12, wt + OFF_L1, 1024, 256, 262144, 262144);
    k_wconv<<<dim3(1024, 1), 256, 0, s2>>>(w1, wt + OFF_W1, 1024, 256, 262144, 262144);
    k_wconv<<<dim3(128, 1), 256, 0, s2>>>(w2, wt + OFF_W2, 256, 128, 32768, 32768);
    cudaEventRecord(ev[1], s2);

    // main: layer-0 weights + input projection -> af
    k_wconv<<<dim3(256, 4), 256>>>(mh_w0, wt + OFF_L0, 256, 256, 65536, 65536);
    k_gemm<2><<<dim3(4, (NN + 63) / 64), 256>>>(x, w_in, b_in, af, NN, 84, 256, 256);
    cudaEventRecord(ev[2], 0);

    float* t1 = tmp;
    float* t2 = tmp + (size_t)NN * 256;
    float* t3 = tmp + (size_t)2 * NN * 256;
    float* ua = tmp + (size_t)3 * NN * 256;
    const int SPG = NN / 4;

    // ---- layer 0: hops on s1, per-range GEMMs on main as hops complete ----
    cudaStreamWaitEvent(s1, ev[2], 0);
    {
        SpArgs p1{af, nullptr, nullptr, t1, nullptr, nullptr, nullptr, 256, 0, 0, 1};
        k_spmm<<<dim3(SPG, 1), 256, 0, s1>>>(p1);
        cudaEventRecord(ev[3], s1);
        SpArgs p2{t1, nullptr, nullptr, t2, nullptr, nullptr, nullptr, 256, 0, 0, 1};
        k_spmm<<<dim3(SPG, 1), 256, 0, s1>>>(p2);
        cudaEventRecord(ev[4], s1);
        SpArgs p3{t2, nullptr, nullptr, t3, nullptr, nullptr, nullptr, 256, 0, 0, 1};
        k_spmm<<<dim3(SPG, 1), 256, 0, s1>>>(p3);
        cudaEventRecord(ev[5], s1);

        GOut o;
        o.a[0] = af; o.a[1] = t1; o.a[2] = t2; o.a[3] = t3;
        o.p[0] = cat; o.p[1] = cat + 256; o.p[2] = cat + 512; o.p[3] = cat + 768;
        o.b[0] = mh_b0; o.b[1] = mh_b0 + 256; o.b[2] = mh_b0 + 512; o.b[3] = mh_b0 + 768;
        o.ld[0] = o.ld[1] = o.ld[2] = o.ld[3] = 1024;
        o.act = 0;
        k_mma2<<<dim3(1, 79), 256, SM2_TOTAL>>>(wt + OFF_L0, o, 256, 0);
        cudaStreamWaitEvent(0, ev[3], 0);
        k_mma2<<<dim3(1, 79), 256, SM2_TOTAL>>>(wt + OFF_L0, o, 256, 1);
        cudaStreamWaitEvent(0, ev[4], 0);
        k_mma2<<<dim3(1, 79), 256, SM2_TOTAL>>>(wt + OFF_L0, o, 256, 2);
        cudaStreamWaitEvent(0, ev[5], 0);
        k_mma2<<<dim3(1, 79), 256, SM2_TOTAL>>>(wt + OFF_L0, o, 256, 3);
        k_ln<<<NN, 256>>>(cat, ln_g, ln_b, af);
    }

    cudaStreamWaitEvent(0, ev[1], 0);   // big weights ready

    // ---- layers 1,2 (R7 schedule): r0 on s2 ∥ ranges1-3 + spmm on main ----
    auto LAYER = [&](size_t woff, const float* bb, const float* lg, const float* lb,
                     int evStart, int evR0) {
        GOut o;
        o.a[0] = o.a[1] = o.a[2] = o.a[3] = af;
        o.p[0] = cat; o.p[1] = t1; o.p[2] = t2; o.p[3] = t3;
        o.b[0] = bb;  o.b[1] = nullptr; o.b[2] = nullptr; o.b[3] = nullptr;
        o.ld[0] = 1024; o.ld[1] = 256; o.ld[2] = 256; o.ld[3] = 256;
        o.act = 0;
        cudaEventRecord(ev[evStart], 0);
        cudaStreamWaitEvent(s2, ev[evStart], 0);
        k_mma2<<<dim3(1, 79), 256, SM2_TOTAL, s2>>>(wt + woff, o, 1024, 0);  // r0 -> cat
        cudaEventRecord(ev[evR0], s2);
        k_mma2<<<dim3(3, 79), 256, SM2_TOTAL>>>(wt + woff, o, 1024, 1);      // r1-3
        SpArgs h1{t1, t2, t3, cat + 256, ua, u2, bb + 256, 1024, 256, 256, 0};
        k_spmm<<<dim3(SPG, 3), 256>>>(h1);
        SpArgs h2a{ua, u2, nullptr, cat + 512, t1, nullptr, bb + 512, 1024, 256, 0, 0};
        k_spmm<<<dim3(SPG, 2), 256>>>(h2a);
        cudaStreamWaitEvent(0, ev[evR0], 0);
        k_spmm_ln<<<SPG, 256>>>(t1, cat, bb + 768, lg, lb, af);
    };

    LAYER(OFF_L1,              mh_b12,        ln_g + 1024, ln_b + 1024, 6, 7);
    LAYER(OFF_L1 + 4 * 262144, mh_b12 + 1024, ln_g + 2048, ln_b + 2048, 8, 9);

    // ---- head MLP ----
    GOut oh;
    oh.a[0] = af; oh.a[1] = oh.a[2] = oh.a[3] = nullptr;
    oh.p[0] = mlp; oh.p[1] = oh.p[2] = oh.p[3] = nullptr;
    oh.b[0] = b1;  oh.b[1] = oh.b[2] = oh.b[3] = nullptr;
    oh.ld[0] = 256; oh.ld[1] = oh.ld[2] = oh.ld[3] = 0;
    oh.act = 2;
    k_mma2<<<dim3(1, 79), 256, SM2_TOTAL>>>(wt + OFF_W1, oh, 1024, 0);

    GOut o2;
    o2.a[0] = mlp; o2.a[1] = o2.a[2] = o2.a[3] = nullptr;
    o2.p[0] = mlp2; o2.p[1] = o2.p[2] = o2.p[3] = nullptr;
    o2.b[0] = b2;   o2.b[1] = o2.b[2] = o2.b[3] = nullptr;
    o2.ld[0] = 128; o2.ld[1] = o2.ld[2] = o2.ld[3] = 0;
    o2.act = 1;
    k_mma<<<dim3(1, 79), 128, 98304>>>(wt + OFF_W2, o2, 256, 0);

    k_out<<<(NN * 32 + 255) / 256, 256>>>(mlp2, w3, b3, out, NN);
}

// round 10
// speedup vs baseline: 1.0772x; 1.0772x over previous
#include <cuda_runtime.h>
#include <cuda_bf16.h>
#include <math.h>
#include <stdint.h>

#define NN 10000
#define EE 160000

// ---------------- scratch (device globals) ----------------------------------
__device__ float g_dinv[NN];
__device__ int   g_count[NN];
__device__ int   g_fill[NN];
__device__ int   g_rowptr[NN + 1];
__device__ int   g_col[EE];
__device__ float g_ew[EE];
__device__ float g_cat[(size_t)NN * 1024];
__device__ float g_tmp[(size_t)NN * 1024];   // slabs t1,t2,t3,ua (NN*256 each)
__device__ float g_u2[NN * 256];
__device__ float g_mlp[NN * 256];            // head buffer; 'ub' scratch in layers
__device__ float g_af[(size_t)NN * 1024];    // tf32-rounded GEMM input
#define WTOT 2654208
__device__ float g_wt[WTOT];                 // tf32-rounded transposed weights

__device__ __forceinline__ float gelu_f(float x) {
    return 0.5f * x * (1.0f + erff(x * 0.70710678118654752f));
}
__device__ __forceinline__ float tf32r(float x) {
    float r;
    asm("cvt.rna.tf32.f32 %0, %1;" : "=f"(r) : "f"(x));
    return r;
}
__device__ __forceinline__ uint32_t smem_u32(const void* p) {
    uint32_t a;
    asm("{ .reg .u64 t; cvta.to.shared.u64 t, %1; cvt.u32.u64 %0, t; }" : "=r"(a) : "l"(p));
    return a;
}
__device__ __forceinline__ void ldsm4(uint32_t& r0, uint32_t& r1, uint32_t& r2,
                                      uint32_t& r3, uint32_t addr) {
    asm volatile("ldmatrix.sync.aligned.m8n8.x4.shared.b16 {%0,%1,%2,%3}, [%4];"
                 : "=r"(r0), "=r"(r1), "=r"(r2), "=r"(r3) : "r"(addr));
}
__device__ __forceinline__ void mma_tf32(float* c, const uint32_t* a, const uint32_t* b) {
    asm volatile(
        "mma.sync.aligned.m16n8k8.row.col.f32.tf32.tf32.f32 "
        "{%0,%1,%2,%3}, {%4,%5,%6,%7}, {%8,%9}, {%0,%1,%2,%3};"
        : "+f"(c[0]), "+f"(c[1]), "+f"(c[2]), "+f"(c[3])
        : "r"(a[0]), "r"(a[1]), "r"(a[2]), "r"(a[3]), "r"(b[0]), "r"(b[1]));
}

// ---------------- graph preprocessing ---------------------------------------
__global__ void k_zero() {
    int i = blockIdx.x * blockDim.x + threadIdx.x;
    if (i < NN) { g_count[i] = 0; g_fill[i] = 0; }
}
__global__ void k_count(const int* __restrict__ ei) {
    int e = blockIdx.x * blockDim.x + threadIdx.x;
    if (e < EE) atomicAdd(&g_count[ei[EE + e]], 1);
}
__global__ void k_dinvk() {
    int i = blockIdx.x * blockDim.x + threadIdx.x;
    if (i < NN) g_dinv[i] = rsqrtf((float)(g_count[i] + 1));
}
__global__ void k_scan() {
    int tid = threadIdx.x, lane = tid & 31, w = tid >> 5;
    const int chunk = 10;
    int b = tid * chunk, e = min(b + chunk, NN);
    int local = 0;
    for (int i = b; i < e; i++) local += g_count[i];
    int v = local;
#pragma unroll
    for (int o = 1; o < 32; o <<= 1) {
        int t = __shfl_up_sync(0xffffffffu, v, o);
        if (lane >= o) v += t;
    }
    __shared__ int ws[32];
    if (lane == 31) ws[w] = v;
    __syncthreads();
    if (w == 0) {
        int s = ws[lane];
#pragma unroll
        for (int o = 1; o < 32; o <<= 1) {
            int t = __shfl_up_sync(0xffffffffu, s, o);
            if (lane >= o) s += t;
        }
        ws[lane] = s;
    }
    __syncthreads();
    int run = v - local + (w ? ws[w - 1] : 0);
    for (int i = b; i < e; i++) { int c = g_count[i]; g_rowptr[i] = run; run += c; }
    if (tid == 1023) g_rowptr[NN] = run;
}
__global__ void k_scatter(const int* __restrict__ ei) {
    int e = blockIdx.x * blockDim.x + threadIdx.x;
    if (e >= EE) return;
    int s = ei[e], d = ei[EE + e];
    int pos = g_rowptr[d] + atomicAdd(&g_fill[d], 1);
    g_col[pos] = s;
    g_ew[pos] = g_dinv[s] * g_dinv[d];
}

// ---------------- weight conversion (transposed, tf32-rounded) ---------------
__global__ void k_wconv(const float* __restrict__ src, float* __restrict__ dst,
                        int K, int N, size_t srcStride, size_t dstStride) {
    int m = blockIdx.y;
    int e = blockIdx.x * 256 + threadIdx.x;
    if (e >= K * N) return;
    int k = e / N, n = e % N;
    dst[m * dstStride + (size_t)n * K + k] = tf32r(src[m * srcStride + e]);
}

// ---------------- tf32 mma GEMM ----------------------------------------------
struct GOut {
    const float* a[4];
    float* p[4];
    const float* b[4];
    int ld[4];
    int act;   // 0 none, 1 gelu, 2 gelu+tf32r, 3 gelu+dot(w3)+b3 -> dout
    const float* w3p;
    const float* b3p;
    float* doutp;
};

__global__ void __launch_bounds__(128, 2) k_mma(
    const float* __restrict__ B, GOut o, int K, int bnoff) {
    extern __shared__ char smc[];
    uint32_t sb = smem_u32(smc);
    int tid = threadIdx.x, lane = tid & 31, wid = tid >> 5;
    int WM = wid >> 1, WN = wid & 1;
    int bm = blockIdx.y * 128, bn = (blockIdx.x + bnoff) * 128;
    int range = bn >> 8;
    const float* A = o.a[range];
    const int NIT = K >> 5;

    float acc[4][8][4];
#pragma unroll
    for (int i = 0; i < 4; i++)
#pragma unroll
        for (int j = 0; j < 8; j++)
#pragma unroll
            for (int r = 0; r < 4; r++) acc[i][j][r] = 0.f;

    auto LOAD = [&](int it) {
        int st = it % 3;
        uint32_t da = sb + st * 32768;
        uint32_t db = da + 16384;
        int k0 = it << 5;
#pragma unroll
        for (int i = 0; i < 8; i++) {
            int idx = i * 128 + tid;
            int row = idx >> 3, c = idx & 7;
            uint32_t so = row * 128 + ((c ^ (row & 7)) << 4);
            int ar = bm + row;
            const float* as = A + (size_t)min(ar, NN - 1) * K + k0 + c * 4;
            int sz = (ar < NN) ? 16 : 0;
            asm volatile("cp.async.cg.shared.global [%0], [%1], 16, %2;"
                         :: "r"(da + so), "l"(as), "r"(sz));
            const float* bs = B + (size_t)(bn + row) * K + k0 + c * 4;
            asm volatile("cp.async.cg.shared.global [%0], [%1], 16;"
                         :: "r"(db + so), "l"(bs));
        }
        asm volatile("cp.async.commit_group;");
    };

    LOAD(0);
    LOAD(1);
    for (int it = 0; it < NIT; it++) {
        asm volatile("cp.async.wait_group 1;");
        __syncthreads();
        if (it + 2 < NIT) LOAD(it + 2);
        int st = it % 3;
        uint32_t da = sb + st * 32768, db = da + 16384;
#pragma unroll
        for (int kk = 0; kk < 4; kk++) {
            uint32_t a[4][4], b[8][2];
#pragma unroll
            for (int mt = 0; mt < 4; mt++) {
                int row = WM * 64 + mt * 16 + (lane & 15);
                int ch = kk * 2 + (lane >> 4);
                uint32_t ad = da + row * 128 + ((ch ^ (row & 7)) << 4);
                ldsm4(a[mt][0], a[mt][1], a[mt][2], a[mt][3], ad);
            }
#pragma unroll
            for (int ng = 0; ng < 4; ng++) {
                int row = WN * 64 + ng * 16 + (lane & 7) + ((lane & 16) >> 1);
                int ch = kk * 2 + ((lane >> 3) & 1);
                uint32_t bd = db + row * 128 + ((ch ^ (row & 7)) << 4);
                ldsm4(b[2 * ng][0], b[2 * ng][1], b[2 * ng + 1][0], b[2 * ng + 1][1], bd);
            }
#pragma unroll
            for (int mt = 0; mt < 4; mt++)
#pragma unroll
                for (int nt = 0; nt < 8; nt++)
                    mma_tf32(acc[mt][nt], a[mt], b[nt]);
        }
    }

    const float* bias = o.b[range];
    int act = o.act;

    if (act == 3) {
        // fused: gelu -> dot with w3 -> out[row] (N==128, one block-col)
        __shared__ float red[128];
        if (tid < 128) red[tid] = 0.f;
        __syncthreads();
#pragma unroll
        for (int mt = 0; mt < 4; mt++) {
            float p0 = 0.f, p1 = 0.f;
#pragma unroll
            for (int nt = 0; nt < 8; nt++) {
                int gcol = WN * 64 + nt * 8 + ((lane & 3) << 1);
                float b0 = bias[gcol], b1 = bias[gcol + 1];
                float w0 = o.w3p[gcol], w1 = o.w3p[gcol + 1];
                p0 += gelu_f(acc[mt][nt][0] + b0) * w0 + gelu_f(acc[mt][nt][1] + b1) * w1;
                p1 += gelu_f(acc[mt][nt][2] + b0) * w0 + gelu_f(acc[mt][nt][3] + b1) * w1;
            }
            p0 += __shfl_xor_sync(0xffffffffu, p0, 1);
            p0 += __shfl_xor_sync(0xffffffffu, p0, 2);
            p1 += __shfl_xor_sync(0xffffffffu, p1, 1);
            p1 += __shfl_xor_sync(0xffffffffu, p1, 2);
            if ((lane & 3) == 0) {
                int lr = WM * 64 + mt * 16 + (lane >> 2);
                atomicAdd(&red[lr], p0);
                atomicAdd(&red[lr + 8], p1);
            }
        }
        __syncthreads();
        if (tid < 128) {
            int gr = bm + tid;
            if (gr < NN) o.doutp[gr] = red[tid] + o.b3p[0];
        }
        return;
    }

    float* D = o.p[range];
    int ldd = o.ld[range];
#pragma unroll
    for (int mt = 0; mt < 4; mt++) {
        int r = bm + WM * 64 + mt * 16 + (lane >> 2);
#pragma unroll
        for (int nt = 0; nt < 8; nt++) {
            int gcol = (bn & 255) + WN * 64 + nt * 8 + ((lane & 3) << 1);
            float b0 = 0.f, b1 = 0.f;
            if (bias) { b0 = bias[gcol]; b1 = bias[gcol + 1]; }
            float v0 = acc[mt][nt][0] + b0, v1 = acc[mt][nt][1] + b1;
            float v2 = acc[mt][nt][2] + b0, v3 = acc[mt][nt][3] + b1;
            if (act) {
                v0 = gelu_f(v0); v1 = gelu_f(v1); v2 = gelu_f(v2); v3 = gelu_f(v3);
                if (act == 2) { v0 = tf32r(v0); v1 = tf32r(v1); v2 = tf32r(v2); v3 = tf32r(v3); }
            }
            if (r < NN) *(float2*)(D + (size_t)r * ldd + gcol) = make_float2(v0, v1);
            if (r + 8 < NN) *(float2*)(D + (size_t)(r + 8) * ldd + gcol) = make_float2(v2, v3);
        }
    }
}

// ---------------- fp32 SGEMM (input projection, K=84) ------------------------
template <int ACT>
__global__ void k_gemm(const float* __restrict__ A, const float* __restrict__ B,
                       const float* __restrict__ bias, float* __restrict__ C,
                       int nrows, int K, int M, int ldc) {
    __shared__ float As[16][68];
    __shared__ float Bs[16][68];
    int bm = blockIdx.y * 64, bn = blockIdx.x * 64;
    int tid = threadIdx.x;
    int tx = tid & 15, ty = tid >> 4;
    int ar = tid >> 2, ak = (tid & 3) * 4;
    int br = tid >> 4, bc = (tid & 15) * 4;
    float acc[4][4];
#pragma unroll
    for (int i = 0; i < 4; i++)
#pragma unroll
        for (int j = 0; j < 4; j++) acc[i][j] = 0.f;
    int arow = bm + ar;
    for (int k0 = 0; k0 < K; k0 += 16) {
        float a0 = 0.f, a1 = 0.f, a2 = 0.f, a3 = 0.f;
        if (arow < nrows) {
            const float* ap = A + (size_t)arow * K + k0 + ak;
            if (k0 + ak + 4 <= K) {
                float4 v = *(const float4*)ap;
                a0 = v.x; a1 = v.y; a2 = v.z; a3 = v.w;
            } else {
                int rem = K - (k0 + ak);
                if (rem > 0) a0 = ap[0];
                if (rem > 1) a1 = ap[1];
                if (rem > 2) a2 = ap[2];
                if (rem > 3) a3 = ap[3];
            }
        }
        As[ak + 0][ar] = a0; As[ak + 1][ar] = a1;
        As[ak + 2][ar] = a2; As[ak + 3][ar] = a3;
        float4 bv = make_float4(0.f, 0.f, 0.f, 0.f);
        if (k0 + br < K) bv = *(const float4*)(B + (size_t)(k0 + br) * M + bn + bc);
        *(float4*)&Bs[br][bc] = bv;
        __syncthreads();
#pragma unroll
        for (int k = 0; k < 16; k++) {
            float4 av = *(const float4*)&As[k][ty * 4];
            float4 bw = *(const float4*)&Bs[k][tx * 4];
            float a[4] = {av.x, av.y, av.z, av.w};
            float bb[4] = {bw.x, bw.y, bw.z, bw.w};
#pragma unroll
            for (int i = 0; i < 4; i++)
#pragma unroll
                for (int j = 0; j < 4; j++) acc[i][j] += a[i] * bb[j];
        }
        __syncthreads();
    }
#pragma unroll
    for (int i = 0; i < 4; i++) {
        int row = bm + ty * 4 + i;
        if (row >= nrows) continue;
#pragma unroll
        for (int j = 0; j < 4; j++) {
            int col = bn + tx * 4 + j;
            if (col >= M) continue;
            float v = acc[i][j] + bias[col];
            v = gelu_f(v);
            if (ACT == 2) v = tf32r(v);
            C[(size_t)row * ldc + col] = v;
        }
    }
}

// ---------------- SpMM: float4, 64 threads/node, 4 nodes/block ---------------
struct SpArgs {
    const float* i0; const float* i1; const float* i2;
    float* o0; float* o1; float* o2;
    const float* bias;
    int ld0, ld1, ld2;
    int rnd;
};
__global__ void __launch_bounds__(256) k_spmm(SpArgs a) {
    int y = blockIdx.y;
    const float* in = (y == 0) ? a.i0 : (y == 1) ? a.i1 : a.i2;
    float* out = (y == 0) ? a.o0 : (y == 1) ? a.o1 : a.o2;
    int ldo = (y == 0) ? a.ld0 : (y == 1) ? a.ld1 : a.ld2;
    int node = blockIdx.x * 4 + (threadIdx.x >> 6);
    int t = threadIdx.x & 63;
    if (node >= NN) return;
    const float4* in4 = (const float4*)in;
    int beg = g_rowptr[node], end = g_rowptr[node + 1];
    float di = g_dinv[node];
    float4 h = in4[(size_t)node * 64 + t];
    float w0 = di * di;
    float4 acc = make_float4(w0 * h.x, w0 * h.y, w0 * h.z, w0 * h.w);
    float4 acc2 = make_float4(0.f, 0.f, 0.f, 0.f);
    int e = beg;
    for (; e + 1 < end; e += 2) {
        float wa = __ldg(&g_ew[e]);
        float wb = __ldg(&g_ew[e + 1]);
        float4 va = in4[(size_t)__ldg(&g_col[e]) * 64 + t];
        float4 vb = in4[(size_t)__ldg(&g_col[e + 1]) * 64 + t];
        acc.x += wa * va.x; acc.y += wa * va.y; acc.z += wa * va.z; acc.w += wa * va.w;
        acc2.x += wb * vb.x; acc2.y += wb * vb.y; acc2.z += wb * vb.z; acc2.w += wb * vb.w;
    }
    if (e < end) {
        float w = __ldg(&g_ew[e]);
        float4 v = in4[(size_t)__ldg(&g_col[e]) * 64 + t];
        acc.x += w * v.x; acc.y += w * v.y; acc.z += w * v.z; acc.w += w * v.w;
    }
    acc.x += acc2.x; acc.y += acc2.y; acc.z += acc2.z; acc.w += acc2.w;
    if (y == 0 && a.bias) {
        const float4 b = *(const float4*)(a.bias + t * 4);
        acc.x += b.x; acc.y += b.y; acc.z += b.z; acc.w += b.w;
    }
    if (a.rnd) {
        acc.x = tf32r(acc.x); acc.y = tf32r(acc.y);
        acc.z = tf32r(acc.z); acc.w = tf32r(acc.w);
    }
    *(float4*)(out + (size_t)node * ldo + t * 4) = acc;
}

// ---------------- fused: hop3 (slab 768) + LayerNorm + GELU -> af -------------
__global__ void __launch_bounds__(256) k_spmm_ln(
    const float* __restrict__ in, const float* __restrict__ cat,
    const float* __restrict__ bias, const float* __restrict__ lg,
    const float* __restrict__ lb, float* __restrict__ af) {
    int tid = threadIdx.x;
    int t = tid & 63;
    int node = blockIdx.x * 4 + (tid >> 6);   // NN % 4 == 0
    const float4* in4 = (const float4*)in;
    int beg = g_rowptr[node], end = g_rowptr[node + 1];
    float di = g_dinv[node];
    float4 h = in4[(size_t)node * 64 + t];
    float w0 = di * di;
    float4 a3 = make_float4(w0 * h.x, w0 * h.y, w0 * h.z, w0 * h.w);
    float4 b3a = make_float4(0.f, 0.f, 0.f, 0.f);
    int e = beg;
    for (; e + 1 < end; e += 2) {
        float wa = __ldg(&g_ew[e]);
        float wb = __ldg(&g_ew[e + 1]);
        float4 va = in4[(size_t)__ldg(&g_col[e]) * 64 + t];
        float4 vb = in4[(size_t)__ldg(&g_col[e + 1]) * 64 + t];
        a3.x += wa * va.x; a3.y += wa * va.y; a3.z += wa * va.z; a3.w += wa * va.w;
        b3a.x += wb * vb.x; b3a.y += wb * vb.y; b3a.z += wb * vb.z; b3a.w += wb * vb.w;
    }
    if (e < end) {
        float w = __ldg(&g_ew[e]);
        float4 v = in4[(size_t)__ldg(&g_col[e]) * 64 + t];
        a3.x += w * v.x; a3.y += w * v.y; a3.z += w * v.z; a3.w += w * v.w;
    }
    a3.x += b3a.x; a3.y += b3a.y; a3.z += b3a.z; a3.w += b3a.w;
    {
        const float4 b4 = *(const float4*)(bias + t * 4);
        a3.x += b4.x; a3.y += b4.y; a3.z += b4.z; a3.w += b4.w;
    }
    const float* crow = cat + (size_t)node * 1024;
    float4 v0 = *(const float4*)(crow + t * 4);
    float4 v1 = *(const float4*)(crow + 256 + t * 4);
    float4 v2 = *(const float4*)(crow + 512 + t * 4);
    float s = v0.x + v0.y + v0.z + v0.w + v1.x + v1.y + v1.z + v1.w +
              v2.x + v2.y + v2.z + v2.w + a3.x + a3.y + a3.z + a3.w;
    float ss = v0.x*v0.x + v0.y*v0.y + v0.z*v0.z + v0.w*v0.w +
               v1.x*v1.x + v1.y*v1.y + v1.z*v1.z + v1.w*v1.w +
               v2.x*v2.x + v2.y*v2.y + v2.z*v2.z + v2.w*v2.w +
               a3.x*a3.x + a3.y*a3.y + a3.z*a3.z + a3.w*a3.w;
    int w_ = tid >> 5, lane = tid & 31;
#pragma unroll
    for (int o = 16; o; o >>= 1) {
        s += __shfl_down_sync(0xffffffffu, s, o);
        ss += __shfl_down_sync(0xffffffffu, ss, o);
    }
    __shared__ float gs[8], gss[8];
    if (lane == 0) { gs[w_] = s; gss[w_] = ss; }
    __syncthreads();
    int wb = w_ & ~1;
    float S = gs[wb] + gs[wb + 1];
    float SS = gss[wb] + gss[wb + 1];
    float mu = S * (1.0f / 1024.0f);
    float var = SS * (1.0f / 1024.0f) - mu * mu;
    float inv = rsqrtf(var + 1e-5f);
    float* arow = af + (size_t)node * 1024;
    float vals[4][4] = {{v0.x, v0.y, v0.z, v0.w}, {v1.x, v1.y, v1.z, v1.w},
                        {v2.x, v2.y, v2.z, v2.w}, {a3.x, a3.y, a3.z, a3.w}};
#pragma unroll
    for (int r = 0; r < 4; r++) {
        int c = r * 256 + t * 4;
        float4 g4 = *(const float4*)(lg + c);
        float4 b4 = *(const float4*)(lb + c);
        float4 o4;
        o4.x = tf32r(gelu_f((vals[r][0] - mu) * inv * g4.x + b4.x));
        o4.y = tf32r(gelu_f((vals[r][1] - mu) * inv * g4.y + b4.y));
        o4.z = tf32r(gelu_f((vals[r][2] - mu) * inv * g4.z + b4.z));
        o4.w = tf32r(gelu_f((vals[r][3] - mu) * inv * g4.w + b4.w));
        *(float4*)(arow + c) = o4;
    }
}

// ---------------- LayerNorm(1024) + GELU -> af (layer 0) ---------------------
__global__ void k_ln(const float* __restrict__ h, const float* __restrict__ g,
                     const float* __restrict__ bta, float* __restrict__ af) {
    int node = blockIdx.x;
    int tid = threadIdx.x;
    const float* row = h + (size_t)node * 1024;
    float v[4];
    float s = 0.f, ss = 0.f;
#pragma unroll
    for (int i = 0; i < 4; i++) {
        v[i] = row[tid + i * 256];
        s += v[i]; ss += v[i] * v[i];
    }
    __shared__ float shs[8], shss[8];
#pragma unroll
    for (int o = 16; o; o >>= 1) {
        s += __shfl_down_sync(0xffffffffu, s, o);
        ss += __shfl_down_sync(0xffffffffu, ss, o);
    }
    int w = tid >> 5, lane = tid & 31;
    if (lane == 0) { shs[w] = s; shss[w] = ss; }
    __syncthreads();
    if (w == 0) {
        s = (lane < 8) ? shs[lane] : 0.f;
        ss = (lane < 8) ? shss[lane] : 0.f;
#pragma unroll
        for (int o = 4; o; o >>= 1) {
            s += __shfl_down_sync(0xffffffffu, s, o);
            ss += __shfl_down_sync(0xffffffffu, ss, o);
        }
        if (lane == 0) { shs[0] = s; shss[0] = ss; }
    }
    __syncthreads();
    float mu = shs[0] * (1.0f / 1024.0f);
    float var = shss[0] * (1.0f / 1024.0f) - mu * mu;
    float inv = rsqrtf(var + 1e-5f);
#pragma unroll
    for (int i = 0; i < 4; i++) {
        int c = tid + i * 256;
        float t = (v[i] - mu) * inv * g[c] + bta[c];
        af[(size_t)node * 1024 + c] = tf32r(gelu_f(t));
    }
}

// ---------------- host orchestration -----------------------------------------
template <typename T>
static T* sym(const void* s) {
    void* p = nullptr;
    cudaGetSymbolAddress(&p, s);
    return (T*)p;
}

extern "C" void kernel_launch(void* const* d_in, const int* in_sizes, int n_in,
                              void* d_out, int out_size) {
    const float* x      = (const float*)d_in[0];
    const int*   ei     = (const int*)d_in[1];
    const float* w_in   = (const float*)d_in[2];
    const float* b_in   = (const float*)d_in[3];
    const float* mh_w0  = (const float*)d_in[4];
    const float* mh_b0  = (const float*)d_in[5];
    const float* mh_w12 = (const float*)d_in[6];
    const float* mh_b12 = (const float*)d_in[7];
    const float* ln_g   = (const float*)d_in[8];
    const float* ln_b   = (const float*)d_in[9];
    const float* w1     = (const float*)d_in[10];
    const float* b1     = (const float*)d_in[11];
    const float* w2     = (const float*)d_in[12];
    const float* b2     = (const float*)d_in[13];
    const float* w3     = (const float*)d_in[14];
    const float* b3     = (const float*)d_in[15];
    float* out = (float*)d_out;

    float* cat  = sym<float>(g_cat);
    float* tmp  = sym<float>(g_tmp);
    float* u2   = sym<float>(g_u2);
    float* mlp  = sym<float>(g_mlp);
    float* af   = sym<float>(g_af);
    float* wt   = sym<float>(g_wt);

    static cudaStream_t s1 = nullptr, s2 = nullptr;
    static cudaEvent_t ev[16];
    static bool init_done = false;
    if (!init_done) {
        cudaFuncSetAttribute(k_mma, cudaFuncAttributeMaxDynamicSharedMemorySize, 98304);
        cudaStreamCreateWithFlags(&s1, cudaStreamNonBlocking);
        cudaStreamCreateWithFlags(&s2, cudaStreamNonBlocking);
        for (int i = 0; i < 16; i++)
            cudaEventCreateWithFlags(&ev[i], cudaEventDisableTiming);
        init_done = true;
    }

    const size_t OFF_L0 = 0, OFF_L1 = 262144, OFF_W1 = 2359296, OFF_W2 = 2621440;

    cudaEventRecord(ev[0], 0);
    cudaStreamWaitEvent(s1, ev[0], 0);
    cudaStreamWaitEvent(s2, ev[0], 0);

    // s1: CSR build
    k_zero<<<(NN + 255) / 256, 256, 0, s1>>>();
    k_count<<<(EE + 255) / 256, 256, 0, s1>>>(ei);
    k_dinvk<<<(NN + 255) / 256, 256, 0, s1>>>();
    k_scan<<<1, 1024, 0, s1>>>();
    k_scatter<<<(EE + 255) / 256, 256, 0, s1>>>(ei);

    // s2: big weight conversions
    k_wconv<<<dim3(1024, 8), 256, 0, s2>>>(mh_w12, wt + OFF_L1, 1024, 256, 262144, 262144);
    k_wconv<<<dim3(1024, 1), 256, 0, s2>>>(w1, wt + OFF_W1, 1024, 256, 262144, 262144);
    k_wconv<<<dim3(128, 1), 256, 0, s2>>>(w2, wt + OFF_W2, 256, 128, 32768, 32768);
    cudaEventRecord(ev[1], s2);

    // main: layer-0 weights + input projection -> af
    k_wconv<<<dim3(256, 4), 256>>>(mh_w0, wt + OFF_L0, 256, 256, 65536, 65536);
    k_gemm<2><<<dim3(4, (NN + 63) / 64), 256>>>(x, w_in, b_in, af, NN, 84, 256, 256);
    cudaEventRecord(ev[2], 0);

    float* t1 = tmp;
    float* t2 = tmp + (size_t)NN * 256;
    float* t3 = tmp + (size_t)2 * NN * 256;
    float* ua = tmp + (size_t)3 * NN * 256;
    float* ub = u2;
    const int SPG = NN / 4;

    // ---- layer 0: hops on s1, per-range GEMMs on main as hops complete ----
    cudaStreamWaitEvent(s1, ev[2], 0);
    {
        SpArgs p1{af, nullptr, nullptr, t1, nullptr, nullptr, nullptr, 256, 0, 0, 1};
        k_spmm<<<dim3(SPG, 1), 256, 0, s1>>>(p1);
        cudaEventRecord(ev[3], s1);
        SpArgs p2{t1, nullptr, nullptr, t2, nullptr, nullptr, nullptr, 256, 0, 0, 1};
        k_spmm<<<dim3(SPG, 1), 256, 0, s1>>>(p2);
        cudaEventRecord(ev[4], s1);
        SpArgs p3{t2, nullptr, nullptr, t3, nullptr, nullptr, nullptr, 256, 0, 0, 1};
        k_spmm<<<dim3(SPG, 1), 256, 0, s1>>>(p3);
        cudaEventRecord(ev[5], s1);

        GOut o;
        o.a[0] = af; o.a[1] = t1; o.a[2] = t2; o.a[3] = t3;
        o.p[0] = cat; o.p[1] = cat + 256; o.p[2] = cat + 512; o.p[3] = cat + 768;
        o.b[0] = mh_b0; o.b[1] = mh_b0 + 256; o.b[2] = mh_b0 + 512; o.b[3] = mh_b0 + 768;
        o.ld[0] = o.ld[1] = o.ld[2] = o.ld[3] = 1024;
        o.act = 0;
        o.w3p = nullptr; o.b3p = nullptr; o.doutp = nullptr;
        k_mma<<<dim3(2, 79), 128, 98304>>>(wt + OFF_L0, o, 256, 0);
        cudaStreamWaitEvent(0, ev[3], 0);
        k_mma<<<dim3(2, 79), 128, 98304>>>(wt + OFF_L0, o, 256, 2);
        cudaStreamWaitEvent(0, ev[4], 0);
        k_mma<<<dim3(2, 79), 128, 98304>>>(wt + OFF_L0, o, 256, 4);
        cudaStreamWaitEvent(0, ev[5], 0);
        k_mma<<<dim3(2, 79), 128, 98304>>>(wt + OFF_L0, o, 256, 6);
        k_ln<<<NN, 256>>>(cat, ln_g, ln_b, af);
    }

    cudaStreamWaitEvent(0, ev[1], 0);   // big weights ready

    // ---- layers 1,2 (R7 schedule): r0 on s2 ∥ ranges1-3 + spmm on main ----
    auto LAYER = [&](size_t woff, const float* bb, const float* lg, const float* lb,
                     int evStart, int evR0) {
        GOut o;
        o.a[0] = o.a[1] = o.a[2] = o.a[3] = af;
        o.p[0] = cat; o.p[1] = t1; o.p[2] = t2; o.p[3] = t3;
        o.b[0] = bb;  o.b[1] = nullptr; o.b[2] = nullptr; o.b[3] = nullptr;
        o.ld[0] = 1024; o.ld[1] = 256; o.ld[2] = 256; o.ld[3] = 256;
        o.act = 0;
        o.w3p = nullptr; o.b3p = nullptr; o.doutp = nullptr;
        cudaEventRecord(ev[evStart], 0);
        cudaStreamWaitEvent(s2, ev[evStart], 0);
        k_mma<<<dim3(2, 79), 128, 98304, s2>>>(wt + woff, o, 1024, 0);   // r0 -> cat
        cudaEventRecord(ev[evR0], s2);
        k_mma<<<dim3(6, 79), 128, 98304>>>(wt + woff, o, 1024, 2);       // ranges 1-3
        SpArgs h1{t1, t2, t3, cat + 256, ua, ub, bb + 256, 1024, 256, 256, 0};
        k_spmm<<<dim3(SPG, 3), 256>>>(h1);
        SpArgs h2a{ua, ub, nullptr, cat + 512, t1, nullptr, bb + 512, 1024, 256, 0, 0};
        k_spmm<<<dim3(SPG, 2), 256>>>(h2a);
        cudaStreamWaitEvent(0, ev[evR0], 0);
        k_spmm_ln<<<SPG, 256>>>(t1, cat, bb + 768, lg, lb, af);
    };

    LAYER(OFF_L1,              mh_b12,        ln_g + 1024, ln_b + 1024, 6, 7);
    LAYER(OFF_L1 + 4 * 262144, mh_b12 + 1024, ln_g + 2048, ln_b + 2048, 8, 9);

    // ---- head MLP: w1 (gelu+tf32r) -> w2+w3 fused (gelu, dot, bias) ----
    GOut oh;
    oh.a[0] = af; oh.a[1] = oh.a[2] = oh.a[3] = nullptr;
    oh.p[0] = mlp; oh.p[1] = oh.p[2] = oh.p[3] = nullptr;
    oh.b[0] = b1;  oh.b[1] = oh.b[2] = oh.b[3] = nullptr;
    oh.ld[0] = 256; oh.ld[1] = oh.ld[2] = oh.ld[3] = 0;
    oh.act = 2;
    oh.w3p = nullptr; oh.b3p = nullptr; oh.doutp = nullptr;
    k_mma<<<dim3(2, 79), 128, 98304>>>(wt + OFF_W1, oh, 1024, 0);

    GOut o2;
    o2.a[0] = mlp; o2.a[1] = o2.a[2] = o2.a[3] = nullptr;
    o2.p[0] = nullptr; o2.p[1] = o2.p[2] = o2.p[3] = nullptr;
    o2.b[0] = b2;   o2.b[1] = o2.b[2] = o2.b[3] = nullptr;
    o2.ld[0] = 128; o2.ld[1] = o2.ld[2] = o2.ld[3] = 0;
    o2.act = 3;
    o2.w3p = w3; o2.b3p = b3; o2.doutp = out;
    k_mma<<<dim3(1, 79), 128, 98304>>>(wt + OFF_W2, o2, 256, 0);
}

// round 11
// speedup vs baseline: 1.1149x; 1.0351x over previous
#include <cuda_runtime.h>
#include <cuda_bf16.h>
#include <cuda_fp16.h>
#include <math.h>
#include <stdint.h>

#define NN 10000
#define EE 160000

// ---------------- scratch (device globals) ----------------------------------
__device__ float g_dinv[NN];
__device__ int   g_count[NN];
__device__ int   g_fill[NN];
__device__ int   g_rowptr[NN + 1];
__device__ int   g_col[EE];
__device__ float g_ew[EE];
__device__ float g_cat[(size_t)NN * 1024];
__device__ float g_tmp[(size_t)NN * 1024];   // fp32 slabs (L0) / half slabs (L1,2)
__device__ float g_u2[NN * 256];
__device__ float g_mlp[NN * 256];
__device__ float g_af[(size_t)NN * 1024];    // tf32-rounded GEMM input
#define WTOT 2654208
__device__ float g_wt[WTOT];                 // tf32-rounded transposed weights

__device__ __forceinline__ float gelu_f(float x) {
    return 0.5f * x * (1.0f + erff(x * 0.70710678118654752f));
}
__device__ __forceinline__ float tf32r(float x) {
    float r;
    asm("cvt.rna.tf32.f32 %0, %1;" : "=f"(r) : "f"(x));
    return r;
}
__device__ __forceinline__ uint32_t smem_u32(const void* p) {
    uint32_t a;
    asm("{ .reg .u64 t; cvta.to.shared.u64 t, %1; cvt.u32.u64 %0, t; }" : "=r"(a) : "l"(p));
    return a;
}
__device__ __forceinline__ void ldsm4(uint32_t& r0, uint32_t& r1, uint32_t& r2,
                                      uint32_t& r3, uint32_t addr) {
    asm volatile("ldmatrix.sync.aligned.m8n8.x4.shared.b16 {%0,%1,%2,%3}, [%4];"
                 : "=r"(r0), "=r"(r1), "=r"(r2), "=r"(r3) : "r"(addr));
}
__device__ __forceinline__ void mma_tf32(float* c, const uint32_t* a, const uint32_t* b) {
    asm volatile(
        "mma.sync.aligned.m16n8k8.row.col.f32.tf32.tf32.f32 "
        "{%0,%1,%2,%3}, {%4,%5,%6,%7}, {%8,%9}, {%0,%1,%2,%3};"
        : "+f"(c[0]), "+f"(c[1]), "+f"(c[2]), "+f"(c[3])
        : "r"(a[0]), "r"(a[1]), "r"(a[2]), "r"(a[3]), "r"(b[0]), "r"(b[1]));
}

// ---------------- graph preprocessing ---------------------------------------
__global__ void k_zero() {
    int i = blockIdx.x * blockDim.x + threadIdx.x;
    if (i < NN) { g_count[i] = 0; g_fill[i] = 0; }
}
__global__ void k_count(const int* __restrict__ ei) {
    int e = blockIdx.x * blockDim.x + threadIdx.x;
    if (e < EE) atomicAdd(&g_count[ei[EE + e]], 1);
}
__global__ void k_dinvk() {
    int i = blockIdx.x * blockDim.x + threadIdx.x;
    if (i < NN) g_dinv[i] = rsqrtf((float)(g_count[i] + 1));
}
__global__ void k_scan() {
    int tid = threadIdx.x, lane = tid & 31, w = tid >> 5;
    const int chunk = 10;
    int b = tid * chunk, e = min(b + chunk, NN);
    int local = 0;
    for (int i = b; i < e; i++) local += g_count[i];
    int v = local;
#pragma unroll
    for (int o = 1; o < 32; o <<= 1) {
        int t = __shfl_up_sync(0xffffffffu, v, o);
        if (lane >= o) v += t;
    }
    __shared__ int ws[32];
    if (lane == 31) ws[w] = v;
    __syncthreads();
    if (w == 0) {
        int s = ws[lane];
#pragma unroll
        for (int o = 1; o < 32; o <<= 1) {
            int t = __shfl_up_sync(0xffffffffu, s, o);
            if (lane >= o) s += t;
        }
        ws[lane] = s;
    }
    __syncthreads();
    int run = v - local + (w ? ws[w - 1] : 0);
    for (int i = b; i < e; i++) { int c = g_count[i]; g_rowptr[i] = run; run += c; }
    if (tid == 1023) g_rowptr[NN] = run;
}
__global__ void k_scatter(const int* __restrict__ ei) {
    int e = blockIdx.x * blockDim.x + threadIdx.x;
    if (e >= EE) return;
    int s = ei[e], d = ei[EE + e];
    int pos = g_rowptr[d] + atomicAdd(&g_fill[d], 1);
    g_col[pos] = s;
    g_ew[pos] = g_dinv[s] * g_dinv[d];
}

// ---------------- weight conversion (transposed, tf32-rounded) ---------------
__global__ void k_wconv(const float* __restrict__ src, float* __restrict__ dst,
                        int K, int N, size_t srcStride, size_t dstStride) {
    int m = blockIdx.y;
    int e = blockIdx.x * 256 + threadIdx.x;
    if (e >= K * N) return;
    int k = e / N, n = e % N;
    dst[m * dstStride + (size_t)n * K + k] = tf32r(src[m * srcStride + e]);
}

// ---------------- tf32 mma GEMM ----------------------------------------------
struct GOut {
    const float* a[4];
    float* p[4];
    const float* b[4];
    int ld[4];
    int act;      // 0 none, 1 gelu, 2 gelu+tf32r, 3 gelu+dot(w3)+b3 -> dout
    int outHalf;  // act==0: write __half2 outputs
    const float* w3p;
    const float* b3p;
    float* doutp;
};

__global__ void __launch_bounds__(128, 2) k_mma(
    const float* __restrict__ B, GOut o, int K, int bnoff) {
    extern __shared__ char smc[];
    uint32_t sb = smem_u32(smc);
    int tid = threadIdx.x, lane = tid & 31, wid = tid >> 5;
    int WM = wid >> 1, WN = wid & 1;
    int bm = blockIdx.y * 128, bn = (blockIdx.x + bnoff) * 128;
    int range = bn >> 8;
    const float* A = o.a[range];
    const int NIT = K >> 5;

    float acc[4][8][4];
#pragma unroll
    for (int i = 0; i < 4; i++)
#pragma unroll
        for (int j = 0; j < 8; j++)
#pragma unroll
            for (int r = 0; r < 4; r++) acc[i][j][r] = 0.f;

    auto LOAD = [&](int it) {
        int st = it % 3;
        uint32_t da = sb + st * 32768;
        uint32_t db = da + 16384;
        int k0 = it << 5;
#pragma unroll
        for (int i = 0; i < 8; i++) {
            int idx = i * 128 + tid;
            int row = idx >> 3, c = idx & 7;
            uint32_t so = row * 128 + ((c ^ (row & 7)) << 4);
            int ar = bm + row;
            const float* as = A + (size_t)min(ar, NN - 1) * K + k0 + c * 4;
            int sz = (ar < NN) ? 16 : 0;
            asm volatile("cp.async.cg.shared.global [%0], [%1], 16, %2;"
                         :: "r"(da + so), "l"(as), "r"(sz));
            const float* bs = B + (size_t)(bn + row) * K + k0 + c * 4;
            asm volatile("cp.async.cg.shared.global [%0], [%1], 16;"
                         :: "r"(db + so), "l"(bs));
        }
        asm volatile("cp.async.commit_group;");
    };

    LOAD(0);
    LOAD(1);
    for (int it = 0; it < NIT; it++) {
        asm volatile("cp.async.wait_group 1;");
        __syncthreads();
        if (it + 2 < NIT) LOAD(it + 2);
        int st = it % 3;
        uint32_t da = sb + st * 32768, db = da + 16384;
#pragma unroll
        for (int kk = 0; kk < 4; kk++) {
            uint32_t a[4][4], b[8][2];
#pragma unroll
            for (int mt = 0; mt < 4; mt++) {
                int row = WM * 64 + mt * 16 + (lane & 15);
                int ch = kk * 2 + (lane >> 4);
                uint32_t ad = da + row * 128 + ((ch ^ (row & 7)) << 4);
                ldsm4(a[mt][0], a[mt][1], a[mt][2], a[mt][3], ad);
            }
#pragma unroll
            for (int ng = 0; ng < 4; ng++) {
                int row = WN * 64 + ng * 16 + (lane & 7) + ((lane & 16) >> 1);
                int ch = kk * 2 + ((lane >> 3) & 1);
                uint32_t bd = db + row * 128 + ((ch ^ (row & 7)) << 4);
                ldsm4(b[2 * ng][0], b[2 * ng][1], b[2 * ng + 1][0], b[2 * ng + 1][1], bd);
            }
#pragma unroll
            for (int mt = 0; mt < 4; mt++)
#pragma unroll
                for (int nt = 0; nt < 8; nt++)
                    mma_tf32(acc[mt][nt], a[mt], b[nt]);
        }
    }

    const float* bias = o.b[range];
    int act = o.act;

    if (act == 3) {
        // fused: gelu -> dot with w3 -> out[row] (N==128, one block-col)
        __shared__ float red[128];
        if (tid < 128) red[tid] = 0.f;
        __syncthreads();
#pragma unroll
        for (int mt = 0; mt < 4; mt++) {
            float p0 = 0.f, p1 = 0.f;
#pragma unroll
            for (int nt = 0; nt < 8; nt++) {
                int gcol = WN * 64 + nt * 8 + ((lane & 3) << 1);
                float b0 = bias[gcol], b1 = bias[gcol + 1];
                float w0 = o.w3p[gcol], w1 = o.w3p[gcol + 1];
                p0 += gelu_f(acc[mt][nt][0] + b0) * w0 + gelu_f(acc[mt][nt][1] + b1) * w1;
                p1 += gelu_f(acc[mt][nt][2] + b0) * w0 + gelu_f(acc[mt][nt][3] + b1) * w1;
            }
            p0 += __shfl_xor_sync(0xffffffffu, p0, 1);
            p0 += __shfl_xor_sync(0xffffffffu, p0, 2);
            p1 += __shfl_xor_sync(0xffffffffu, p1, 1);
            p1 += __shfl_xor_sync(0xffffffffu, p1, 2);
            if ((lane & 3) == 0) {
                int lr = WM * 64 + mt * 16 + (lane >> 2);
                atomicAdd(&red[lr], p0);
                atomicAdd(&red[lr + 8], p1);
            }
        }
        __syncthreads();
        if (tid < 128) {
            int gr = bm + tid;
            if (gr < NN) o.doutp[gr] = red[tid] + o.b3p[0];
        }
        return;
    }

    int ldd = o.ld[range];
    if (act == 0 && o.outHalf) {
        __half* Dh = (__half*)o.p[range];
#pragma unroll
        for (int mt = 0; mt < 4; mt++) {
            int r = bm + WM * 64 + mt * 16 + (lane >> 2);
#pragma unroll
            for (int nt = 0; nt < 8; nt++) {
                int gcol = (bn & 255) + WN * 64 + nt * 8 + ((lane & 3) << 1);
                __half2 hv01 = __floats2half2_rn(acc[mt][nt][0], acc[mt][nt][1]);
                __half2 hv23 = __floats2half2_rn(acc[mt][nt][2], acc[mt][nt][3]);
                if (r < NN) *(__half2*)(Dh + (size_t)r * ldd + gcol) = hv01;
                if (r + 8 < NN) *(__half2*)(Dh + (size_t)(r + 8) * ldd + gcol) = hv23;
            }
        }
        return;
    }

    float* D = o.p[range];
#pragma unroll
    for (int mt = 0; mt < 4; mt++) {
        int r = bm + WM * 64 + mt * 16 + (lane >> 2);
#pragma unroll
        for (int nt = 0; nt < 8; nt++) {
            int gcol = (bn & 255) + WN * 64 + nt * 8 + ((lane & 3) << 1);
            float b0 = 0.f, b1 = 0.f;
            if (bias) { b0 = bias[gcol]; b1 = bias[gcol + 1]; }
            float v0 = acc[mt][nt][0] + b0, v1 = acc[mt][nt][1] + b1;
            float v2 = acc[mt][nt][2] + b0, v3 = acc[mt][nt][3] + b1;
            if (act) {
                v0 = gelu_f(v0); v1 = gelu_f(v1); v2 = gelu_f(v2); v3 = gelu_f(v3);
                if (act == 2) { v0 = tf32r(v0); v1 = tf32r(v1); v2 = tf32r(v2); v3 = tf32r(v3); }
            }
            if (r < NN) *(float2*)(D + (size_t)r * ldd + gcol) = make_float2(v0, v1);
            if (r + 8 < NN) *(float2*)(D + (size_t)(r + 8) * ldd + gcol) = make_float2(v2, v3);
        }
    }
}

// ---------------- fp32 SGEMM (input projection, K=84) ------------------------
template <int ACT>
__global__ void k_gemm(const float* __restrict__ A, const float* __restrict__ B,
                       const float* __restrict__ bias, float* __restrict__ C,
                       int nrows, int K, int M, int ldc) {
    __shared__ float As[16][68];
    __shared__ float Bs[16][68];
    int bm = blockIdx.y * 64, bn = blockIdx.x * 64;
    int tid = threadIdx.x;
    int tx = tid & 15, ty = tid >> 4;
    int ar = tid >> 2, ak = (tid & 3) * 4;
    int br = tid >> 4, bc = (tid & 15) * 4;
    float acc[4][4];
#pragma unroll
    for (int i = 0; i < 4; i++)
#pragma unroll
        for (int j = 0; j < 4; j++) acc[i][j] = 0.f;
    int arow = bm + ar;
    for (int k0 = 0; k0 < K; k0 += 16) {
        float a0 = 0.f, a1 = 0.f, a2 = 0.f, a3 = 0.f;
        if (arow < nrows) {
            const float* ap = A + (size_t)arow * K + k0 + ak;
            if (k0 + ak + 4 <= K) {
                float4 v = *(const float4*)ap;
                a0 = v.x; a1 = v.y; a2 = v.z; a3 = v.w;
            } else {
                int rem = K - (k0 + ak);
                if (rem > 0) a0 = ap[0];
                if (rem > 1) a1 = ap[1];
                if (rem > 2) a2 = ap[2];
                if (rem > 3) a3 = ap[3];
            }
        }
        As[ak + 0][ar] = a0; As[ak + 1][ar] = a1;
        As[ak + 2][ar] = a2; As[ak + 3][ar] = a3;
        float4 bv = make_float4(0.f, 0.f, 0.f, 0.f);
        if (k0 + br < K) bv = *(const float4*)(B + (size_t)(k0 + br) * M + bn + bc);
        *(float4*)&Bs[br][bc] = bv;
        __syncthreads();
#pragma unroll
        for (int k = 0; k < 16; k++) {
            float4 av = *(const float4*)&As[k][ty * 4];
            float4 bw = *(const float4*)&Bs[k][tx * 4];
            float a[4] = {av.x, av.y, av.z, av.w};
            float bb[4] = {bw.x, bw.y, bw.z, bw.w};
#pragma unroll
            for (int i = 0; i < 4; i++)
#pragma unroll
                for (int j = 0; j < 4; j++) acc[i][j] += a[i] * bb[j];
        }
        __syncthreads();
    }
#pragma unroll
    for (int i = 0; i < 4; i++) {
        int row = bm + ty * 4 + i;
        if (row >= nrows) continue;
#pragma unroll
        for (int j = 0; j < 4; j++) {
            int col = bn + tx * 4 + j;
            if (col >= M) continue;
            float v = acc[i][j] + bias[col];
            v = gelu_f(v);
            if (ACT == 2) v = tf32r(v);
            C[(size_t)row * ldc + col] = v;
        }
    }
}

// ---------------- SpMM fp32 (layer 0): float4, 64 thr/node, 4 nodes/block ----
struct SpArgs {
    const float* i0; const float* i1; const float* i2;
    float* o0; float* o1; float* o2;
    const float* bias;
    int ld0, ld1, ld2;
    int rnd;
};
__global__ void __launch_bounds__(256) k_spmm(SpArgs a) {
    int y = blockIdx.y;
    const float* in = (y == 0) ? a.i0 : (y == 1) ? a.i1 : a.i2;
    float* out = (y == 0) ? a.o0 : (y == 1) ? a.o1 : a.o2;
    int ldo = (y == 0) ? a.ld0 : (y == 1) ? a.ld1 : a.ld2;
    int node = blockIdx.x * 4 + (threadIdx.x >> 6);
    int t = threadIdx.x & 63;
    if (node >= NN) return;
    const float4* in4 = (const float4*)in;
    int beg = g_rowptr[node], end = g_rowptr[node + 1];
    float di = g_dinv[node];
    float4 h = in4[(size_t)node * 64 + t];
    float w0 = di * di;
    float4 acc = make_float4(w0 * h.x, w0 * h.y, w0 * h.z, w0 * h.w);
    float4 acc2 = make_float4(0.f, 0.f, 0.f, 0.f);
    int e = beg;
    for (; e + 1 < end; e += 2) {
        float wa = __ldg(&g_ew[e]);
        float wb = __ldg(&g_ew[e + 1]);
        float4 va = in4[(size_t)__ldg(&g_col[e]) * 64 + t];
        float4 vb = in4[(size_t)__ldg(&g_col[e + 1]) * 64 + t];
        acc.x += wa * va.x; acc.y += wa * va.y; acc.z += wa * va.z; acc.w += wa * va.w;
        acc2.x += wb * vb.x; acc2.y += wb * vb.y; acc2.z += wb * vb.z; acc2.w += wb * vb.w;
    }
    if (e < end) {
        float w = __ldg(&g_ew[e]);
        float4 v = in4[(size_t)__ldg(&g_col[e]) * 64 + t];
        acc.x += w * v.x; acc.y += w * v.y; acc.z += w * v.z; acc.w += w * v.w;
    }
    acc.x += acc2.x; acc.y += acc2.y; acc.z += acc2.z; acc.w += acc2.w;
    if (y == 0 && a.bias) {
        const float4 b = *(const float4*)(a.bias + t * 4);
        acc.x += b.x; acc.y += b.y; acc.z += b.z; acc.w += b.w;
    }
    if (a.rnd) {
        acc.x = tf32r(acc.x); acc.y = tf32r(acc.y);
        acc.z = tf32r(acc.z); acc.w = tf32r(acc.w);
    }
    *(float4*)(out + (size_t)node * ldo + t * 4) = acc;
}

// ---------------- SpMM fp16-in (layers 1,2): uint2 gathers -------------------
struct SpHArgs {
    const __half* i0; const __half* i1; const __half* i2;
    void* o0; void* o1; void* o2;
    int oh0, oh1, oh2;            // output-is-half flags
    const float* bias;            // y==0 only
    int ld0, ld1, ld2;
};
__device__ __forceinline__ void h4acc(float4& acc, float w, uint2 hv) {
    float2 f0 = __half22float2(*(__half2*)&hv.x);
    float2 f1 = __half22float2(*(__half2*)&hv.y);
    acc.x += w * f0.x; acc.y += w * f0.y; acc.z += w * f1.x; acc.w += w * f1.y;
}
__global__ void __launch_bounds__(256) k_spmmh(SpHArgs a) {
    int y = blockIdx.y;
    const __half* in = (y == 0) ? a.i0 : (y == 1) ? a.i1 : a.i2;
    void* out = (y == 0) ? a.o0 : (y == 1) ? a.o1 : a.o2;
    int oh = (y == 0) ? a.oh0 : (y == 1) ? a.oh1 : a.oh2;
    int ldo = (y == 0) ? a.ld0 : (y == 1) ? a.ld1 : a.ld2;
    int node = blockIdx.x * 4 + (threadIdx.x >> 6);
    int t = threadIdx.x & 63;
    const uint2* in2 = (const uint2*)in;      // row stride 64 uint2 (256 halves)
    int beg = g_rowptr[node], end = g_rowptr[node + 1];
    float di = g_dinv[node];
    float w0 = di * di;
    float4 acc = make_float4(0.f, 0.f, 0.f, 0.f);
    h4acc(acc, w0, in2[(size_t)node * 64 + t]);
    float4 acc2 = make_float4(0.f, 0.f, 0.f, 0.f);
    int e = beg;
    for (; e + 1 < end; e += 2) {
        float wa = __ldg(&g_ew[e]);
        float wb = __ldg(&g_ew[e + 1]);
        uint2 va = __ldg(&in2[(size_t)__ldg(&g_col[e]) * 64 + t]);
        uint2 vb = __ldg(&in2[(size_t)__ldg(&g_col[e + 1]) * 64 + t]);
        h4acc(acc, wa, va);
        h4acc(acc2, wb, vb);
    }
    if (e < end) {
        float w = __ldg(&g_ew[e]);
        h4acc(acc, w, __ldg(&in2[(size_t)__ldg(&g_col[e]) * 64 + t]));
    }
    acc.x += acc2.x; acc.y += acc2.y; acc.z += acc2.z; acc.w += acc2.w;
    if (y == 0 && a.bias) {
        const float4 b = *(const float4*)(a.bias + t * 4);
        acc.x += b.x; acc.y += b.y; acc.z += b.z; acc.w += b.w;
    }
    if (oh) {
        __half2 lo = __floats2half2_rn(acc.x, acc.y);
        __half2 hi = __floats2half2_rn(acc.z, acc.w);
        uint2 st;
        st.x = *(uint32_t*)&lo;
        st.y = *(uint32_t*)&hi;
        *(uint2*)((__half*)out + (size_t)node * ldo + t * 4) = st;
    } else {
        *(float4*)((float*)out + (size_t)node * ldo + t * 4) = acc;
    }
}

// ---------------- fused: fp16 hop3 + LayerNorm + GELU -> af -------------------
__global__ void __launch_bounds__(256) k_spmm_lnh(
    const __half* __restrict__ in, const float* __restrict__ cat,
    const float* __restrict__ bias, const float* __restrict__ lg,
    const float* __restrict__ lb, float* __restrict__ af) {
    int tid = threadIdx.x;
    int t = tid & 63;
    int node = blockIdx.x * 4 + (tid >> 6);   // NN % 4 == 0
    const uint2* in2 = (const uint2*)in;
    int beg = g_rowptr[node], end = g_rowptr[node + 1];
    float di = g_dinv[node];
    float w0 = di * di;
    float4 a3 = make_float4(0.f, 0.f, 0.f, 0.f);
    h4acc(a3, w0, in2[(size_t)node * 64 + t]);
    float4 b3a = make_float4(0.f, 0.f, 0.f, 0.f);
    int e = beg;
    for (; e + 1 < end; e += 2) {
        float wa = __ldg(&g_ew[e]);
        float wb = __ldg(&g_ew[e + 1]);
        uint2 va = __ldg(&in2[(size_t)__ldg(&g_col[e]) * 64 + t]);
        uint2 vb = __ldg(&in2[(size_t)__ldg(&g_col[e + 1]) * 64 + t]);
        h4acc(a3, wa, va);
        h4acc(b3a, wb, vb);
    }
    if (e < end) {
        float w = __ldg(&g_ew[e]);
        h4acc(a3, w, __ldg(&in2[(size_t)__ldg(&g_col[e]) * 64 + t]));
    }
    a3.x += b3a.x; a3.y += b3a.y; a3.z += b3a.z; a3.w += b3a.w;
    {
        const float4 b4 = *(const float4*)(bias + t * 4);
        a3.x += b4.x; a3.y += b4.y; a3.z += b4.z; a3.w += b4.w;
    }
    const float* crow = cat + (size_t)node * 1024;
    float4 v0 = *(const float4*)(crow + t * 4);
    float4 v1 = *(const float4*)(crow + 256 + t * 4);
    float4 v2 = *(const float4*)(crow + 512 + t * 4);
    float s = v0.x + v0.y + v0.z + v0.w + v1.x + v1.y + v1.z + v1.w +
              v2.x + v2.y + v2.z + v2.w + a3.x + a3.y + a3.z + a3.w;
    float ss = v0.x*v0.x + v0.y*v0.y + v0.z*v0.z + v0.w*v0.w +
               v1.x*v1.x + v1.y*v1.y + v1.z*v1.z + v1.w*v1.w +
               v2.x*v2.x + v2.y*v2.y + v2.z*v2.z + v2.w*v2.w +
               a3.x*a3.x + a3.y*a3.y + a3.z*a3.z + a3.w*a3.w;
    int w_ = tid >> 5, lane = tid & 31;
#pragma unroll
    for (int o = 16; o; o >>= 1) {
        s += __shfl_down_sync(0xffffffffu, s, o);
        ss += __shfl_down_sync(0xffffffffu, ss, o);
    }
    __shared__ float gs[8], gss[8];
    if (lane == 0) { gs[w_] = s; gss[w_] = ss; }
    __syncthreads();
    int wb = w_ & ~1;
    float S = gs[wb] + gs[wb + 1];
    float SS = gss[wb] + gss[wb + 1];
    float mu = S * (1.0f / 1024.0f);
    float var = SS * (1.0f / 1024.0f) - mu * mu;
    float inv = rsqrtf(var + 1e-5f);
    float* arow = af + (size_t)node * 1024;
    float vals[4][4] = {{v0.x, v0.y, v0.z, v0.w}, {v1.x, v1.y, v1.z, v1.w},
                        {v2.x, v2.y, v2.z, v2.w}, {a3.x, a3.y, a3.z, a3.w}};
#pragma unroll
    for (int r = 0; r < 4; r++) {
        int c = r * 256 + t * 4;
        float4 g4 = *(const float4*)(lg + c);
        float4 b4 = *(const float4*)(lb + c);
        float4 o4;
        o4.x = tf32r(gelu_f((vals[r][0] - mu) * inv * g4.x + b4.x));
        o4.y = tf32r(gelu_f((vals[r][1] - mu) * inv * g4.y + b4.y));
        o4.z = tf32r(gelu_f((vals[r][2] - mu) * inv * g4.z + b4.z));
        o4.w = tf32r(gelu_f((vals[r][3] - mu) * inv * g4.w + b4.w));
        *(float4*)(arow + c) = o4;
    }
}

// ---------------- LayerNorm(1024) + GELU -> af (layer 0) ---------------------
__global__ void k_ln(const float* __restrict__ h, const float* __restrict__ g,
                     const float* __restrict__ bta, float* __restrict__ af) {
    int node = blockIdx.x;
    int tid = threadIdx.x;
    const float* row = h + (size_t)node * 1024;
    float v[4];
    float s = 0.f, ss = 0.f;
#pragma unroll
    for (int i = 0; i < 4; i++) {
        v[i] = row[tid + i * 256];
        s += v[i]; ss += v[i] * v[i];
    }
    __shared__ float shs[8], shss[8];
#pragma unroll
    for (int o = 16; o; o >>= 1) {
        s += __shfl_down_sync(0xffffffffu, s, o);
        ss += __shfl_down_sync(0xffffffffu, ss, o);
    }
    int w = tid >> 5, lane = tid & 31;
    if (lane == 0) { shs[w] = s; shss[w] = ss; }
    __syncthreads();
    if (w == 0) {
        s = (lane < 8) ? shs[lane] : 0.f;
        ss = (lane < 8) ? shss[lane] : 0.f;
#pragma unroll
        for (int o = 4; o; o >>= 1) {
            s += __shfl_down_sync(0xffffffffu, s, o);
            ss += __shfl_down_sync(0xffffffffu, ss, o);
        }
        if (lane == 0) { shs[0] = s; shss[0] = ss; }
    }
    __syncthreads();
    float mu = shs[0] * (1.0f / 1024.0f);
    float var = shss[0] * (1.0f / 1024.0f) - mu * mu;
    float inv = rsqrtf(var + 1e-5f);
#pragma unroll
    for (int i = 0; i < 4; i++) {
        int c = tid + i * 256;
        float t = (v[i] - mu) * inv * g[c] + bta[c];
        af[(size_t)node * 1024 + c] = tf32r(gelu_f(t));
    }
}

// ---------------- host orchestration -----------------------------------------
template <typename T>
static T* sym(const void* s) {
    void* p = nullptr;
    cudaGetSymbolAddress(&p, s);
    return (T*)p;
}

extern "C" void kernel_launch(void* const* d_in, const int* in_sizes, int n_in,
                              void* d_out, int out_size) {
    const float* x      = (const float*)d_in[0];
    const int*   ei     = (const int*)d_in[1];
    const float* w_in   = (const float*)d_in[2];
    const float* b_in   = (const float*)d_in[3];
    const float* mh_w0  = (const float*)d_in[4];
    const float* mh_b0  = (const float*)d_in[5];
    const float* mh_w12 = (const float*)d_in[6];
    const float* mh_b12 = (const float*)d_in[7];
    const float* ln_g   = (const float*)d_in[8];
    const float* ln_b   = (const float*)d_in[9];
    const float* w1     = (const float*)d_in[10];
    const float* b1     = (const float*)d_in[11];
    const float* w2     = (const float*)d_in[12];
    const float* b2     = (const float*)d_in[13];
    const float* w3     = (const float*)d_in[14];
    const float* b3     = (const float*)d_in[15];
    float* out = (float*)d_out;

    float* cat  = sym<float>(g_cat);
    float* tmp  = sym<float>(g_tmp);
    float* mlp  = sym<float>(g_mlp);
    float* af   = sym<float>(g_af);
    float* wt   = sym<float>(g_wt);

    static cudaStream_t s1 = nullptr, s2 = nullptr;
    static cudaEvent_t ev[16];
    static bool init_done = false;
    if (!init_done) {
        cudaFuncSetAttribute(k_mma, cudaFuncAttributeMaxDynamicSharedMemorySize, 98304);
        cudaStreamCreateWithFlags(&s1, cudaStreamNonBlocking);
        cudaStreamCreateWithFlags(&s2, cudaStreamNonBlocking);
        for (int i = 0; i < 16; i++)
            cudaEventCreateWithFlags(&ev[i], cudaEventDisableTiming);
        init_done = true;
    }

    const size_t OFF_L0 = 0, OFF_L1 = 262144, OFF_W1 = 2359296, OFF_W2 = 2621440;

    cudaEventRecord(ev[0], 0);
    cudaStreamWaitEvent(s1, ev[0], 0);
    cudaStreamWaitEvent(s2, ev[0], 0);

    // s1: CSR build
    k_zero<<<(NN + 255) / 256, 256, 0, s1>>>();
    k_count<<<(EE + 255) / 256, 256, 0, s1>>>(ei);
    k_dinvk<<<(NN + 255) / 256, 256, 0, s1>>>();
    k_scan<<<1, 1024, 0, s1>>>();
    k_scatter<<<(EE + 255) / 256, 256, 0, s1>>>(ei);

    // s2: big weight conversions
    k_wconv<<<dim3(1024, 8), 256, 0, s2>>>(mh_w12, wt + OFF_L1, 1024, 256, 262144, 262144);
    k_wconv<<<dim3(1024, 1), 256, 0, s2>>>(w1, wt + OFF_W1, 1024, 256, 262144, 262144);
    k_wconv<<<dim3(128, 1), 256, 0, s2>>>(w2, wt + OFF_W2, 256, 128, 32768, 32768);
    cudaEventRecord(ev[1], s2);

    // main: layer-0 weights + input projection -> af
    k_wconv<<<dim3(256, 4), 256>>>(mh_w0, wt + OFF_L0, 256, 256, 65536, 65536);
    k_gemm<2><<<dim3(4, (NN + 63) / 64), 256>>>(x, w_in, b_in, af, NN, 84, 256, 256);
    cudaEventRecord(ev[2], 0);

    // fp32 slabs (layer 0)
    float* t1 = tmp;
    float* t2 = tmp + (size_t)NN * 256;
    float* t3 = tmp + (size_t)2 * NN * 256;
    // fp16 slabs (layers 1,2) — carved from the same scratch, used after L0
    __half* th1  = (__half*)tmp;
    __half* th2  = (__half*)(tmp + (size_t)NN * 128);
    __half* th3  = (__half*)(tmp + (size_t)NN * 256);
    __half* uah  = (__half*)(tmp + (size_t)NN * 384);
    __half* ubh  = (__half*)(tmp + (size_t)NN * 512);
    __half* t1h2 = (__half*)(tmp + (size_t)NN * 640);
    const int SPG = NN / 4;

    // ---- layer 0 (fp32): hops on s1, per-range GEMMs on main as hops land ----
    cudaStreamWaitEvent(s1, ev[2], 0);
    {
        SpArgs p1{af, nullptr, nullptr, t1, nullptr, nullptr, nullptr, 256, 0, 0, 1};
        k_spmm<<<dim3(SPG, 1), 256, 0, s1>>>(p1);
        cudaEventRecord(ev[3], s1);
        SpArgs p2{t1, nullptr, nullptr, t2, nullptr, nullptr, nullptr, 256, 0, 0, 1};
        k_spmm<<<dim3(SPG, 1), 256, 0, s1>>>(p2);
        cudaEventRecord(ev[4], s1);
        SpArgs p3{t2, nullptr, nullptr, t3, nullptr, nullptr, nullptr, 256, 0, 0, 1};
        k_spmm<<<dim3(SPG, 1), 256, 0, s1>>>(p3);
        cudaEventRecord(ev[5], s1);

        GOut o;
        o.a[0] = af; o.a[1] = t1; o.a[2] = t2; o.a[3] = t3;
        o.p[0] = cat; o.p[1] = cat + 256; o.p[2] = cat + 512; o.p[3] = cat + 768;
        o.b[0] = mh_b0; o.b[1] = mh_b0 + 256; o.b[2] = mh_b0 + 512; o.b[3] = mh_b0 + 768;
        o.ld[0] = o.ld[1] = o.ld[2] = o.ld[3] = 1024;
        o.act = 0; o.outHalf = 0;
        o.w3p = nullptr; o.b3p = nullptr; o.doutp = nullptr;
        k_mma<<<dim3(2, 79), 128, 98304>>>(wt + OFF_L0, o, 256, 0);
        cudaStreamWaitEvent(0, ev[3], 0);
        k_mma<<<dim3(2, 79), 128, 98304>>>(wt + OFF_L0, o, 256, 2);
        cudaStreamWaitEvent(0, ev[4], 0);
        k_mma<<<dim3(2, 79), 128, 98304>>>(wt + OFF_L0, o, 256, 4);
        cudaStreamWaitEvent(0, ev[5], 0);
        k_mma<<<dim3(2, 79), 128, 98304>>>(wt + OFF_L0, o, 256, 6);
        k_ln<<<NN, 256>>>(cat, ln_g, ln_b, af);
    }

    cudaStreamWaitEvent(0, ev[1], 0);   // big weights ready

    // ---- layers 1,2 (fp16 slabs): r0 on s2 ∥ ranges1-3 + spmm on main ----
    auto LAYER = [&](size_t woff, const float* bb, const float* lg, const float* lb,
                     int evStart, int evR0) {
        GOut of;   // range 0 -> cat fp32 (with bias)
        of.a[0] = of.a[1] = of.a[2] = of.a[3] = af;
        of.p[0] = cat; of.p[1] = (float*)th1; of.p[2] = (float*)th2; of.p[3] = (float*)th3;
        of.b[0] = bb;  of.b[1] = nullptr; of.b[2] = nullptr; of.b[3] = nullptr;
        of.ld[0] = 1024; of.ld[1] = 256; of.ld[2] = 256; of.ld[3] = 256;
        of.act = 0; of.outHalf = 0;
        of.w3p = nullptr; of.b3p = nullptr; of.doutp = nullptr;
        cudaEventRecord(ev[evStart], 0);
        cudaStreamWaitEvent(s2, ev[evStart], 0);
        k_mma<<<dim3(2, 79), 128, 98304, s2>>>(wt + woff, of, 1024, 0);  // r0 -> cat
        cudaEventRecord(ev[evR0], s2);

        GOut oh2 = of;
        oh2.outHalf = 1;                                                  // r1-3 -> half
        k_mma<<<dim3(6, 79), 128, 98304>>>(wt + woff, oh2, 1024, 2);

        SpHArgs h1{th1, th2, th3, cat + 256, uah, ubh, 0, 1, 1,
                   bb + 256, 1024, 256, 256};
        k_spmmh<<<dim3(SPG, 3), 256>>>(h1);
        SpHArgs h2{uah, ubh, nullptr, cat + 512, t1h2, nullptr, 0, 1, 0,
                   bb + 512, 1024, 256, 0};
        k_spmmh<<<dim3(SPG, 2), 256>>>(h2);
        cudaStreamWaitEvent(0, ev[evR0], 0);
        k_spmm_lnh<<<SPG, 256>>>(t1h2, cat, bb + 768, lg, lb, af);
    };

    LAYER(OFF_L1,              mh_b12,        ln_g + 1024, ln_b + 1024, 6, 7);
    LAYER(OFF_L1 + 4 * 262144, mh_b12 + 1024, ln_g + 2048, ln_b + 2048, 8, 9);

    // ---- head MLP: w1 (gelu+tf32r) -> w2+w3 fused (gelu, dot, bias) ----
    GOut oh;
    oh.a[0] = af; oh.a[1] = oh.a[2] = oh.a[3] = nullptr;
    oh.p[0] = mlp; oh.p[1] = oh.p[2] = oh.p[3] = nullptr;
    oh.b[0] = b1;  oh.b[1] = oh.b[2] = oh.b[3] = nullptr;
    oh.ld[0] = 256; oh.ld[1] = oh.ld[2] = oh.ld[3] = 0;
    oh.act = 2; oh.outHalf = 0;
    oh.w3p = nullptr; oh.b3p = nullptr; oh.doutp = nullptr;
    k_mma<<<dim3(2, 79), 128, 98304>>>(wt + OFF_W1, oh, 1024, 0);

    GOut o2;
    o2.a[0] = mlp; o2.a[1] = o2.a[2] = o2.a[3] = nullptr;
    o2.p[0] = nullptr; o2.p[1] = o2.p[2] = o2.p[3] = nullptr;
    o2.b[0] = b2;   o2.b[1] = o2.b[2] = o2.b[3] = nullptr;
    o2.ld[0] = 128; o2.ld[1] = o2.ld[2] = o2.ld[3] = 0;
    o2.act = 3; o2.outHalf = 0;
    o2.w3p = w3; o2.b3p = b3; o2.doutp = out;
    k_mma<<<dim3(1, 79), 128, 98304>>>(wt + OFF_W2, o2, 256, 0);
}

// round 12
// speedup vs baseline: 1.4949x; 1.3408x over previous
#include <cuda_runtime.h>
#include <cuda_fp16.h>
#include <math.h>
#include <stdint.h>

#define NN 10000
#define EE 160000

// ---------------- scratch (device globals) ----------------------------------
__device__ float g_dinv[NN];
__device__ int   g_count[NN];
__device__ int   g_fill[NN];
__device__ int   g_rowptr[NN + 1];
__device__ int   g_col[EE];
__device__ float g_ew[EE];
__device__ float g_cat[(size_t)NN * 1024];
__device__ __half g_tmph[(size_t)NN * 1536];  // 6 half slabs of NN*256
__device__ __half g_mlph[NN * 256];
__device__ __half g_afh[(size_t)NN * 1024];   // fp16 GEMM input
#define WTOT 2654208
__device__ __half g_wth[WTOT];                // fp16 transposed weights

__device__ __forceinline__ float gelu_f(float x) {
    return 0.5f * x * (1.0f + erff(x * 0.70710678118654752f));
}
__device__ __forceinline__ uint32_t smem_u32(const void* p) {
    uint32_t a;
    asm("{ .reg .u64 t; cvta.to.shared.u64 t, %1; cvt.u32.u64 %0, t; }" : "=r"(a) : "l"(p));
    return a;
}
__device__ __forceinline__ void ldsm4(uint32_t& r0, uint32_t& r1, uint32_t& r2,
                                      uint32_t& r3, uint32_t addr) {
    asm volatile("ldmatrix.sync.aligned.m8n8.x4.shared.b16 {%0,%1,%2,%3}, [%4];"
                 : "=r"(r0), "=r"(r1), "=r"(r2), "=r"(r3) : "r"(addr));
}
__device__ __forceinline__ void mma_f16(float* c, const uint32_t* a, const uint32_t* b) {
    asm volatile(
        "mma.sync.aligned.m16n8k16.row.col.f32.f16.f16.f32 "
        "{%0,%1,%2,%3}, {%4,%5,%6,%7}, {%8,%9}, {%0,%1,%2,%3};"
        : "+f"(c[0]), "+f"(c[1]), "+f"(c[2]), "+f"(c[3])
        : "r"(a[0]), "r"(a[1]), "r"(a[2]), "r"(a[3]), "r"(b[0]), "r"(b[1]));
}

// ---------------- graph preprocessing ---------------------------------------
__global__ void k_zero() {
    int i = blockIdx.x * blockDim.x + threadIdx.x;
    if (i < NN) { g_count[i] = 0; g_fill[i] = 0; }
}
__global__ void k_count(const int* __restrict__ ei) {
    int e = blockIdx.x * blockDim.x + threadIdx.x;
    if (e < EE) atomicAdd(&g_count[ei[EE + e]], 1);
}
__global__ void k_dinvk() {
    int i = blockIdx.x * blockDim.x + threadIdx.x;
    if (i < NN) g_dinv[i] = rsqrtf((float)(g_count[i] + 1));
}
__global__ void k_scan() {
    int tid = threadIdx.x, lane = tid & 31, w = tid >> 5;
    const int chunk = 10;
    int b = tid * chunk, e = min(b + chunk, NN);
    int local = 0;
    for (int i = b; i < e; i++) local += g_count[i];
    int v = local;
#pragma unroll
    for (int o = 1; o < 32; o <<= 1) {
        int t = __shfl_up_sync(0xffffffffu, v, o);
        if (lane >= o) v += t;
    }
    __shared__ int ws[32];
    if (lane == 31) ws[w] = v;
    __syncthreads();
    if (w == 0) {
        int s = ws[lane];
#pragma unroll
        for (int o = 1; o < 32; o <<= 1) {
            int t = __shfl_up_sync(0xffffffffu, s, o);
            if (lane >= o) s += t;
        }
        ws[lane] = s;
    }
    __syncthreads();
    int run = v - local + (w ? ws[w - 1] : 0);
    for (int i = b; i < e; i++) { int c = g_count[i]; g_rowptr[i] = run; run += c; }
    if (tid == 1023) g_rowptr[NN] = run;
}
__global__ void k_scatter(const int* __restrict__ ei) {
    int e = blockIdx.x * blockDim.x + threadIdx.x;
    if (e >= EE) return;
    int s = ei[e], d = ei[EE + e];
    int pos = g_rowptr[d] + atomicAdd(&g_fill[d], 1);
    g_col[pos] = s;
    g_ew[pos] = g_dinv[s] * g_dinv[d];
}

// ---------------- weight conversion (transposed, fp16) -----------------------
__global__ void k_wconv(const float* __restrict__ src, __half* __restrict__ dst,
                        int K, int N, size_t srcStride, size_t dstStride) {
    int m = blockIdx.y;
    int e = blockIdx.x * 256 + threadIdx.x;
    if (e >= K * N) return;
    int k = e / N, n = e % N;
    dst[m * dstStride + (size_t)n * K + k] = __float2half(src[m * srcStride + e]);
}

// ---------------- fp16 mma GEMM (m16n8k16, fp32 accum) ------------------------
// Block 128x128, 4 warps 64x64, BK=64 halves (128B rows), 3-stage cp.async.
struct GOut {
    const __half* a[4];
    void* p[4];
    const float* b[4];
    int ld[4];
    int act;      // 0 none, 2 gelu, 3 gelu+dot(w3)+b3 -> dout
    int outHalf;  // store half outputs (act 0 or 2)
    const float* w3p;
    const float* b3p;
    float* doutp;
};

__global__ void __launch_bounds__(128, 2) k_mma(
    const __half* __restrict__ B, GOut o, int K, int bnoff) {
    extern __shared__ char smc[];
    uint32_t sb = smem_u32(smc);
    int tid = threadIdx.x, lane = tid & 31, wid = tid >> 5;
    int WM = wid >> 1, WN = wid & 1;
    int bm = blockIdx.y * 128, bn = (blockIdx.x + bnoff) * 128;
    int range = bn >> 8;
    const __half* A = o.a[range];
    const int NIT = K >> 6;

    float acc[4][8][4];
#pragma unroll
    for (int i = 0; i < 4; i++)
#pragma unroll
        for (int j = 0; j < 8; j++)
#pragma unroll
            for (int r = 0; r < 4; r++) acc[i][j][r] = 0.f;

    auto LOAD = [&](int it) {
        int st = it % 3;
        uint32_t da = sb + st * 32768;
        uint32_t db = da + 16384;
        int k0 = it << 6;
#pragma unroll
        for (int i = 0; i < 8; i++) {
            int idx = i * 128 + tid;
            int row = idx >> 3, c = idx & 7;
            uint32_t so = row * 128 + ((c ^ (row & 7)) << 4);
            int ar = bm + row;
            const __half* as = A + (size_t)min(ar, NN - 1) * K + k0 + c * 8;
            int sz = (ar < NN) ? 16 : 0;
            asm volatile("cp.async.cg.shared.global [%0], [%1], 16, %2;"
                         :: "r"(da + so), "l"(as), "r"(sz));
            const __half* bs = B + (size_t)(bn + row) * K + k0 + c * 8;
            asm volatile("cp.async.cg.shared.global [%0], [%1], 16;"
                         :: "r"(db + so), "l"(bs));
        }
        asm volatile("cp.async.commit_group;");
    };

    LOAD(0);
    LOAD(1);
    for (int it = 0; it < NIT; it++) {
        asm volatile("cp.async.wait_group 1;");
        __syncthreads();
        if (it + 2 < NIT) LOAD(it + 2);
        int st = it % 3;
        uint32_t da = sb + st * 32768, db = da + 16384;
#pragma unroll
        for (int kk = 0; kk < 4; kk++) {      // 4 k16 steps in BK=64
            uint32_t a[4][4], b[8][2];
#pragma unroll
            for (int mt = 0; mt < 4; mt++) {
                int row = WM * 64 + mt * 16 + (lane & 15);
                int ch = kk * 2 + (lane >> 4);
                uint32_t ad = da + row * 128 + ((ch ^ (row & 7)) << 4);
                ldsm4(a[mt][0], a[mt][1], a[mt][2], a[mt][3], ad);
            }
#pragma unroll
            for (int ng = 0; ng < 4; ng++) {
                int row = WN * 64 + ng * 16 + (lane & 7) + ((lane & 16) >> 1);
                int ch = kk * 2 + ((lane >> 3) & 1);
                uint32_t bd = db + row * 128 + ((ch ^ (row & 7)) << 4);
                ldsm4(b[2 * ng][0], b[2 * ng][1], b[2 * ng + 1][0], b[2 * ng + 1][1], bd);
            }
#pragma unroll
            for (int mt = 0; mt < 4; mt++)
#pragma unroll
                for (int nt = 0; nt < 8; nt++)
                    mma_f16(acc[mt][nt], a[mt], b[nt]);
        }
    }

    const float* bias = o.b[range];
    int act = o.act;

    if (act == 3) {
        // fused: gelu -> dot with w3 -> out[row] (N==128, one block-col)
        __shared__ float red[128];
        if (tid < 128) red[tid] = 0.f;
        __syncthreads();
#pragma unroll
        for (int mt = 0; mt < 4; mt++) {
            float p0 = 0.f, p1 = 0.f;
#pragma unroll
            for (int nt = 0; nt < 8; nt++) {
                int gcol = WN * 64 + nt * 8 + ((lane & 3) << 1);
                float b0 = bias[gcol], b1 = bias[gcol + 1];
                float w0 = o.w3p[gcol], w1 = o.w3p[gcol + 1];
                p0 += gelu_f(acc[mt][nt][0] + b0) * w0 + gelu_f(acc[mt][nt][1] + b1) * w1;
                p1 += gelu_f(acc[mt][nt][2] + b0) * w0 + gelu_f(acc[mt][nt][3] + b1) * w1;
            }
            p0 += __shfl_xor_sync(0xffffffffu, p0, 1);
            p0 += __shfl_xor_sync(0xffffffffu, p0, 2);
            p1 += __shfl_xor_sync(0xffffffffu, p1, 1);
            p1 += __shfl_xor_sync(0xffffffffu, p1, 2);
            if ((lane & 3) == 0) {
                int lr = WM * 64 + mt * 16 + (lane >> 2);
                atomicAdd(&red[lr], p0);
                atomicAdd(&red[lr + 8], p1);
            }
        }
        __syncthreads();
        if (tid < 128) {
            int gr = bm + tid;
            if (gr < NN) o.doutp[gr] = red[tid] + o.b3p[0];
        }
        return;
    }

    int ldd = o.ld[range];
    if (o.outHalf) {
        __half* Dh = (__half*)o.p[range];
#pragma unroll
        for (int mt = 0; mt < 4; mt++) {
            int r = bm + WM * 64 + mt * 16 + (lane >> 2);
#pragma unroll
            for (int nt = 0; nt < 8; nt++) {
                int gcol = (bn & 255) + WN * 64 + nt * 8 + ((lane & 3) << 1);
                float v0 = acc[mt][nt][0], v1 = acc[mt][nt][1];
                float v2 = acc[mt][nt][2], v3 = acc[mt][nt][3];
                if (act == 2) {
                    float b0 = bias[gcol], b1 = bias[gcol + 1];
                    v0 = gelu_f(v0 + b0); v1 = gelu_f(v1 + b1);
                    v2 = gelu_f(v2 + b0); v3 = gelu_f(v3 + b1);
                }
                __half2 hv01 = __floats2half2_rn(v0, v1);
                __half2 hv23 = __floats2half2_rn(v2, v3);
                if (r < NN) *(__half2*)(Dh + (size_t)r * ldd + gcol) = hv01;
                if (r + 8 < NN) *(__half2*)(Dh + (size_t)(r + 8) * ldd + gcol) = hv23;
            }
        }
        return;
    }

    float* D = (float*)o.p[range];
#pragma unroll
    for (int mt = 0; mt < 4; mt++) {
        int r = bm + WM * 64 + mt * 16 + (lane >> 2);
#pragma unroll
        for (int nt = 0; nt < 8; nt++) {
            int gcol = (bn & 255) + WN * 64 + nt * 8 + ((lane & 3) << 1);
            float b0 = 0.f, b1 = 0.f;
            if (bias) { b0 = bias[gcol]; b1 = bias[gcol + 1]; }
            float v0 = acc[mt][nt][0] + b0, v1 = acc[mt][nt][1] + b1;
            float v2 = acc[mt][nt][2] + b0, v3 = acc[mt][nt][3] + b1;
            if (r < NN) *(float2*)(D + (size_t)r * ldd + gcol) = make_float2(v0, v1);
            if (r + 8 < NN) *(float2*)(D + (size_t)(r + 8) * ldd + gcol) = make_float2(v2, v3);
        }
    }
}

// ---------------- fp32 SGEMM (input projection, K=84) -> fp16 out -------------
__global__ void k_gemm(const float* __restrict__ A, const float* __restrict__ B,
                       const float* __restrict__ bias, __half* __restrict__ C,
                       int nrows, int K, int M, int ldc) {
    __shared__ float As[16][68];
    __shared__ float Bs[16][68];
    int bm = blockIdx.y * 64, bn = blockIdx.x * 64;
    int tid = threadIdx.x;
    int tx = tid & 15, ty = tid >> 4;
    int ar = tid >> 2, ak = (tid & 3) * 4;
    int br = tid >> 4, bc = (tid & 15) * 4;
    float acc[4][4];
#pragma unroll
    for (int i = 0; i < 4; i++)
#pragma unroll
        for (int j = 0; j < 4; j++) acc[i][j] = 0.f;
    int arow = bm + ar;
    for (int k0 = 0; k0 < K; k0 += 16) {
        float a0 = 0.f, a1 = 0.f, a2 = 0.f, a3 = 0.f;
        if (arow < nrows) {
            const float* ap = A + (size_t)arow * K + k0 + ak;
            if (k0 + ak + 4 <= K) {
                float4 v = *(const float4*)ap;
                a0 = v.x; a1 = v.y; a2 = v.z; a3 = v.w;
            } else {
                int rem = K - (k0 + ak);
                if (rem > 0) a0 = ap[0];
                if (rem > 1) a1 = ap[1];
                if (rem > 2) a2 = ap[2];
                if (rem > 3) a3 = ap[3];
            }
        }
        As[ak + 0][ar] = a0; As[ak + 1][ar] = a1;
        As[ak + 2][ar] = a2; As[ak + 3][ar] = a3;
        float4 bv = make_float4(0.f, 0.f, 0.f, 0.f);
        if (k0 + br < K) bv = *(const float4*)(B + (size_t)(k0 + br) * M + bn + bc);
        *(float4*)&Bs[br][bc] = bv;
        __syncthreads();
#pragma unroll
        for (int k = 0; k < 16; k++) {
            float4 av = *(const float4*)&As[k][ty * 4];
            float4 bw = *(const float4*)&Bs[k][tx * 4];
            float a[4] = {av.x, av.y, av.z, av.w};
            float bb[4] = {bw.x, bw.y, bw.z, bw.w};
#pragma unroll
            for (int i = 0; i < 4; i++)
#pragma unroll
                for (int j = 0; j < 4; j++) acc[i][j] += a[i] * bb[j];
        }
        __syncthreads();
    }
#pragma unroll
    for (int i = 0; i < 4; i++) {
        int row = bm + ty * 4 + i;
        if (row >= nrows) continue;
#pragma unroll
        for (int j = 0; j < 4; j++) {
            int col = bn + tx * 4 + j;
            if (col >= M) continue;
            C[(size_t)row * ldc + col] = __float2half(gelu_f(acc[i][j] + bias[col]));
        }
    }
}

// ---------------- SpMM fp16-in: uint2 gathers, 64 thr/node, 4 nodes/block ----
struct SpHArgs {
    const __half* i0; const __half* i1; const __half* i2;
    void* o0; void* o1; void* o2;
    int oh0, oh1, oh2;            // output-is-half flags
    const float* bias;            // y==0 only
    int ld0, ld1, ld2;
};
__device__ __forceinline__ void h4acc(float4& acc, float w, uint2 hv) {
    float2 f0 = __half22float2(*(__half2*)&hv.x);
    float2 f1 = __half22float2(*(__half2*)&hv.y);
    acc.x += w * f0.x; acc.y += w * f0.y; acc.z += w * f1.x; acc.w += w * f1.y;
}
__global__ void __launch_bounds__(256) k_spmmh(SpHArgs a) {
    int y = blockIdx.y;
    const __half* in = (y == 0) ? a.i0 : (y == 1) ? a.i1 : a.i2;
    void* out = (y == 0) ? a.o0 : (y == 1) ? a.o1 : a.o2;
    int oh = (y == 0) ? a.oh0 : (y == 1) ? a.oh1 : a.oh2;
    int ldo = (y == 0) ? a.ld0 : (y == 1) ? a.ld1 : a.ld2;
    int node = blockIdx.x * 4 + (threadIdx.x >> 6);
    int t = threadIdx.x & 63;
    const uint2* in2 = (const uint2*)in;
    int beg = g_rowptr[node], end = g_rowptr[node + 1];
    float di = g_dinv[node];
    float w0 = di * di;
    float4 acc = make_float4(0.f, 0.f, 0.f, 0.f);
    h4acc(acc, w0, in2[(size_t)node * 64 + t]);
    float4 acc2 = make_float4(0.f, 0.f, 0.f, 0.f);
    int e = beg;
    for (; e + 1 < end; e += 2) {
        float wa = __ldg(&g_ew[e]);
        float wb = __ldg(&g_ew[e + 1]);
        uint2 va = __ldg(&in2[(size_t)__ldg(&g_col[e]) * 64 + t]);
        uint2 vb = __ldg(&in2[(size_t)__ldg(&g_col[e + 1]) * 64 + t]);
        h4acc(acc, wa, va);
        h4acc(acc2, wb, vb);
    }
    if (e < end) {
        float w = __ldg(&g_ew[e]);
        h4acc(acc, w, __ldg(&in2[(size_t)__ldg(&g_col[e]) * 64 + t]));
    }
    acc.x += acc2.x; acc.y += acc2.y; acc.z += acc2.z; acc.w += acc2.w;
    if (y == 0 && a.bias) {
        const float4 b = *(const float4*)(a.bias + t * 4);
        acc.x += b.x; acc.y += b.y; acc.z += b.z; acc.w += b.w;
    }
    if (oh) {
        __half2 lo = __floats2half2_rn(acc.x, acc.y);
        __half2 hi = __floats2half2_rn(acc.z, acc.w);
        uint2 st;
        st.x = *(uint32_t*)&lo;
        st.y = *(uint32_t*)&hi;
        *(uint2*)((__half*)out + (size_t)node * ldo + t * 4) = st;
    } else {
        *(float4*)((float*)out + (size_t)node * ldo + t * 4) = acc;
    }
}

// ---------------- fused: fp16 hop3 + LayerNorm + GELU -> afh ------------------
__global__ void __launch_bounds__(256) k_spmm_lnh(
    const __half* __restrict__ in, const float* __restrict__ cat,
    const float* __restrict__ bias, const float* __restrict__ lg,
    const float* __restrict__ lb, __half* __restrict__ af) {
    int tid = threadIdx.x;
    int t = tid & 63;
    int node = blockIdx.x * 4 + (tid >> 6);   // NN % 4 == 0
    const uint2* in2 = (const uint2*)in;
    int beg = g_rowptr[node], end = g_rowptr[node + 1];
    float di = g_dinv[node];
    float w0 = di * di;
    float4 a3 = make_float4(0.f, 0.f, 0.f, 0.f);
    h4acc(a3, w0, in2[(size_t)node * 64 + t]);
    float4 b3a = make_float4(0.f, 0.f, 0.f, 0.f);
    int e = beg;
    for (; e + 1 < end; e += 2) {
        float wa = __ldg(&g_ew[e]);
        float wb = __ldg(&g_ew[e + 1]);
        uint2 va = __ldg(&in2[(size_t)__ldg(&g_col[e]) * 64 + t]);
        uint2 vb = __ldg(&in2[(size_t)__ldg(&g_col[e + 1]) * 64 + t]);
        h4acc(a3, wa, va);
        h4acc(b3a, wb, vb);
    }
    if (e < end) {
        float w = __ldg(&g_ew[e]);
        h4acc(a3, w, __ldg(&in2[(size_t)__ldg(&g_col[e]) * 64 + t]));
    }
    a3.x += b3a.x; a3.y += b3a.y; a3.z += b3a.z; a3.w += b3a.w;
    {
        const float4 b4 = *(const float4*)(bias + t * 4);
        a3.x += b4.x; a3.y += b4.y; a3.z += b4.z; a3.w += b4.w;
    }
    const float* crow = cat + (size_t)node * 1024;
    float4 v0 = *(const float4*)(crow + t * 4);
    float4 v1 = *(const float4*)(crow + 256 + t * 4);
    float4 v2 = *(const float4*)(crow + 512 + t * 4);
    float s = v0.x + v0.y + v0.z + v0.w + v1.x + v1.y + v1.z + v1.w +
              v2.x + v2.y + v2.z + v2.w + a3.x + a3.y + a3.z + a3.w;
    float ss = v0.x*v0.x + v0.y*v0.y + v0.z*v0.z + v0.w*v0.w +
               v1.x*v1.x + v1.y*v1.y + v1.z*v1.z + v1.w*v1.w +
               v2.x*v2.x + v2.y*v2.y + v2.z*v2.z + v2.w*v2.w +
               a3.x*a3.x + a3.y*a3.y + a3.z*a3.z + a3.w*a3.w;
    int w_ = tid >> 5, lane = tid & 31;
#pragma unroll
    for (int o = 16; o; o >>= 1) {
        s += __shfl_down_sync(0xffffffffu, s, o);
        ss += __shfl_down_sync(0xffffffffu, ss, o);
    }
    __shared__ float gs[8], gss[8];
    if (lane == 0) { gs[w_] = s; gss[w_] = ss; }
    __syncthreads();
    int wb = w_ & ~1;
    float S = gs[wb] + gs[wb + 1];
    float SS = gss[wb] + gss[wb + 1];
    float mu = S * (1.0f / 1024.0f);
    float var = SS * (1.0f / 1024.0f) - mu * mu;
    float inv = rsqrtf(var + 1e-5f);
    __half* arow = af + (size_t)node * 1024;
    float vals[4][4] = {{v0.x, v0.y, v0.z, v0.w}, {v1.x, v1.y, v1.z, v1.w},
                        {v2.x, v2.y, v2.z, v2.w}, {a3.x, a3.y, a3.z, a3.w}};
#pragma unroll
    for (int r = 0; r < 4; r++) {
        int c = r * 256 + t * 4;
        float4 g4 = *(const float4*)(lg + c);
        float4 b4 = *(const float4*)(lb + c);
        __half2 lo = __floats2half2_rn(gelu_f((vals[r][0] - mu) * inv * g4.x + b4.x),
                                       gelu_f((vals[r][1] - mu) * inv * g4.y + b4.y));
        __half2 hi = __floats2half2_rn(gelu_f((vals[r][2] - mu) * inv * g4.z + b4.z),
                                       gelu_f((vals[r][3] - mu) * inv * g4.w + b4.w));
        uint2 st;
        st.x = *(uint32_t*)&lo;
        st.y = *(uint32_t*)&hi;
        *(uint2*)(arow + c) = st;
    }
}

// ---------------- LayerNorm(1024) + GELU -> afh (layer 0) --------------------
__global__ void k_ln(const float* __restrict__ h, const float* __restrict__ g,
                     const float* __restrict__ bta, __half* __restrict__ af) {
    int node = blockIdx.x;
    int tid = threadIdx.x;
    const float* row = h + (size_t)node * 1024;
    float v[4];
    float s = 0.f, ss = 0.f;
#pragma unroll
    for (int i = 0; i < 4; i++) {
        v[i] = row[tid + i * 256];
        s += v[i]; ss += v[i] * v[i];
    }
    __shared__ float shs[8], shss[8];
#pragma unroll
    for (int o = 16; o; o >>= 1) {
        s += __shfl_down_sync(0xffffffffu, s, o);
        ss += __shfl_down_sync(0xffffffffu, ss, o);
    }
    int w = tid >> 5, lane = tid & 31;
    if (lane == 0) { shs[w] = s; shss[w] = ss; }
    __syncthreads();
    if (w == 0) {
        s = (lane < 8) ? shs[lane] : 0.f;
        ss = (lane < 8) ? shss[lane] : 0.f;
#pragma unroll
        for (int o = 4; o; o >>= 1) {
            s += __shfl_down_sync(0xffffffffu, s, o);
            ss += __shfl_down_sync(0xffffffffu, ss, o);
        }
        if (lane == 0) { shs[0] = s; shss[0] = ss; }
    }
    __syncthreads();
    float mu = shs[0] * (1.0f / 1024.0f);
    float var = shss[0] * (1.0f / 1024.0f) - mu * mu;
    float inv = rsqrtf(var + 1e-5f);
#pragma unroll
    for (int i = 0; i < 4; i++) {
        int c = tid + i * 256;
        float t = (v[i] - mu) * inv * g[c] + bta[c];
        af[(size_t)node * 1024 + c] = __float2half(gelu_f(t));
    }
}

// ---------------- host orchestration -----------------------------------------
template <typename T>
static T* sym(const void* s) {
    void* p = nullptr;
    cudaGetSymbolAddress(&p, s);
    return (T*)p;
}

extern "C" void kernel_launch(void* const* d_in, const int* in_sizes, int n_in,
                              void* d_out, int out_size) {
    const float* x      = (const float*)d_in[0];
    const int*   ei     = (const int*)d_in[1];
    const float* w_in   = (const float*)d_in[2];
    const float* b_in   = (const float*)d_in[3];
    const float* mh_w0  = (const float*)d_in[4];
    const float* mh_b0  = (const float*)d_in[5];
    const float* mh_w12 = (const float*)d_in[6];
    const float* mh_b12 = (const float*)d_in[7];
    const float* ln_g   = (const float*)d_in[8];
    const float* ln_b   = (const float*)d_in[9];
    const float* w1     = (const float*)d_in[10];
    const float* b1     = (const float*)d_in[11];
    const float* w2     = (const float*)d_in[12];
    const float* b2     = (const float*)d_in[13];
    const float* w3     = (const float*)d_in[14];
    const float* b3     = (const float*)d_in[15];
    float* out = (float*)d_out;

    float*  cat  = sym<float>(g_cat);
    __half* tmph = sym<__half>(g_tmph);
    __half* mlph = sym<__half>(g_mlph);
    __half* afh  = sym<__half>(g_afh);
    __half* wth  = sym<__half>(g_wth);

    static cudaStream_t s1 = nullptr, s2 = nullptr;
    static cudaEvent_t ev[16];
    static bool init_done = false;
    if (!init_done) {
        cudaFuncSetAttribute(k_mma, cudaFuncAttributeMaxDynamicSharedMemorySize, 98304);
        cudaStreamCreateWithFlags(&s1, cudaStreamNonBlocking);
        cudaStreamCreateWithFlags(&s2, cudaStreamNonBlocking);
        for (int i = 0; i < 16; i++)
            cudaEventCreateWithFlags(&ev[i], cudaEventDisableTiming);
        init_done = true;
    }

    const size_t OFF_L0 = 0, OFF_L1 = 262144, OFF_W1 = 2359296, OFF_W2 = 2621440;

    cudaEventRecord(ev[0], 0);
    cudaStreamWaitEvent(s1, ev[0], 0);
    cudaStreamWaitEvent(s2, ev[0], 0);

    // s1: CSR build
    k_zero<<<(NN + 255) / 256, 256, 0, s1>>>();
    k_count<<<(EE + 255) / 256, 256, 0, s1>>>(ei);
    k_dinvk<<<(NN + 255) / 256, 256, 0, s1>>>();
    k_scan<<<1, 1024, 0, s1>>>();
    k_scatter<<<(EE + 255) / 256, 256, 0, s1>>>(ei);

    // s2: big weight conversions
    k_wconv<<<dim3(1024, 8), 256, 0, s2>>>(mh_w12, wth + OFF_L1, 1024, 256, 262144, 262144);
    k_wconv<<<dim3(1024, 1), 256, 0, s2>>>(w1, wth + OFF_W1, 1024, 256, 262144, 262144);
    k_wconv<<<dim3(128, 1), 256, 0, s2>>>(w2, wth + OFF_W2, 256, 128, 32768, 32768);
    cudaEventRecord(ev[1], s2);

    // main: layer-0 weights + input projection -> afh (fp16)
    k_wconv<<<dim3(256, 4), 256>>>(mh_w0, wth + OFF_L0, 256, 256, 65536, 65536);
    k_gemm<<<dim3(4, (NN + 63) / 64), 256>>>(x, w_in, b_in, afh, NN, 84, 256, 256);
    cudaEventRecord(ev[2], 0);

    // half slabs
    __half* th1  = tmph;
    __half* th2  = tmph + (size_t)NN * 256;
    __half* th3  = tmph + (size_t)NN * 512;
    __half* uah  = tmph + (size_t)NN * 768;
    __half* ubh  = tmph + (size_t)NN * 1024;
    __half* t1h2 = tmph + (size_t)NN * 1280;
    const int SPG = NN / 4;

    // ---- layer 0 (fp16 hops on s1, per-range GEMMs on main as hops land) ----
    cudaStreamWaitEvent(s1, ev[2], 0);
    {
        SpHArgs p1{afh, nullptr, nullptr, th1, nullptr, nullptr, 1, 0, 0,
                   nullptr, 256, 0, 0};
        k_spmmh<<<dim3(SPG, 1), 256, 0, s1>>>(p1);
        cudaEventRecord(ev[3], s1);
        SpHArgs p2{th1, nullptr, nullptr, th2, nullptr, nullptr, 1, 0, 0,
                   nullptr, 256, 0, 0};
        k_spmmh<<<dim3(SPG, 1), 256, 0, s1>>>(p2);
        cudaEventRecord(ev[4], s1);
        SpHArgs p3{th2, nullptr, nullptr, th3, nullptr, nullptr, 1, 0, 0,
                   nullptr, 256, 0, 0};
        k_spmmh<<<dim3(SPG, 1), 256, 0, s1>>>(p3);
        cudaEventRecord(ev[5], s1);

        GOut o;
        o.a[0] = afh; o.a[1] = th1; o.a[2] = th2; o.a[3] = th3;
        o.p[0] = cat; o.p[1] = cat + 256; o.p[2] = cat + 512; o.p[3] = cat + 768;
        o.b[0] = mh_b0; o.b[1] = mh_b0 + 256; o.b[2] = mh_b0 + 512; o.b[3] = mh_b0 + 768;
        o.ld[0] = o.ld[1] = o.ld[2] = o.ld[3] = 1024;
        o.act = 0; o.outHalf = 0;
        o.w3p = nullptr; o.b3p = nullptr; o.doutp = nullptr;
        k_mma<<<dim3(2, 79), 128, 98304>>>(wth + OFF_L0, o, 256, 0);
        cudaStreamWaitEvent(0, ev[3], 0);
        k_mma<<<dim3(2, 79), 128, 98304>>>(wth + OFF_L0, o, 256, 2);
        cudaStreamWaitEvent(0, ev[4], 0);
        k_mma<<<dim3(2, 79), 128, 98304>>>(wth + OFF_L0, o, 256, 4);
        cudaStreamWaitEvent(0, ev[5], 0);
        k_mma<<<dim3(2, 79), 128, 98304>>>(wth + OFF_L0, o, 256, 6);
        k_ln<<<NN, 256>>>(cat, ln_g, ln_b, afh);
    }

    cudaStreamWaitEvent(0, ev[1], 0);   // big weights ready

    // ---- layers 1,2: r0 on s2 ∥ ranges1-3 + spmm on main ----
    auto LAYER = [&](size_t woff, const float* bb, const float* lg, const float* lb,
                     int evStart, int evR0) {
        GOut of;   // range 0 -> cat fp32 (with bias)
        of.a[0] = of.a[1] = of.a[2] = of.a[3] = afh;
        of.p[0] = cat; of.p[1] = th1; of.p[2] = th2; of.p[3] = th3;
        of.b[0] = bb;  of.b[1] = nullptr; of.b[2] = nullptr; of.b[3] = nullptr;
        of.ld[0] = 1024; of.ld[1] = 256; of.ld[2] = 256; of.ld[3] = 256;
        of.act = 0; of.outHalf = 0;
        of.w3p = nullptr; of.b3p = nullptr; of.doutp = nullptr;
        cudaEventRecord(ev[evStart], 0);
        cudaStreamWaitEvent(s2, ev[evStart], 0);
        k_mma<<<dim3(2, 79), 128, 98304, s2>>>(wth + woff, of, 1024, 0);  // r0 -> cat
        cudaEventRecord(ev[evR0], s2);

        GOut oh2 = of;
        oh2.outHalf = 1;                                                   // r1-3 -> half
        k_mma<<<dim3(6, 79), 128, 98304>>>(wth + woff, oh2, 1024, 2);

        SpHArgs h1{th1, th2, th3, cat + 256, uah, ubh, 0, 1, 1,
                   bb + 256, 1024, 256, 256};
        k_spmmh<<<dim3(SPG, 3), 256>>>(h1);
        SpHArgs h2{uah, ubh, nullptr, cat + 512, t1h2, nullptr, 0, 1, 0,
                   bb + 512, 1024, 256, 0};
        k_spmmh<<<dim3(SPG, 2), 256>>>(h2);
        cudaStreamWaitEvent(0, ev[evR0], 0);
        k_spmm_lnh<<<SPG, 256>>>(t1h2, cat, bb + 768, lg, lb, afh);
    };

    LAYER(OFF_L1,              mh_b12,        ln_g + 1024, ln_b + 1024, 6, 7);
    LAYER(OFF_L1 + 4 * 262144, mh_b12 + 1024, ln_g + 2048, ln_b + 2048, 8, 9);

    // ---- head MLP: w1 (gelu -> fp16 mlph) -> w2+w3 fused (gelu, dot, bias) ----
    GOut oh;
    oh.a[0] = afh; oh.a[1] = oh.a[2] = oh.a[3] = nullptr;
    oh.p[0] = mlph; oh.p[1] = oh.p[2] = oh.p[3] = nullptr;
    oh.b[0] = b1;  oh.b[1] = oh.b[2] = oh.b[3] = nullptr;
    oh.ld[0] = 256; oh.ld[1] = oh.ld[2] = oh.ld[3] = 0;
    oh.act = 2; oh.outHalf = 1;
    oh.w3p = nullptr; oh.b3p = nullptr; oh.doutp = nullptr;
    k_mma<<<dim3(2, 79), 128, 98304>>>(wth + OFF_W1, oh, 1024, 0);

    GOut o2;
    o2.a[0] = mlph; o2.a[1] = o2.a[2] = o2.a[3] = nullptr;
    o2.p[0] = nullptr; o2.p[1] = o2.p[2] = o2.p[3] = nullptr;
    o2.b[0] = b2;   o2.b[1] = o2.b[2] = o2.b[3] = nullptr;
    o2.ld[0] = 128; o2.ld[1] = o2.ld[2] = o2.ld[3] = 0;
    o2.act = 3; o2.outHalf = 0;
    o2.w3p = w3; o2.b3p = b3; o2.doutp = out;
    k_mma<<<dim3(1, 79), 128, 98304>>>(wth + OFF_W2, o2, 256, 0);
}

// round 13
// speedup vs baseline: 1.5308x; 1.0240x over previous
#include <cuda_runtime.h>
#include <cuda_fp16.h>
#include <math.h>
#include <stdint.h>

#define NN 10000
#define EE 160000

// ---------------- scratch (device globals) ----------------------------------
__device__ float g_dinv[NN];
__device__ int   g_count[NN];
__device__ int   g_fill[NN];
__device__ int   g_rowptr[NN + 1];
__device__ int   g_col[EE];
__device__ float g_ew[EE];
__device__ float g_cat[(size_t)NN * 1024];
__device__ __half g_tmph[(size_t)NN * 1536];  // 6 half slabs of NN*256
__device__ __half g_mlph[NN * 256];
__device__ __half g_afh[(size_t)NN * 1024];   // fp16 GEMM input
#define WTOT 2654208
__device__ __half g_wth[WTOT];                // fp16 transposed weights

__device__ __forceinline__ float gelu_f(float x) {
    return 0.5f * x * (1.0f + erff(x * 0.70710678118654752f));
}
__device__ __forceinline__ uint32_t smem_u32(const void* p) {
    uint32_t a;
    asm("{ .reg .u64 t; cvta.to.shared.u64 t, %1; cvt.u32.u64 %0, t; }" : "=r"(a) : "l"(p));
    return a;
}
__device__ __forceinline__ void ldsm4(uint32_t& r0, uint32_t& r1, uint32_t& r2,
                                      uint32_t& r3, uint32_t addr) {
    asm volatile("ldmatrix.sync.aligned.m8n8.x4.shared.b16 {%0,%1,%2,%3}, [%4];"
                 : "=r"(r0), "=r"(r1), "=r"(r2), "=r"(r3) : "r"(addr));
}
__device__ __forceinline__ void mma_f16(float* c, const uint32_t* a, const uint32_t* b) {
    asm volatile(
        "mma.sync.aligned.m16n8k16.row.col.f32.f16.f16.f32 "
        "{%0,%1,%2,%3}, {%4,%5,%6,%7}, {%8,%9}, {%0,%1,%2,%3};"
        : "+f"(c[0]), "+f"(c[1]), "+f"(c[2]), "+f"(c[3])
        : "r"(a[0]), "r"(a[1]), "r"(a[2]), "r"(a[3]), "r"(b[0]), "r"(b[1]));
}

// ---------------- graph preprocessing ---------------------------------------
__global__ void k_zero() {
    int i = blockIdx.x * blockDim.x + threadIdx.x;
    if (i < NN) { g_count[i] = 0; g_fill[i] = 0; }
}
__global__ void k_count(const int* __restrict__ ei) {
    int e = blockIdx.x * blockDim.x + threadIdx.x;
    if (e < EE) atomicAdd(&g_count[ei[EE + e]], 1);
}
__global__ void k_dinvk() {
    int i = blockIdx.x * blockDim.x + threadIdx.x;
    if (i < NN) g_dinv[i] = rsqrtf((float)(g_count[i] + 1));
}
__global__ void k_scan() {
    int tid = threadIdx.x, lane = tid & 31, w = tid >> 5;
    const int chunk = 10;
    int b = tid * chunk, e = min(b + chunk, NN);
    int local = 0;
    for (int i = b; i < e; i++) local += g_count[i];
    int v = local;
#pragma unroll
    for (int o = 1; o < 32; o <<= 1) {
        int t = __shfl_up_sync(0xffffffffu, v, o);
        if (lane >= o) v += t;
    }
    __shared__ int ws[32];
    if (lane == 31) ws[w] = v;
    __syncthreads();
    if (w == 0) {
        int s = ws[lane];
#pragma unroll
        for (int o = 1; o < 32; o <<= 1) {
            int t = __shfl_up_sync(0xffffffffu, s, o);
            if (lane >= o) s += t;
        }
        ws[lane] = s;
    }
    __syncthreads();
    int run = v - local + (w ? ws[w - 1] : 0);
    for (int i = b; i < e; i++) { int c = g_count[i]; g_rowptr[i] = run; run += c; }
    if (tid == 1023) g_rowptr[NN] = run;
}
__global__ void k_scatter(const int* __restrict__ ei) {
    int e = blockIdx.x * blockDim.x + threadIdx.x;
    if (e >= EE) return;
    int s = ei[e], d = ei[EE + e];
    int pos = g_rowptr[d] + atomicAdd(&g_fill[d], 1);
    g_col[pos] = s;
    g_ew[pos] = g_dinv[s] * g_dinv[d];
}

// ---------------- weight conversion (transposed, fp16) -----------------------
__global__ void k_wconv(const float* __restrict__ src, __half* __restrict__ dst,
                        int K, int N, size_t srcStride, size_t dstStride) {
    int m = blockIdx.y;
    int e = blockIdx.x * 256 + threadIdx.x;
    if (e >= K * N) return;
    int k = e / N, n = e % N;
    dst[m * dstStride + (size_t)n * K + k] = __float2half(src[m * srcStride + e]);
}

// ---------------- fp16 mma GEMM (m16n8k16, fp32 accum) ------------------------
struct GOut {
    const __half* a[4];
    void* p[4];
    const float* b[4];
    int ld[4];
    int act;      // 0 none, 2 gelu, 3 gelu+dot(w3)+b3 -> dout
    int outHalf;
    const float* w3p;
    const float* b3p;
    float* doutp;
};

__global__ void __launch_bounds__(128, 2) k_mma(
    const __half* __restrict__ B, GOut o, int K, int bnoff) {
    extern __shared__ char smc[];
    uint32_t sb = smem_u32(smc);
    int tid = threadIdx.x, lane = tid & 31, wid = tid >> 5;
    int WM = wid >> 1, WN = wid & 1;
    int bm = blockIdx.y * 128, bn = (blockIdx.x + bnoff) * 128;
    int range = bn >> 8;
    const __half* A = o.a[range];
    const int NIT = K >> 6;

    float acc[4][8][4];
#pragma unroll
    for (int i = 0; i < 4; i++)
#pragma unroll
        for (int j = 0; j < 8; j++)
#pragma unroll
            for (int r = 0; r < 4; r++) acc[i][j][r] = 0.f;

    auto LOAD = [&](int it) {
        int st = it % 3;
        uint32_t da = sb + st * 32768;
        uint32_t db = da + 16384;
        int k0 = it << 6;
#pragma unroll
        for (int i = 0; i < 8; i++) {
            int idx = i * 128 + tid;
            int row = idx >> 3, c = idx & 7;
            uint32_t so = row * 128 + ((c ^ (row & 7)) << 4);
            int ar = bm + row;
            const __half* as = A + (size_t)min(ar, NN - 1) * K + k0 + c * 8;
            int sz = (ar < NN) ? 16 : 0;
            asm volatile("cp.async.cg.shared.global [%0], [%1], 16, %2;"
                         :: "r"(da + so), "l"(as), "r"(sz));
            const __half* bs = B + (size_t)(bn + row) * K + k0 + c * 8;
            asm volatile("cp.async.cg.shared.global [%0], [%1], 16;"
                         :: "r"(db + so), "l"(bs));
        }
        asm volatile("cp.async.commit_group;");
    };

    LOAD(0);
    LOAD(1);
    for (int it = 0; it < NIT; it++) {
        asm volatile("cp.async.wait_group 1;");
        __syncthreads();
        if (it + 2 < NIT) LOAD(it + 2);
        int st = it % 3;
        uint32_t da = sb + st * 32768, db = da + 16384;
#pragma unroll
        for (int kk = 0; kk < 4; kk++) {
            uint32_t a[4][4], b[8][2];
#pragma unroll
            for (int mt = 0; mt < 4; mt++) {
                int row = WM * 64 + mt * 16 + (lane & 15);
                int ch = kk * 2 + (lane >> 4);
                uint32_t ad = da + row * 128 + ((ch ^ (row & 7)) << 4);
                ldsm4(a[mt][0], a[mt][1], a[mt][2], a[mt][3], ad);
            }
#pragma unroll
            for (int ng = 0; ng < 4; ng++) {
                int row = WN * 64 + ng * 16 + (lane & 7) + ((lane & 16) >> 1);
                int ch = kk * 2 + ((lane >> 3) & 1);
                uint32_t bd = db + row * 128 + ((ch ^ (row & 7)) << 4);
                ldsm4(b[2 * ng][0], b[2 * ng][1], b[2 * ng + 1][0], b[2 * ng + 1][1], bd);
            }
#pragma unroll
            for (int mt = 0; mt < 4; mt++)
#pragma unroll
                for (int nt = 0; nt < 8; nt++)
                    mma_f16(acc[mt][nt], a[mt], b[nt]);
        }
    }

    const float* bias = o.b[range];
    int act = o.act;

    if (act == 3) {
        __shared__ float red[128];
        if (tid < 128) red[tid] = 0.f;
        __syncthreads();
#pragma unroll
        for (int mt = 0; mt < 4; mt++) {
            float p0 = 0.f, p1 = 0.f;
#pragma unroll
            for (int nt = 0; nt < 8; nt++) {
                int gcol = WN * 64 + nt * 8 + ((lane & 3) << 1);
                float b0 = bias[gcol], b1 = bias[gcol + 1];
                float w0 = o.w3p[gcol], w1 = o.w3p[gcol + 1];
                p0 += gelu_f(acc[mt][nt][0] + b0) * w0 + gelu_f(acc[mt][nt][1] + b1) * w1;
                p1 += gelu_f(acc[mt][nt][2] + b0) * w0 + gelu_f(acc[mt][nt][3] + b1) * w1;
            }
            p0 += __shfl_xor_sync(0xffffffffu, p0, 1);
            p0 += __shfl_xor_sync(0xffffffffu, p0, 2);
            p1 += __shfl_xor_sync(0xffffffffu, p1, 1);
            p1 += __shfl_xor_sync(0xffffffffu, p1, 2);
            if ((lane & 3) == 0) {
                int lr = WM * 64 + mt * 16 + (lane >> 2);
                atomicAdd(&red[lr], p0);
                atomicAdd(&red[lr + 8], p1);
            }
        }
        __syncthreads();
        if (tid < 128) {
            int gr = bm + tid;
            if (gr < NN) o.doutp[gr] = red[tid] + o.b3p[0];
        }
        return;
    }

    int ldd = o.ld[range];
    if (o.outHalf) {
        __half* Dh = (__half*)o.p[range];
#pragma unroll
        for (int mt = 0; mt < 4; mt++) {
            int r = bm + WM * 64 + mt * 16 + (lane >> 2);
#pragma unroll
            for (int nt = 0; nt < 8; nt++) {
                int gcol = (bn & 255) + WN * 64 + nt * 8 + ((lane & 3) << 1);
                float v0 = acc[mt][nt][0], v1 = acc[mt][nt][1];
                float v2 = acc[mt][nt][2], v3 = acc[mt][nt][3];
                if (act == 2) {
                    float b0 = bias[gcol], b1 = bias[gcol + 1];
                    v0 = gelu_f(v0 + b0); v1 = gelu_f(v1 + b1);
                    v2 = gelu_f(v2 + b0); v3 = gelu_f(v3 + b1);
                }
                __half2 hv01 = __floats2half2_rn(v0, v1);
                __half2 hv23 = __floats2half2_rn(v2, v3);
                if (r < NN) *(__half2*)(Dh + (size_t)r * ldd + gcol) = hv01;
                if (r + 8 < NN) *(__half2*)(Dh + (size_t)(r + 8) * ldd + gcol) = hv23;
            }
        }
        return;
    }

    float* D = (float*)o.p[range];
#pragma unroll
    for (int mt = 0; mt < 4; mt++) {
        int r = bm + WM * 64 + mt * 16 + (lane >> 2);
#pragma unroll
        for (int nt = 0; nt < 8; nt++) {
            int gcol = (bn & 255) + WN * 64 + nt * 8 + ((lane & 3) << 1);
            float b0 = 0.f, b1 = 0.f;
            if (bias) { b0 = bias[gcol]; b1 = bias[gcol + 1]; }
            float v0 = acc[mt][nt][0] + b0, v1 = acc[mt][nt][1] + b1;
            float v2 = acc[mt][nt][2] + b0, v3 = acc[mt][nt][3] + b1;
            if (r < NN) *(float2*)(D + (size_t)r * ldd + gcol) = make_float2(v0, v1);
            if (r + 8 < NN) *(float2*)(D + (size_t)(r + 8) * ldd + gcol) = make_float2(v2, v3);
        }
    }
}

// ---------------- fp32 SGEMM (input projection, K=84) -> fp16 out -------------
__global__ void k_gemm(const float* __restrict__ A, const float* __restrict__ B,
                       const float* __restrict__ bias, __half* __restrict__ C,
                       int nrows, int K, int M, int ldc) {
    __shared__ float As[16][68];
    __shared__ float Bs[16][68];
    int bm = blockIdx.y * 64, bn = blockIdx.x * 64;
    int tid = threadIdx.x;
    int tx = tid & 15, ty = tid >> 4;
    int ar = tid >> 2, ak = (tid & 3) * 4;
    int br = tid >> 4, bc = (tid & 15) * 4;
    float acc[4][4];
#pragma unroll
    for (int i = 0; i < 4; i++)
#pragma unroll
        for (int j = 0; j < 4; j++) acc[i][j] = 0.f;
    int arow = bm + ar;
    for (int k0 = 0; k0 < K; k0 += 16) {
        float a0 = 0.f, a1 = 0.f, a2 = 0.f, a3 = 0.f;
        if (arow < nrows) {
            const float* ap = A + (size_t)arow * K + k0 + ak;
            if (k0 + ak + 4 <= K) {
                float4 v = *(const float4*)ap;
                a0 = v.x; a1 = v.y; a2 = v.z; a3 = v.w;
            } else {
                int rem = K - (k0 + ak);
                if (rem > 0) a0 = ap[0];
                if (rem > 1) a1 = ap[1];
                if (rem > 2) a2 = ap[2];
                if (rem > 3) a3 = ap[3];
            }
        }
        As[ak + 0][ar] = a0; As[ak + 1][ar] = a1;
        As[ak + 2][ar] = a2; As[ak + 3][ar] = a3;
        float4 bv = make_float4(0.f, 0.f, 0.f, 0.f);
        if (k0 + br < K) bv = *(const float4*)(B + (size_t)(k0 + br) * M + bn + bc);
        *(float4*)&Bs[br][bc] = bv;
        __syncthreads();
#pragma unroll
        for (int k = 0; k < 16; k++) {
            float4 av = *(const float4*)&As[k][ty * 4];
            float4 bw = *(const float4*)&Bs[k][tx * 4];
            float a[4] = {av.x, av.y, av.z, av.w};
            float bb[4] = {bw.x, bw.y, bw.z, bw.w};
#pragma unroll
            for (int i = 0; i < 4; i++)
#pragma unroll
                for (int j = 0; j < 4; j++) acc[i][j] += a[i] * bb[j];
        }
        __syncthreads();
    }
#pragma unroll
    for (int i = 0; i < 4; i++) {
        int row = bm + ty * 4 + i;
        if (row >= nrows) continue;
#pragma unroll
        for (int j = 0; j < 4; j++) {
            int col = bn + tx * 4 + j;
            if (col >= M) continue;
            C[(size_t)row * ldc + col] = __float2half(gelu_f(acc[i][j] + bias[col]));
        }
    }
}

// ---------------- SpMM fp16: uint4 gathers, 32 thr/node, 8 nodes/block -------
struct SpHArgs {
    const __half* i0; const __half* i1; const __half* i2;
    void* o0; void* o1; void* o2;
    int oh0, oh1, oh2;
    const float* bias;            // y==0 only
    int ld0, ld1, ld2;
};
__device__ __forceinline__ void h8acc(float* acc, float w, uint4 hv) {
    const __half2* h = (const __half2*)&hv;
#pragma unroll
    for (int i = 0; i < 4; i++) {
        float2 f = __half22float2(h[i]);
        acc[2 * i] += w * f.x;
        acc[2 * i + 1] += w * f.y;
    }
}
__global__ void __launch_bounds__(256) k_spmmh(SpHArgs a) {
    int y = blockIdx.y;
    const __half* in = (y == 0) ? a.i0 : (y == 1) ? a.i1 : a.i2;
    void* out = (y == 0) ? a.o0 : (y == 1) ? a.o1 : a.o2;
    int oh = (y == 0) ? a.oh0 : (y == 1) ? a.oh1 : a.oh2;
    int ldo = (y == 0) ? a.ld0 : (y == 1) ? a.ld1 : a.ld2;
    int node = blockIdx.x * 8 + (threadIdx.x >> 5);   // NN % 8 == 0
    int t = threadIdx.x & 31;
    const uint4* in4 = (const uint4*)in;              // 32 uint4 per 256-half row
    int beg = g_rowptr[node], end = g_rowptr[node + 1];
    float di = g_dinv[node];
    float acc[8] = {0.f, 0.f, 0.f, 0.f, 0.f, 0.f, 0.f, 0.f};
    float acc2[8] = {0.f, 0.f, 0.f, 0.f, 0.f, 0.f, 0.f, 0.f};
    h8acc(acc, di * di, in4[(size_t)node * 32 + t]);
    int e = beg;
    for (; e + 1 < end; e += 2) {
        float wa = __ldg(&g_ew[e]);
        float wb = __ldg(&g_ew[e + 1]);
        uint4 va = __ldg(&in4[(size_t)__ldg(&g_col[e]) * 32 + t]);
        uint4 vb = __ldg(&in4[(size_t)__ldg(&g_col[e + 1]) * 32 + t]);
        h8acc(acc, wa, va);
        h8acc(acc2, wb, vb);
    }
    if (e < end) {
        float w = __ldg(&g_ew[e]);
        h8acc(acc, w, __ldg(&in4[(size_t)__ldg(&g_col[e]) * 32 + t]));
    }
#pragma unroll
    for (int i = 0; i < 8; i++) acc[i] += acc2[i];
    if (y == 0 && a.bias) {
        float4 b0 = *(const float4*)(a.bias + t * 8);
        float4 b1 = *(const float4*)(a.bias + t * 8 + 4);
        acc[0] += b0.x; acc[1] += b0.y; acc[2] += b0.z; acc[3] += b0.w;
        acc[4] += b1.x; acc[5] += b1.y; acc[6] += b1.z; acc[7] += b1.w;
    }
    if (oh) {
        uint4 st;
        __half2* sh = (__half2*)&st;
#pragma unroll
        for (int i = 0; i < 4; i++)
            sh[i] = __floats2half2_rn(acc[2 * i], acc[2 * i + 1]);
        *(uint4*)((__half*)out + (size_t)node * ldo + t * 8) = st;
    } else {
        float* op = (float*)out + (size_t)node * ldo + t * 8;
        *(float4*)op = make_float4(acc[0], acc[1], acc[2], acc[3]);
        *(float4*)(op + 4) = make_float4(acc[4], acc[5], acc[6], acc[7]);
    }
}

// ---------------- fused: fp16 hop3 + LayerNorm + GELU -> afh ------------------
// one warp per node: warp-local LN reduction, no smem/syncthreads
__global__ void __launch_bounds__(256) k_spmm_lnh(
    const __half* __restrict__ in, const float* __restrict__ cat,
    const float* __restrict__ bias, const float* __restrict__ lg,
    const float* __restrict__ lb, __half* __restrict__ af) {
    int tid = threadIdx.x;
    int t = tid & 31;
    int node = blockIdx.x * 8 + (tid >> 5);   // NN % 8 == 0
    const uint4* in4 = (const uint4*)in;
    int beg = g_rowptr[node], end = g_rowptr[node + 1];
    float di = g_dinv[node];
    float a3[8] = {0.f, 0.f, 0.f, 0.f, 0.f, 0.f, 0.f, 0.f};
    float b3a[8] = {0.f, 0.f, 0.f, 0.f, 0.f, 0.f, 0.f, 0.f};
    h8acc(a3, di * di, in4[(size_t)node * 32 + t]);
    int e = beg;
    for (; e + 1 < end; e += 2) {
        float wa = __ldg(&g_ew[e]);
        float wb = __ldg(&g_ew[e + 1]);
        uint4 va = __ldg(&in4[(size_t)__ldg(&g_col[e]) * 32 + t]);
        uint4 vb = __ldg(&in4[(size_t)__ldg(&g_col[e + 1]) * 32 + t]);
        h8acc(a3, wa, va);
        h8acc(b3a, wb, vb);
    }
    if (e < end) {
        float w = __ldg(&g_ew[e]);
        h8acc(a3, w, __ldg(&in4[(size_t)__ldg(&g_col[e]) * 32 + t]));
    }
#pragma unroll
    for (int i = 0; i < 8; i++) a3[i] += b3a[i];
    {
        float4 b0 = *(const float4*)(bias + t * 8);
        float4 b1 = *(const float4*)(bias + t * 8 + 4);
        a3[0] += b0.x; a3[1] += b0.y; a3[2] += b0.z; a3[3] += b0.w;
        a3[4] += b1.x; a3[5] += b1.y; a3[6] += b1.z; a3[7] += b1.w;
    }
    const float* crow = cat + (size_t)node * 1024;
    float v[3][8];
#pragma unroll
    for (int r = 0; r < 3; r++) {
        float4 x0 = *(const float4*)(crow + r * 256 + t * 8);
        float4 x1 = *(const float4*)(crow + r * 256 + t * 8 + 4);
        v[r][0] = x0.x; v[r][1] = x0.y; v[r][2] = x0.z; v[r][3] = x0.w;
        v[r][4] = x1.x; v[r][5] = x1.y; v[r][6] = x1.z; v[r][7] = x1.w;
    }
    float s = 0.f, ss = 0.f;
#pragma unroll
    for (int i = 0; i < 8; i++) {
        s += v[0][i] + v[1][i] + v[2][i] + a3[i];
        ss += v[0][i] * v[0][i] + v[1][i] * v[1][i] + v[2][i] * v[2][i] + a3[i] * a3[i];
    }
#pragma unroll
    for (int o = 16; o; o >>= 1) {
        s += __shfl_xor_sync(0xffffffffu, s, o);
        ss += __shfl_xor_sync(0xffffffffu, ss, o);
    }
    float mu = s * (1.0f / 1024.0f);
    float var = ss * (1.0f / 1024.0f) - mu * mu;
    float inv = rsqrtf(var + 1e-5f);
    __half* arow = af + (size_t)node * 1024;
#pragma unroll
    for (int r = 0; r < 4; r++) {
        int c = r * 256 + t * 8;
        float4 g0 = *(const float4*)(lg + c);
        float4 g1 = *(const float4*)(lg + c + 4);
        float4 bb0 = *(const float4*)(lb + c);
        float4 bb1 = *(const float4*)(lb + c + 4);
        const float* vr = (r < 3) ? v[r] : a3;
        float gv[8] = {g0.x, g0.y, g0.z, g0.w, g1.x, g1.y, g1.z, g1.w};
        float bv[8] = {bb0.x, bb0.y, bb0.z, bb0.w, bb1.x, bb1.y, bb1.z, bb1.w};
        uint4 st;
        __half2* sh = (__half2*)&st;
#pragma unroll
        for (int i = 0; i < 4; i++) {
            float q0 = gelu_f((vr[2 * i] - mu) * inv * gv[2 * i] + bv[2 * i]);
            float q1 = gelu_f((vr[2 * i + 1] - mu) * inv * gv[2 * i + 1] + bv[2 * i + 1]);
            sh[i] = __floats2half2_rn(q0, q1);
        }
        *(uint4*)(arow + c) = st;
    }
}

// ---------------- LayerNorm(1024) + GELU -> afh (layer 0) --------------------
__global__ void k_ln(const float* __restrict__ h, const float* __restrict__ g,
                     const float* __restrict__ bta, __half* __restrict__ af) {
    int node = blockIdx.x;
    int tid = threadIdx.x;
    const float* row = h + (size_t)node * 1024;
    float v[4];
    float s = 0.f, ss = 0.f;
#pragma unroll
    for (int i = 0; i < 4; i++) {
        v[i] = row[tid + i * 256];
        s += v[i]; ss += v[i] * v[i];
    }
    __shared__ float shs[8], shss[8];
#pragma unroll
    for (int o = 16; o; o >>= 1) {
        s += __shfl_down_sync(0xffffffffu, s, o);
        ss += __shfl_down_sync(0xffffffffu, ss, o);
    }
    int w = tid >> 5, lane = tid & 31;
    if (lane == 0) { shs[w] = s; shss[w] = ss; }
    __syncthreads();
    if (w == 0) {
        s = (lane < 8) ? shs[lane] : 0.f;
        ss = (lane < 8) ? shss[lane] : 0.f;
#pragma unroll
        for (int o = 4; o; o >>= 1) {
            s += __shfl_down_sync(0xffffffffu, s, o);
            ss += __shfl_down_sync(0xffffffffu, ss, o);
        }
        if (lane == 0) { shs[0] = s; shss[0] = ss; }
    }
    __syncthreads();
    float mu = shs[0] * (1.0f / 1024.0f);
    float var = shss[0] * (1.0f / 1024.0f) - mu * mu;
    float inv = rsqrtf(var + 1e-5f);
#pragma unroll
    for (int i = 0; i < 4; i++) {
        int c = tid + i * 256;
        float t = (v[i] - mu) * inv * g[c] + bta[c];
        af[(size_t)node * 1024 + c] = __float2half(gelu_f(t));
    }
}

// ---------------- host orchestration -----------------------------------------
template <typename T>
static T* sym(const void* s) {
    void* p = nullptr;
    cudaGetSymbolAddress(&p, s);
    return (T*)p;
}

extern "C" void kernel_launch(void* const* d_in, const int* in_sizes, int n_in,
                              void* d_out, int out_size) {
    const float* x      = (const float*)d_in[0];
    const int*   ei     = (const int*)d_in[1];
    const float* w_in   = (const float*)d_in[2];
    const float* b_in   = (const float*)d_in[3];
    const float* mh_w0  = (const float*)d_in[4];
    const float* mh_b0  = (const float*)d_in[5];
    const float* mh_w12 = (const float*)d_in[6];
    const float* mh_b12 = (const float*)d_in[7];
    const float* ln_g   = (const float*)d_in[8];
    const float* ln_b   = (const float*)d_in[9];
    const float* w1     = (const float*)d_in[10];
    const float* b1     = (const float*)d_in[11];
    const float* w2     = (const float*)d_in[12];
    const float* b2     = (const float*)d_in[13];
    const float* w3     = (const float*)d_in[14];
    const float* b3     = (const float*)d_in[15];
    float* out = (float*)d_out;

    float*  cat  = sym<float>(g_cat);
    __half* tmph = sym<__half>(g_tmph);
    __half* mlph = sym<__half>(g_mlph);
    __half* afh  = sym<__half>(g_afh);
    __half* wth  = sym<__half>(g_wth);

    static cudaStream_t s1 = nullptr, s2 = nullptr;
    static cudaEvent_t ev[16];
    static bool init_done = false;
    if (!init_done) {
        cudaFuncSetAttribute(k_mma, cudaFuncAttributeMaxDynamicSharedMemorySize, 98304);
        cudaStreamCreateWithFlags(&s1, cudaStreamNonBlocking);
        cudaStreamCreateWithFlags(&s2, cudaStreamNonBlocking);
        for (int i = 0; i < 16; i++)
            cudaEventCreateWithFlags(&ev[i], cudaEventDisableTiming);
        init_done = true;
    }

    const size_t OFF_L0 = 0, OFF_L1 = 262144, OFF_W1 = 2359296, OFF_W2 = 2621440;

    cudaEventRecord(ev[0], 0);
    cudaStreamWaitEvent(s1, ev[0], 0);
    cudaStreamWaitEvent(s2, ev[0], 0);

    // s1: CSR build
    k_zero<<<(NN + 255) / 256, 256, 0, s1>>>();
    k_count<<<(EE + 255) / 256, 256, 0, s1>>>(ei);
    k_dinvk<<<(NN + 255) / 256, 256, 0, s1>>>();
    k_scan<<<1, 1024, 0, s1>>>();
    k_scatter<<<(EE + 255) / 256, 256, 0, s1>>>(ei);

    // s2: big weight conversions
    k_wconv<<<dim3(1024, 8), 256, 0, s2>>>(mh_w12, wth + OFF_L1, 1024, 256, 262144, 262144);
    k_wconv<<<dim3(1024, 1), 256, 0, s2>>>(w1, wth + OFF_W1, 1024, 256, 262144, 262144);
    k_wconv<<<dim3(128, 1), 256, 0, s2>>>(w2, wth + OFF_W2, 256, 128, 32768, 32768);
    cudaEventRecord(ev[1], s2);

    // main: layer-0 weights + input projection -> afh (fp16)
    k_wconv<<<dim3(256, 4), 256>>>(mh_w0, wth + OFF_L0, 256, 256, 65536, 65536);
    k_gemm<<<dim3(4, (NN + 63) / 64), 256>>>(x, w_in, b_in, afh, NN, 84, 256, 256);
    cudaEventRecord(ev[2], 0);

    // half slabs
    __half* th1  = tmph;
    __half* th2  = tmph + (size_t)NN * 256;
    __half* th3  = tmph + (size_t)NN * 512;
    __half* uah  = tmph + (size_t)NN * 768;
    __half* ubh  = tmph + (size_t)NN * 1024;
    __half* t1h2 = tmph + (size_t)NN * 1280;
    const int SPG = NN / 8;

    // ---- layer 0 (fp16 hops on s1, per-range GEMMs on main as hops land) ----
    cudaStreamWaitEvent(s1, ev[2], 0);
    {
        SpHArgs p1{afh, nullptr, nullptr, th1, nullptr, nullptr, 1, 0, 0,
                   nullptr, 256, 0, 0};
        k_spmmh<<<dim3(SPG, 1), 256, 0, s1>>>(p1);
        cudaEventRecord(ev[3], s1);
        SpHArgs p2{th1, nullptr, nullptr, th2, nullptr, nullptr, 1, 0, 0,
                   nullptr, 256, 0, 0};
        k_spmmh<<<dim3(SPG, 1), 256, 0, s1>>>(p2);
        cudaEventRecord(ev[4], s1);
        SpHArgs p3{th2, nullptr, nullptr, th3, nullptr, nullptr, 1, 0, 0,
                   nullptr, 256, 0, 0};
        k_spmmh<<<dim3(SPG, 1), 256, 0, s1>>>(p3);
        cudaEventRecord(ev[5], s1);

        GOut o;
        o.a[0] = afh; o.a[1] = th1; o.a[2] = th2; o.a[3] = th3;
        o.p[0] = cat; o.p[1] = cat + 256; o.p[2] = cat + 512; o.p[3] = cat + 768;
        o.b[0] = mh_b0; o.b[1] = mh_b0 + 256; o.b[2] = mh_b0 + 512; o.b[3] = mh_b0 + 768;
        o.ld[0] = o.ld[1] = o.ld[2] = o.ld[3] = 1024;
        o.act = 0; o.outHalf = 0;
        o.w3p = nullptr; o.b3p = nullptr; o.doutp = nullptr;
        k_mma<<<dim3(2, 79), 128, 98304>>>(wth + OFF_L0, o, 256, 0);
        cudaStreamWaitEvent(0, ev[3], 0);
        k_mma<<<dim3(2, 79), 128, 98304>>>(wth + OFF_L0, o, 256, 2);
        cudaStreamWaitEvent(0, ev[4], 0);
        k_mma<<<dim3(2, 79), 128, 98304>>>(wth + OFF_L0, o, 256, 4);
        cudaStreamWaitEvent(0, ev[5], 0);
        k_mma<<<dim3(2, 79), 128, 98304>>>(wth + OFF_L0, o, 256, 6);
        k_ln<<<NN, 256>>>(cat, ln_g, ln_b, afh);
    }

    cudaStreamWaitEvent(0, ev[1], 0);   // big weights ready

    // ---- layers 1,2: r0 on s2 ∥ ranges1-3 + spmm on main ----
    auto LAYER = [&](size_t woff, const float* bb, const float* lg, const float* lb,
                     int evStart, int evR0) {
        GOut of;   // range 0 -> cat fp32 (with bias)
        of.a[0] = of.a[1] = of.a[2] = of.a[3] = afh;
        of.p[0] = cat; of.p[1] = th1; of.p[2] = th2; of.p[3] = th3;
        of.b[0] = bb;  of.b[1] = nullptr; of.b[2] = nullptr; of.b[3] = nullptr;
        of.ld[0] = 1024; of.ld[1] = 256; of.ld[2] = 256; of.ld[3] = 256;
        of.act = 0; of.outHalf = 0;
        of.w3p = nullptr; of.b3p = nullptr; of.doutp = nullptr;
        cudaEventRecord(ev[evStart], 0);
        cudaStreamWaitEvent(s2, ev[evStart], 0);
        k_mma<<<dim3(2, 79), 128, 98304, s2>>>(wth + woff, of, 1024, 0);  // r0 -> cat
        cudaEventRecord(ev[evR0], s2);

        GOut oh2 = of;
        oh2.outHalf = 1;                                                   // r1-3 -> half
        k_mma<<<dim3(6, 79), 128, 98304>>>(wth + woff, oh2, 1024, 2);

        SpHArgs h1{th1, th2, th3, cat + 256, uah, ubh, 0, 1, 1,
                   bb + 256, 1024, 256, 256};
        k_spmmh<<<dim3(SPG, 3), 256>>>(h1);
        SpHArgs h2{uah, ubh, nullptr, cat + 512, t1h2, nullptr, 0, 1, 0,
                   bb + 512, 1024, 256, 0};
        k_spmmh<<<dim3(SPG, 2), 256>>>(h2);
        cudaStreamWaitEvent(0, ev[evR0], 0);
        k_spmm_lnh<<<SPG, 256>>>(t1h2, cat, bb + 768, lg, lb, afh);
    };

    LAYER(OFF_L1,              mh_b12,        ln_g + 1024, ln_b + 1024, 6, 7);
    LAYER(OFF_L1 + 4 * 262144, mh_b12 + 1024, ln_g + 2048, ln_b + 2048, 8, 9);

    // ---- head MLP: w1 (gelu -> fp16 mlph) -> w2+w3 fused (gelu, dot, bias) ----
    GOut oh;
    oh.a[0] = afh; oh.a[1] = oh.a[2] = oh.a[3] = nullptr;
    oh.p[0] = mlph; oh.p[1] = oh.p[2] = oh.p[3] = nullptr;
    oh.b[0] = b1;  oh.b[1] = oh.b[2] = oh.b[3] = nullptr;
    oh.ld[0] = 256; oh.ld[1] = oh.ld[2] = oh.ld[3] = 0;
    oh.act = 2; oh.outHalf = 1;
    oh.w3p = nullptr; oh.b3p = nullptr; oh.doutp = nullptr;
    k_mma<<<dim3(2, 79), 128, 98304>>>(wth + OFF_W1, oh, 1024, 0);

    GOut o2;
    o2.a[0] = mlph; o2.a[1] = o2.a[2] = o2.a[3] = nullptr;
    o2.p[0] = nullptr; o2.p[1] = o2.p[2] = o2.p[3] = nullptr;
    o2.b[0] = b2;   o2.b[1] = o2.b[2] = o2.b[3] = nullptr;
    o2.ld[0] = 128; o2.ld[1] = o2.ld[2] = o2.ld[3] = 0;
    o2.act = 3; o2.outHalf = 0;
    o2.w3p = w3; o2.b3p = b3; o2.doutp = out;
    k_mma<<<dim3(1, 79), 128, 98304>>>(wth + OFF_W2, o2, 256, 0);
}

// round 14
// speedup vs baseline: 1.5897x; 1.0385x over previous
#include <cuda_runtime.h>
#include <cuda_fp16.h>
#include <math.h>
#include <stdint.h>

#define NN 10000
#define EE 160000

// ---------------- scratch (device globals) ----------------------------------
__device__ float g_dinv[NN];
__device__ int   g_count[NN];
__device__ int   g_fill[NN];
__device__ int   g_rowptr[NN + 1];
__device__ uint2 g_ecw[EE];                   // packed {col, weight-bits}
__device__ __half g_cath[(size_t)NN * 1024];  // fp16 pre-LN concat
__device__ __half g_tmph[(size_t)NN * 1536];  // 6 half slabs of NN*256
__device__ __half g_mlph[NN * 256];
__device__ __half g_afh[(size_t)NN * 1024];   // fp16 GEMM input
#define WTOT 2654208
__device__ __half g_wth[WTOT];                // fp16 transposed weights

__device__ __forceinline__ float gelu_f(float x) {
    return 0.5f * x * (1.0f + erff(x * 0.70710678118654752f));
}
__device__ __forceinline__ uint32_t smem_u32(const void* p) {
    uint32_t a;
    asm("{ .reg .u64 t; cvta.to.shared.u64 t, %1; cvt.u32.u64 %0, t; }" : "=r"(a) : "l"(p));
    return a;
}
__device__ __forceinline__ void ldsm4(uint32_t& r0, uint32_t& r1, uint32_t& r2,
                                      uint32_t& r3, uint32_t addr) {
    asm volatile("ldmatrix.sync.aligned.m8n8.x4.shared.b16 {%0,%1,%2,%3}, [%4];"
                 : "=r"(r0), "=r"(r1), "=r"(r2), "=r"(r3) : "r"(addr));
}
__device__ __forceinline__ void mma_f16(float* c, const uint32_t* a, const uint32_t* b) {
    asm volatile(
        "mma.sync.aligned.m16n8k16.row.col.f32.f16.f16.f32 "
        "{%0,%1,%2,%3}, {%4,%5,%6,%7}, {%8,%9}, {%0,%1,%2,%3};"
        : "+f"(c[0]), "+f"(c[1]), "+f"(c[2]), "+f"(c[3])
        : "r"(a[0]), "r"(a[1]), "r"(a[2]), "r"(a[3]), "r"(b[0]), "r"(b[1]));
}

// ---------------- graph preprocessing ---------------------------------------
__global__ void k_zero() {
    int i = blockIdx.x * blockDim.x + threadIdx.x;
    if (i < NN) { g_count[i] = 0; g_fill[i] = 0; }
}
__global__ void k_count(const int* __restrict__ ei) {
    int e = blockIdx.x * blockDim.x + threadIdx.x;
    if (e < EE) atomicAdd(&g_count[ei[EE + e]], 1);
}
__global__ void k_dinvk() {
    int i = blockIdx.x * blockDim.x + threadIdx.x;
    if (i < NN) g_dinv[i] = rsqrtf((float)(g_count[i] + 1));
}
__global__ void k_scan() {
    int tid = threadIdx.x, lane = tid & 31, w = tid >> 5;
    const int chunk = 10;
    int b = tid * chunk, e = min(b + chunk, NN);
    int local = 0;
    for (int i = b; i < e; i++) local += g_count[i];
    int v = local;
#pragma unroll
    for (int o = 1; o < 32; o <<= 1) {
        int t = __shfl_up_sync(0xffffffffu, v, o);
        if (lane >= o) v += t;
    }
    __shared__ int ws[32];
    if (lane == 31) ws[w] = v;
    __syncthreads();
    if (w == 0) {
        int s = ws[lane];
#pragma unroll
        for (int o = 1; o < 32; o <<= 1) {
            int t = __shfl_up_sync(0xffffffffu, s, o);
            if (lane >= o) s += t;
        }
        ws[lane] = s;
    }
    __syncthreads();
    int run = v - local + (w ? ws[w - 1] : 0);
    for (int i = b; i < e; i++) { int c = g_count[i]; g_rowptr[i] = run; run += c; }
    if (tid == 1023) g_rowptr[NN] = run;
}
__global__ void k_scatter(const int* __restrict__ ei) {
    int e = blockIdx.x * blockDim.x + threadIdx.x;
    if (e >= EE) return;
    int s = ei[e], d = ei[EE + e];
    int pos = g_rowptr[d] + atomicAdd(&g_fill[d], 1);
    g_ecw[pos] = make_uint2((unsigned)s, __float_as_uint(g_dinv[s] * g_dinv[d]));
}

// ---------------- weight conversion (transposed, fp16) -----------------------
__global__ void k_wconv(const float* __restrict__ src, __half* __restrict__ dst,
                        int K, int N, size_t srcStride, size_t dstStride) {
    int m = blockIdx.y;
    int e = blockIdx.x * 256 + threadIdx.x;
    if (e >= K * N) return;
    int k = e / N, n = e % N;
    dst[m * dstStride + (size_t)n * K + k] = __float2half(src[m * srcStride + e]);
}

// ---------------- fp16 mma GEMM (m16n8k16, fp32 accum) ------------------------
struct GOut {
    const __half* a[4];
    void* p[4];
    const float* b[4];
    int ld[4];
    int act;      // 0 none(+bias if set), 2 gelu, 3 gelu+dot(w3)+b3 -> dout
    int outHalf;
    const float* w3p;
    const float* b3p;
    float* doutp;
};

__global__ void __launch_bounds__(128, 2) k_mma(
    const __half* __restrict__ B, GOut o, int K, int bnoff) {
    extern __shared__ char smc[];
    uint32_t sb = smem_u32(smc);
    int tid = threadIdx.x, lane = tid & 31, wid = tid >> 5;
    int WM = wid >> 1, WN = wid & 1;
    int bm = blockIdx.y * 128, bn = (blockIdx.x + bnoff) * 128;
    int range = bn >> 8;
    const __half* A = o.a[range];
    const int NIT = K >> 6;

    float acc[4][8][4];
#pragma unroll
    for (int i = 0; i < 4; i++)
#pragma unroll
        for (int j = 0; j < 8; j++)
#pragma unroll
            for (int r = 0; r < 4; r++) acc[i][j][r] = 0.f;

    auto LOAD = [&](int it) {
        int st = it % 3;
        uint32_t da = sb + st * 32768;
        uint32_t db = da + 16384;
        int k0 = it << 6;
#pragma unroll
        for (int i = 0; i < 8; i++) {
            int idx = i * 128 + tid;
            int row = idx >> 3, c = idx & 7;
            uint32_t so = row * 128 + ((c ^ (row & 7)) << 4);
            int ar = bm + row;
            const __half* as = A + (size_t)min(ar, NN - 1) * K + k0 + c * 8;
            int sz = (ar < NN) ? 16 : 0;
            asm volatile("cp.async.cg.shared.global [%0], [%1], 16, %2;"
                         :: "r"(da + so), "l"(as), "r"(sz));
            const __half* bs = B + (size_t)(bn + row) * K + k0 + c * 8;
            asm volatile("cp.async.cg.shared.global [%0], [%1], 16;"
                         :: "r"(db + so), "l"(bs));
        }
        asm volatile("cp.async.commit_group;");
    };

    LOAD(0);
    LOAD(1);
    for (int it = 0; it < NIT; it++) {
        asm volatile("cp.async.wait_group 1;");
        __syncthreads();
        if (it + 2 < NIT) LOAD(it + 2);
        int st = it % 3;
        uint32_t da = sb + st * 32768, db = da + 16384;
#pragma unroll
        for (int kk = 0; kk < 4; kk++) {
            uint32_t a[4][4], b[8][2];
#pragma unroll
            for (int mt = 0; mt < 4; mt++) {
                int row = WM * 64 + mt * 16 + (lane & 15);
                int ch = kk * 2 + (lane >> 4);
                uint32_t ad = da + row * 128 + ((ch ^ (row & 7)) << 4);
                ldsm4(a[mt][0], a[mt][1], a[mt][2], a[mt][3], ad);
            }
#pragma unroll
            for (int ng = 0; ng < 4; ng++) {
                int row = WN * 64 + ng * 16 + (lane & 7) + ((lane & 16) >> 1);
                int ch = kk * 2 + ((lane >> 3) & 1);
                uint32_t bd = db + row * 128 + ((ch ^ (row & 7)) << 4);
                ldsm4(b[2 * ng][0], b[2 * ng][1], b[2 * ng + 1][0], b[2 * ng + 1][1], bd);
            }
#pragma unroll
            for (int mt = 0; mt < 4; mt++)
#pragma unroll
                for (int nt = 0; nt < 8; nt++)
                    mma_f16(acc[mt][nt], a[mt], b[nt]);
        }
    }

    const float* bias = o.b[range];
    int act = o.act;

    if (act == 3) {
        __shared__ float red[128];
        if (tid < 128) red[tid] = 0.f;
        __syncthreads();
#pragma unroll
        for (int mt = 0; mt < 4; mt++) {
            float p0 = 0.f, p1 = 0.f;
#pragma unroll
            for (int nt = 0; nt < 8; nt++) {
                int gcol = WN * 64 + nt * 8 + ((lane & 3) << 1);
                float b0 = bias[gcol], b1 = bias[gcol + 1];
                float w0 = o.w3p[gcol], w1 = o.w3p[gcol + 1];
                p0 += gelu_f(acc[mt][nt][0] + b0) * w0 + gelu_f(acc[mt][nt][1] + b1) * w1;
                p1 += gelu_f(acc[mt][nt][2] + b0) * w0 + gelu_f(acc[mt][nt][3] + b1) * w1;
            }
            p0 += __shfl_xor_sync(0xffffffffu, p0, 1);
            p0 += __shfl_xor_sync(0xffffffffu, p0, 2);
            p1 += __shfl_xor_sync(0xffffffffu, p1, 1);
            p1 += __shfl_xor_sync(0xffffffffu, p1, 2);
            if ((lane & 3) == 0) {
                int lr = WM * 64 + mt * 16 + (lane >> 2);
                atomicAdd(&red[lr], p0);
                atomicAdd(&red[lr + 8], p1);
            }
        }
        __syncthreads();
        if (tid < 128) {
            int gr = bm + tid;
            if (gr < NN) o.doutp[gr] = red[tid] + o.b3p[0];
        }
        return;
    }

    int ldd = o.ld[range];
    if (o.outHalf) {
        __half* Dh = (__half*)o.p[range];
#pragma unroll
        for (int mt = 0; mt < 4; mt++) {
            int r = bm + WM * 64 + mt * 16 + (lane >> 2);
#pragma unroll
            for (int nt = 0; nt < 8; nt++) {
                int gcol = (bn & 255) + WN * 64 + nt * 8 + ((lane & 3) << 1);
                float v0 = acc[mt][nt][0], v1 = acc[mt][nt][1];
                float v2 = acc[mt][nt][2], v3 = acc[mt][nt][3];
                if (bias) {
                    float b0 = bias[gcol], b1 = bias[gcol + 1];
                    v0 += b0; v1 += b1; v2 += b0; v3 += b1;
                }
                if (act == 2) {
                    v0 = gelu_f(v0); v1 = gelu_f(v1);
                    v2 = gelu_f(v2); v3 = gelu_f(v3);
                }
                __half2 hv01 = __floats2half2_rn(v0, v1);
                __half2 hv23 = __floats2half2_rn(v2, v3);
                if (r < NN) *(__half2*)(Dh + (size_t)r * ldd + gcol) = hv01;
                if (r + 8 < NN) *(__half2*)(Dh + (size_t)(r + 8) * ldd + gcol) = hv23;
            }
        }
        return;
    }

    float* D = (float*)o.p[range];
#pragma unroll
    for (int mt = 0; mt < 4; mt++) {
        int r = bm + WM * 64 + mt * 16 + (lane >> 2);
#pragma unroll
        for (int nt = 0; nt < 8; nt++) {
            int gcol = (bn & 255) + WN * 64 + nt * 8 + ((lane & 3) << 1);
            float b0 = 0.f, b1 = 0.f;
            if (bias) { b0 = bias[gcol]; b1 = bias[gcol + 1]; }
            float v0 = acc[mt][nt][0] + b0, v1 = acc[mt][nt][1] + b1;
            float v2 = acc[mt][nt][2] + b0, v3 = acc[mt][nt][3] + b1;
            if (r < NN) *(float2*)(D + (size_t)r * ldd + gcol) = make_float2(v0, v1);
            if (r + 8 < NN) *(float2*)(D + (size_t)(r + 8) * ldd + gcol) = make_float2(v2, v3);
        }
    }
}

// ---------------- fp32 SGEMM (input projection, K=84) -> fp16 out -------------
__global__ void k_gemm(const float* __restrict__ A, const float* __restrict__ B,
                       const float* __restrict__ bias, __half* __restrict__ C,
                       int nrows, int K, int M, int ldc) {
    __shared__ float As[16][68];
    __shared__ float Bs[16][68];
    int bm = blockIdx.y * 64, bn = blockIdx.x * 64;
    int tid = threadIdx.x;
    int tx = tid & 15, ty = tid >> 4;
    int ar = tid >> 2, ak = (tid & 3) * 4;
    int br = tid >> 4, bc = (tid & 15) * 4;
    float acc[4][4];
#pragma unroll
    for (int i = 0; i < 4; i++)
#pragma unroll
        for (int j = 0; j < 4; j++) acc[i][j] = 0.f;
    int arow = bm + ar;
    for (int k0 = 0; k0 < K; k0 += 16) {
        float a0 = 0.f, a1 = 0.f, a2 = 0.f, a3 = 0.f;
        if (arow < nrows) {
            const float* ap = A + (size_t)arow * K + k0 + ak;
            if (k0 + ak + 4 <= K) {
                float4 v = *(const float4*)ap;
                a0 = v.x; a1 = v.y; a2 = v.z; a3 = v.w;
            } else {
                int rem = K - (k0 + ak);
                if (rem > 0) a0 = ap[0];
                if (rem > 1) a1 = ap[1];
                if (rem > 2) a2 = ap[2];
                if (rem > 3) a3 = ap[3];
            }
        }
        As[ak + 0][ar] = a0; As[ak + 1][ar] = a1;
        As[ak + 2][ar] = a2; As[ak + 3][ar] = a3;
        float4 bv = make_float4(0.f, 0.f, 0.f, 0.f);
        if (k0 + br < K) bv = *(const float4*)(B + (size_t)(k0 + br) * M + bn + bc);
        *(float4*)&Bs[br][bc] = bv;
        __syncthreads();
#pragma unroll
        for (int k = 0; k < 16; k++) {
            float4 av = *(const float4*)&As[k][ty * 4];
            float4 bw = *(const float4*)&Bs[k][tx * 4];
            float a[4] = {av.x, av.y, av.z, av.w};
            float bb[4] = {bw.x, bw.y, bw.z, bw.w};
#pragma unroll
            for (int i = 0; i < 4; i++)
#pragma unroll
                for (int j = 0; j < 4; j++) acc[i][j] += a[i] * bb[j];
        }
        __syncthreads();
    }
#pragma unroll
    for (int i = 0; i < 4; i++) {
        int row = bm + ty * 4 + i;
        if (row >= nrows) continue;
#pragma unroll
        for (int j = 0; j < 4; j++) {
            int col = bn + tx * 4 + j;
            if (col >= M) continue;
            C[(size_t)row * ldc + col] = __float2half(gelu_f(acc[i][j] + bias[col]));
        }
    }
}

// ---------------- SpMM fp16: uint4 gathers, 32 thr/node, 8 nodes/block -------
struct SpHArgs {
    const __half* i0; const __half* i1; const __half* i2;
    __half* o0; __half* o1; __half* o2;
    const float* bias;            // y==0 only
    int ld0, ld1, ld2;
};
__device__ __forceinline__ void h8acc(float* acc, float w, uint4 hv) {
    const __half2* h = (const __half2*)&hv;
#pragma unroll
    for (int i = 0; i < 4; i++) {
        float2 f = __half22float2(h[i]);
        acc[2 * i] += w * f.x;
        acc[2 * i + 1] += w * f.y;
    }
}
__global__ void __launch_bounds__(256) k_spmmh(SpHArgs a) {
    int y = blockIdx.y;
    const __half* in = (y == 0) ? a.i0 : (y == 1) ? a.i1 : a.i2;
    __half* out = (y == 0) ? a.o0 : (y == 1) ? a.o1 : a.o2;
    int ldo = (y == 0) ? a.ld0 : (y == 1) ? a.ld1 : a.ld2;
    int node = blockIdx.x * 8 + (threadIdx.x >> 5);   // NN % 8 == 0
    int t = threadIdx.x & 31;
    const uint4* in4 = (const uint4*)in;
    int beg = g_rowptr[node], end = g_rowptr[node + 1];
    float di = g_dinv[node];
    float acc[8] = {0.f, 0.f, 0.f, 0.f, 0.f, 0.f, 0.f, 0.f};
    float acc2[8] = {0.f, 0.f, 0.f, 0.f, 0.f, 0.f, 0.f, 0.f};
    h8acc(acc, di * di, in4[(size_t)node * 32 + t]);
    int e = beg;
    for (; e + 1 < end; e += 2) {
        uint2 m0 = __ldg(&g_ecw[e]);
        uint2 m1 = __ldg(&g_ecw[e + 1]);
        uint4 va = __ldg(&in4[(size_t)m0.x * 32 + t]);
        uint4 vb = __ldg(&in4[(size_t)m1.x * 32 + t]);
        h8acc(acc, __uint_as_float(m0.y), va);
        h8acc(acc2, __uint_as_float(m1.y), vb);
    }
    if (e < end) {
        uint2 m = __ldg(&g_ecw[e]);
        h8acc(acc, __uint_as_float(m.y), __ldg(&in4[(size_t)m.x * 32 + t]));
    }
#pragma unroll
    for (int i = 0; i < 8; i++) acc[i] += acc2[i];
    if (y == 0 && a.bias) {
        float4 b0 = *(const float4*)(a.bias + t * 8);
        float4 b1 = *(const float4*)(a.bias + t * 8 + 4);
        acc[0] += b0.x; acc[1] += b0.y; acc[2] += b0.z; acc[3] += b0.w;
        acc[4] += b1.x; acc[5] += b1.y; acc[6] += b1.z; acc[7] += b1.w;
    }
    uint4 st;
    __half2* sh = (__half2*)&st;
#pragma unroll
    for (int i = 0; i < 4; i++)
        sh[i] = __floats2half2_rn(acc[2 * i], acc[2 * i + 1]);
    *(uint4*)(out + (size_t)node * ldo + t * 8) = st;
}

// ---------------- fused: fp16 hop3 + LayerNorm(fp16 cat) + GELU -> afh --------
__global__ void __launch_bounds__(256) k_spmm_lnh(
    const __half* __restrict__ in, const __half* __restrict__ cat,
    const float* __restrict__ bias, const float* __restrict__ lg,
    const float* __restrict__ lb, __half* __restrict__ af) {
    int tid = threadIdx.x;
    int t = tid & 31;
    int node = blockIdx.x * 8 + (tid >> 5);
    const uint4* in4 = (const uint4*)in;
    int beg = g_rowptr[node], end = g_rowptr[node + 1];
    float di = g_dinv[node];
    float a3[8] = {0.f, 0.f, 0.f, 0.f, 0.f, 0.f, 0.f, 0.f};
    float b3a[8] = {0.f, 0.f, 0.f, 0.f, 0.f, 0.f, 0.f, 0.f};
    h8acc(a3, di * di, in4[(size_t)node * 32 + t]);
    int e = beg;
    for (; e + 1 < end; e += 2) {
        uint2 m0 = __ldg(&g_ecw[e]);
        uint2 m1 = __ldg(&g_ecw[e + 1]);
        uint4 va = __ldg(&in4[(size_t)m0.x * 32 + t]);
        uint4 vb = __ldg(&in4[(size_t)m1.x * 32 + t]);
        h8acc(a3, __uint_as_float(m0.y), va);
        h8acc(b3a, __uint_as_float(m1.y), vb);
    }
    if (e < end) {
        uint2 m = __ldg(&g_ecw[e]);
        h8acc(a3, __uint_as_float(m.y), __ldg(&in4[(size_t)m.x * 32 + t]));
    }
#pragma unroll
    for (int i = 0; i < 8; i++) a3[i] += b3a[i];
    {
        float4 b0 = *(const float4*)(bias + t * 8);
        float4 b1 = *(const float4*)(bias + t * 8 + 4);
        a3[0] += b0.x; a3[1] += b0.y; a3[2] += b0.z; a3[3] += b0.w;
        a3[4] += b1.x; a3[5] += b1.y; a3[6] += b1.z; a3[7] += b1.w;
    }
    const uint4* crow = (const uint4*)(cat + (size_t)node * 1024);
    float v[3][8];
#pragma unroll
    for (int r = 0; r < 3; r++) {
        uint4 hv = crow[r * 32 + t];
        const __half2* h = (const __half2*)&hv;
#pragma unroll
        for (int i = 0; i < 4; i++) {
            float2 f = __half22float2(h[i]);
            v[r][2 * i] = f.x;
            v[r][2 * i + 1] = f.y;
        }
    }
    float s = 0.f, ss = 0.f;
#pragma unroll
    for (int i = 0; i < 8; i++) {
        s += v[0][i] + v[1][i] + v[2][i] + a3[i];
        ss += v[0][i] * v[0][i] + v[1][i] * v[1][i] + v[2][i] * v[2][i] + a3[i] * a3[i];
    }
#pragma unroll
    for (int o = 16; o; o >>= 1) {
        s += __shfl_xor_sync(0xffffffffu, s, o);
        ss += __shfl_xor_sync(0xffffffffu, ss, o);
    }
    float mu = s * (1.0f / 1024.0f);
    float var = ss * (1.0f / 1024.0f) - mu * mu;
    float inv = rsqrtf(var + 1e-5f);
    __half* arow = af + (size_t)node * 1024;
#pragma unroll
    for (int r = 0; r < 4; r++) {
        int c = r * 256 + t * 8;
        float4 g0 = *(const float4*)(lg + c);
        float4 g1 = *(const float4*)(lg + c + 4);
        float4 bb0 = *(const float4*)(lb + c);
        float4 bb1 = *(const float4*)(lb + c + 4);
        const float* vr = (r < 3) ? v[r] : a3;
        float gv[8] = {g0.x, g0.y, g0.z, g0.w, g1.x, g1.y, g1.z, g1.w};
        float bv[8] = {bb0.x, bb0.y, bb0.z, bb0.w, bb1.x, bb1.y, bb1.z, bb1.w};
        uint4 st;
        __half2* sh = (__half2*)&st;
#pragma unroll
        for (int i = 0; i < 4; i++) {
            float q0 = gelu_f((vr[2 * i] - mu) * inv * gv[2 * i] + bv[2 * i]);
            float q1 = gelu_f((vr[2 * i + 1] - mu) * inv * gv[2 * i + 1] + bv[2 * i + 1]);
            sh[i] = __floats2half2_rn(q0, q1);
        }
        *(uint4*)(arow + c) = st;
    }
}

// ---------------- LayerNorm(1024, fp16 cat) + GELU -> afh (layer 0) ----------
__global__ void __launch_bounds__(256) k_lnh(
    const __half* __restrict__ cat, const float* __restrict__ lg,
    const float* __restrict__ lb, __half* __restrict__ af) {
    int tid = threadIdx.x;
    int t = tid & 31;
    int node = blockIdx.x * 8 + (tid >> 5);
    const uint4* crow = (const uint4*)(cat + (size_t)node * 1024);
    float v[4][8];
#pragma unroll
    for (int r = 0; r < 4; r++) {
        uint4 hv = crow[r * 32 + t];
        const __half2* h = (const __half2*)&hv;
#pragma unroll
        for (int i = 0; i < 4; i++) {
            float2 f = __half22float2(h[i]);
            v[r][2 * i] = f.x;
            v[r][2 * i + 1] = f.y;
        }
    }
    float s = 0.f, ss = 0.f;
#pragma unroll
    for (int r = 0; r < 4; r++)
#pragma unroll
        for (int i = 0; i < 8; i++) {
            s += v[r][i];
            ss += v[r][i] * v[r][i];
        }
#pragma unroll
    for (int o = 16; o; o >>= 1) {
        s += __shfl_xor_sync(0xffffffffu, s, o);
        ss += __shfl_xor_sync(0xffffffffu, ss, o);
    }
    float mu = s * (1.0f / 1024.0f);
    float var = ss * (1.0f / 1024.0f) - mu * mu;
    float inv = rsqrtf(var + 1e-5f);
    __half* arow = af + (size_t)node * 1024;
#pragma unroll
    for (int r = 0; r < 4; r++) {
        int c = r * 256 + t * 8;
        float4 g0 = *(const float4*)(lg + c);
        float4 g1 = *(const float4*)(lg + c + 4);
        float4 bb0 = *(const float4*)(lb + c);
        float4 bb1 = *(const float4*)(lb + c + 4);
        float gv[8] = {g0.x, g0.y, g0.z, g0.w, g1.x, g1.y, g1.z, g1.w};
        float bv[8] = {bb0.x, bb0.y, bb0.z, bb0.w, bb1.x, bb1.y, bb1.z, bb1.w};
        uint4 st;
        __half2* sh = (__half2*)&st;
#pragma unroll
        for (int i = 0; i < 4; i++) {
            float q0 = gelu_f((v[r][2 * i] - mu) * inv * gv[2 * i] + bv[2 * i]);
            float q1 = gelu_f((v[r][2 * i + 1] - mu) * inv * gv[2 * i + 1] + bv[2 * i + 1]);
            sh[i] = __floats2half2_rn(q0, q1);
        }
        *(uint4*)(arow + c) = st;
    }
}

// ---------------- host orchestration -----------------------------------------
template <typename T>
static T* sym(const void* s) {
    void* p = nullptr;
    cudaGetSymbolAddress(&p, s);
    return (T*)p;
}

extern "C" void kernel_launch(void* const* d_in, const int* in_sizes, int n_in,
                              void* d_out, int out_size) {
    const float* x      = (const float*)d_in[0];
    const int*   ei     = (const int*)d_in[1];
    const float* w_in   = (const float*)d_in[2];
    const float* b_in   = (const float*)d_in[3];
    const float* mh_w0  = (const float*)d_in[4];
    const float* mh_b0  = (const float*)d_in[5];
    const float* mh_w12 = (const float*)d_in[6];
    const float* mh_b12 = (const float*)d_in[7];
    const float* ln_g   = (const float*)d_in[8];
    const float* ln_b   = (const float*)d_in[9];
    const float* w1     = (const float*)d_in[10];
    const float* b1     = (const float*)d_in[11];
    const float* w2     = (const float*)d_in[12];
    const float* b2     = (const float*)d_in[13];
    const float* w3     = (const float*)d_in[14];
    const float* b3     = (const float*)d_in[15];
    float* out = (float*)d_out;

    __half* cath = sym<__half>(g_cath);
    __half* tmph = sym<__half>(g_tmph);
    __half* mlph = sym<__half>(g_mlph);
    __half* afh  = sym<__half>(g_afh);
    __half* wth  = sym<__half>(g_wth);

    static cudaStream_t s1 = nullptr, s2 = nullptr;
    static cudaEvent_t ev[16];
    static bool init_done = false;
    if (!init_done) {
        cudaFuncSetAttribute(k_mma, cudaFuncAttributeMaxDynamicSharedMemorySize, 98304);
        cudaStreamCreateWithFlags(&s1, cudaStreamNonBlocking);
        cudaStreamCreateWithFlags(&s2, cudaStreamNonBlocking);
        for (int i = 0; i < 16; i++)
            cudaEventCreateWithFlags(&ev[i], cudaEventDisableTiming);
        init_done = true;
    }

    const size_t OFF_L0 = 0, OFF_L1 = 262144, OFF_W1 = 2359296, OFF_W2 = 2621440;

    cudaEventRecord(ev[0], 0);
    cudaStreamWaitEvent(s1, ev[0], 0);
    cudaStreamWaitEvent(s2, ev[0], 0);

    // s1: CSR build
    k_zero<<<(NN + 255) / 256, 256, 0, s1>>>();
    k_count<<<(EE + 255) / 256, 256, 0, s1>>>(ei);
    k_dinvk<<<(NN + 255) / 256, 256, 0, s1>>>();
    k_scan<<<1, 1024, 0, s1>>>();
    k_scatter<<<(EE + 255) / 256, 256, 0, s1>>>(ei);

    // s2: big weight conversions
    k_wconv<<<dim3(1024, 8), 256, 0, s2>>>(mh_w12, wth + OFF_L1, 1024, 256, 262144, 262144);
    k_wconv<<<dim3(1024, 1), 256, 0, s2>>>(w1, wth + OFF_W1, 1024, 256, 262144, 262144);
    k_wconv<<<dim3(128, 1), 256, 0, s2>>>(w2, wth + OFF_W2, 256, 128, 32768, 32768);
    cudaEventRecord(ev[1], s2);

    // main: layer-0 weights + input projection -> afh (fp16)
    k_wconv<<<dim3(256, 4), 256>>>(mh_w0, wth + OFF_L0, 256, 256, 65536, 65536);
    k_gemm<<<dim3(4, (NN + 63) / 64), 256>>>(x, w_in, b_in, afh, NN, 84, 256, 256);
    cudaEventRecord(ev[2], 0);

    // half slabs
    __half* th1  = tmph;
    __half* th2  = tmph + (size_t)NN * 256;
    __half* th3  = tmph + (size_t)NN * 512;
    __half* uah  = tmph + (size_t)NN * 768;
    __half* ubh  = tmph + (size_t)NN * 1024;
    __half* t1h2 = tmph + (size_t)NN * 1280;
    const int SPG = NN / 8;

    // ---- layer 0 (fp16 hops on s1, per-range GEMMs on main as hops land) ----
    cudaStreamWaitEvent(s1, ev[2], 0);
    {
        SpHArgs p1{afh, nullptr, nullptr, th1, nullptr, nullptr, nullptr, 256, 0, 0};
        k_spmmh<<<dim3(SPG, 1), 256, 0, s1>>>(p1);
        cudaEventRecord(ev[3], s1);
        SpHArgs p2{th1, nullptr, nullptr, th2, nullptr, nullptr, nullptr, 256, 0, 0};
        k_spmmh<<<dim3(SPG, 1), 256, 0, s1>>>(p2);
        cudaEventRecord(ev[4], s1);
        SpHArgs p3{th2, nullptr, nullptr, th3, nullptr, nullptr, nullptr, 256, 0, 0};
        k_spmmh<<<dim3(SPG, 1), 256, 0, s1>>>(p3);
        cudaEventRecord(ev[5], s1);

        GOut o;
        o.a[0] = afh; o.a[1] = th1; o.a[2] = th2; o.a[3] = th3;
        o.p[0] = cath; o.p[1] = cath + 256; o.p[2] = cath + 512; o.p[3] = cath + 768;
        o.b[0] = mh_b0; o.b[1] = mh_b0 + 256; o.b[2] = mh_b0 + 512; o.b[3] = mh_b0 + 768;
        o.ld[0] = o.ld[1] = o.ld[2] = o.ld[3] = 1024;
        o.act = 0; o.outHalf = 1;
        o.w3p = nullptr; o.b3p = nullptr; o.doutp = nullptr;
        k_mma<<<dim3(2, 79), 128, 98304>>>(wth + OFF_L0, o, 256, 0);
        cudaStreamWaitEvent(0, ev[3], 0);
        k_mma<<<dim3(2, 79), 128, 98304>>>(wth + OFF_L0, o, 256, 2);
        cudaStreamWaitEvent(0, ev[4], 0);
        k_mma<<<dim3(2, 79), 128, 98304>>>(wth + OFF_L0, o, 256, 4);
        cudaStreamWaitEvent(0, ev[5], 0);
        k_mma<<<dim3(2, 79), 128, 98304>>>(wth + OFF_L0, o, 256, 6);
        k_lnh<<<SPG, 256>>>(cath, ln_g, ln_b, afh);
    }

    cudaStreamWaitEvent(0, ev[1], 0);   // big weights ready

    // ---- layers 1,2: r0 on s2 ∥ ranges1-3 + spmm on main ----
    auto LAYER = [&](size_t woff, const float* bb, const float* lg, const float* lb,
                     int evStart, int evR0) {
        GOut of;   // range 0 -> cath (half, with bias)
        of.a[0] = of.a[1] = of.a[2] = of.a[3] = afh;
        of.p[0] = cath; of.p[1] = th1; of.p[2] = th2; of.p[3] = th3;
        of.b[0] = bb;  of.b[1] = nullptr; of.b[2] = nullptr; of.b[3] = nullptr;
        of.ld[0] = 1024; of.ld[1] = 256; of.ld[2] = 256; of.ld[3] = 256;
        of.act = 0; of.outHalf = 1;
        of.w3p = nullptr; of.b3p = nullptr; of.doutp = nullptr;
        cudaEventRecord(ev[evStart], 0);
        cudaStreamWaitEvent(s2, ev[evStart], 0);
        k_mma<<<dim3(2, 79), 128, 98304, s2>>>(wth + woff, of, 1024, 0);  // r0 -> cath
        cudaEventRecord(ev[evR0], s2);

        k_mma<<<dim3(6, 79), 128, 98304>>>(wth + woff, of, 1024, 2);      // r1-3 -> slabs

        SpHArgs h1{th1, th2, th3, cath + 256, uah, ubh, bb + 256, 1024, 256, 256};
        k_spmmh<<<dim3(SPG, 3), 256>>>(h1);
        SpHArgs h2{uah, ubh, nullptr, cath + 512, t1h2, nullptr, bb + 512, 1024, 256, 0};
        k_spmmh<<<dim3(SPG, 2), 256>>>(h2);
        cudaStreamWaitEvent(0, ev[evR0], 0);
        k_spmm_lnh<<<SPG, 256>>>(t1h2, cath, bb + 768, lg, lb, afh);
    };

    LAYER(OFF_L1,              mh_b12,        ln_g + 1024, ln_b + 1024, 6, 7);
    LAYER(OFF_L1 + 4 * 262144, mh_b12 + 1024, ln_g + 2048, ln_b + 2048, 8, 9);

    // ---- head MLP: w1 (gelu -> fp16 mlph) -> w2+w3 fused (gelu, dot, bias) ----
    GOut oh;
    oh.a[0] = afh; oh.a[1] = oh.a[2] = oh.a[3] = nullptr;
    oh.p[0] = mlph; oh.p[1] = oh.p[2] = oh.p[3] = nullptr;
    oh.b[0] = b1;  oh.b[1] = oh.b[2] = oh.b[3] = nullptr;
    oh.ld[0] = 256; oh.ld[1] = oh.ld[2] = oh.ld[3] = 0;
    oh.act = 2; oh.outHalf = 1;
    oh.w3p = nullptr; oh.b3p = nullptr; oh.doutp = nullptr;
    k_mma<<<dim3(2, 79), 128, 98304>>>(wth + OFF_W1, oh, 1024, 0);

    GOut o2;
    o2.a[0] = mlph; o2.a[1] = o2.a[2] = o2.a[3] = nullptr;
    o2.p[0] = nullptr; o2.p[1] = o2.p[2] = o2.p[3] = nullptr;
    o2.b[0] = b2;   o2.b[1] = o2.b[2] = o2.b[3] = nullptr;
    o2.ld[0] = 128; o2.ld[1] = o2.ld[2] = o2.ld[3] = 0;
    o2.act = 3; o2.outHalf = 0;
    o2.w3p = w3; o2.b3p = b3; o2.doutp = out;
    k_mma<<<dim3(1, 79), 128, 98304>>>(wth + OFF_W2, o2, 256, 0);
}